// round 1
// baseline (speedup 1.0000x reference)
#include <cuda_runtime.h>
#include <math.h>

// Problem constants
#define BATCH 32
#define HGT   64
#define WID   64
#define CH    256
#define EMB   256
#define NHEAD 8
#define HD    32           // head dim
#define WK    8            // window size
#define SHFT  4
#define TT    64           // tokens per window
#define NWIN  64           // windows per image
#define TOTW  (BATCH*NWIN) // 2048 windows
#define MROWS (TOTW*TT)    // 131072 token rows
#define HID   768

// ---------------- scratch (static device allocations are the sanctioned path) ----
__device__ float g_q [MROWS * EMB];
__device__ float g_k [MROWS * EMB];
__device__ float g_v [MROWS * EMB];
__device__ float g_o [MROWS * EMB];   // attn out; reused for mlp2 out
__device__ float g_x2[MROWS * CH];    // after attn block (res2 input to MLP)
__device__ float g_h [MROWS * HID];   // proj tmp ([M,256] view) then mlp hidden [M,768]

// row (window*64+token) -> pixel index in the ORIGINAL query tensor,
// folding in the cyclic roll by (-S,-S). Identical map is used for the final
// scatter (roll by +S is the inverse permutation at pixel granularity).
__device__ __forceinline__ int map_row(int row) {
    int w  = row >> 6;          // window id 0..2047
    int t  = row & 63;          // token in window
    int b  = w >> 6;            // image
    int wi = w & 63;            // window within image
    int hb = wi >> 3, wb = wi & 7;
    int i  = ((hb << 3) + (t >> 3) + SHFT) & 63;
    int j  = ((wb << 3) + (t & 7) + SHFT) & 63;
    return (b << 12) + (i << 6) + j;   // b*4096 + i*64 + j
}

// ---------------- generic 128x128x16 SGEMM, 8x8 per thread ---------------------
// GATHER: A rows come from query via map_row (row stride fixed = CH)
// GELU:   tanh-approx gelu epilogue (matches jax.nn.gelu approximate=True)
template<bool GATHER, bool GELU>
__global__ __launch_bounds__(256)
void gemm_k(const float* __restrict__ A, const float* __restrict__ Bm,
            const float* __restrict__ bias, float* __restrict__ Cm,
            int N, int Kd)
{
    __shared__ __align__(16) float As[16][128];
    __shared__ __align__(16) float Bs[16][128];

    const int tid  = threadIdx.x;
    const int row0 = blockIdx.y * 128;
    const int col0 = blockIdx.x * 128;

    // A-load mapping: two rows per thread, 1 float4 each per k-step half
    const int mA0 = tid >> 2;            // 0..63
    const int mA1 = mA0 + 64;
    const int kqA = (tid & 3) << 2;      // 0,4,8,12
    const float* arow0;
    const float* arow1;
    if (GATHER) {
        arow0 = A + (size_t)map_row(row0 + mA0) * CH;
        arow1 = A + (size_t)map_row(row0 + mA1) * CH;
    } else {
        arow0 = A + (size_t)(row0 + mA0) * Kd;
        arow1 = A + (size_t)(row0 + mA1) * Kd;
    }
    // B-load mapping: two rows of Bs per thread, 1 float4 each
    const int kB = tid >> 5;             // 0..7
    const int nB = (tid & 31) << 2;      // 0..124

    const int tm = (tid >> 4) << 3;      // output row offset 0..120
    const int tn = (tid & 15) << 3;      // output col offset 0..120

    float acc[8][8];
#pragma unroll
    for (int i = 0; i < 8; i++)
#pragma unroll
        for (int j = 0; j < 8; j++) acc[i][j] = 0.f;

    for (int k0 = 0; k0 < Kd; k0 += 16) {
        float4 a0 = *(const float4*)(arow0 + k0 + kqA);
        float4 a1 = *(const float4*)(arow1 + k0 + kqA);
        As[kqA + 0][mA0] = a0.x; As[kqA + 1][mA0] = a0.y;
        As[kqA + 2][mA0] = a0.z; As[kqA + 3][mA0] = a0.w;
        As[kqA + 0][mA1] = a1.x; As[kqA + 1][mA1] = a1.y;
        As[kqA + 2][mA1] = a1.z; As[kqA + 3][mA1] = a1.w;

        *(float4*)&Bs[kB    ][nB] = *(const float4*)(Bm + (size_t)(k0 + kB    ) * N + col0 + nB);
        *(float4*)&Bs[kB + 8][nB] = *(const float4*)(Bm + (size_t)(k0 + kB + 8) * N + col0 + nB);
        __syncthreads();

#pragma unroll
        for (int kk = 0; kk < 16; kk++) {
            float ar[8], br[8];
            *(float4*)&ar[0] = *(const float4*)&As[kk][tm];
            *(float4*)&ar[4] = *(const float4*)&As[kk][tm + 4];
            *(float4*)&br[0] = *(const float4*)&Bs[kk][tn];
            *(float4*)&br[4] = *(const float4*)&Bs[kk][tn + 4];
#pragma unroll
            for (int i = 0; i < 8; i++)
#pragma unroll
                for (int j = 0; j < 8; j++)
                    acc[i][j] = fmaf(ar[i], br[j], acc[i][j]);
        }
        __syncthreads();
    }

    // epilogue: +bias (optionally gelu), vectorized stores
    float bv[8];
#pragma unroll
    for (int j = 0; j < 8; j++) bv[j] = bias[col0 + tn + j];

#pragma unroll
    for (int i = 0; i < 8; i++) {
        float* crow = Cm + (size_t)(row0 + tm + i) * N + col0 + tn;
        float4 o0, o1;
        float tmp[8];
#pragma unroll
        for (int j = 0; j < 8; j++) {
            float x = acc[i][j] + bv[j];
            if (GELU) {
                float x3 = x * x * x;
                x = 0.5f * x * (1.f + tanhf(0.7978845608028654f * (x + 0.044715f * x3)));
            }
            tmp[j] = x;
        }
        o0.x = tmp[0]; o0.y = tmp[1]; o0.z = tmp[2]; o0.w = tmp[3];
        o1.x = tmp[4]; o1.y = tmp[5]; o1.z = tmp[6]; o1.w = tmp[7];
        *(float4*)(crow)     = o0;
        *(float4*)(crow + 4) = o1;
    }
}

// ---------------- windowed attention: one block per (window, head) -------------
__global__ __launch_bounds__(64)
void attn_kernel(const float* __restrict__ q, const float* __restrict__ k,
                 const float* __restrict__ v, const float* __restrict__ rpe,
                 const float* __restrict__ mask, const int* __restrict__ rel,
                 float* __restrict__ o)
{
    const int w    = blockIdx.x;
    const int head = blockIdx.y;
    const int t    = threadIdx.x;

    __shared__ __align__(16) float ks[64][32];
    __shared__ __align__(16) float vs[64][32];
    __shared__ float lgs[64][65];   // +1 pad: bank-conflict-free column access

    const size_t base = (size_t)w * (64 * 256) + head * 32;
    const float4* kr = (const float4*)(k + base + (size_t)t * 256);
    const float4* vr = (const float4*)(v + base + (size_t)t * 256);
#pragma unroll
    for (int i = 0; i < 8; i++) {
        ((float4*)ks[t])[i] = kr[i];
        ((float4*)vs[t])[i] = vr[i];
    }
    float qr[32];
    const float* qp = q + base + (size_t)t * 256;
#pragma unroll
    for (int d = 0; d < 32; d++) qr[d] = qp[d] * 0.17677669529663687f; // 1/sqrt(32)
    __syncthreads();

    const float* mrow = mask + (size_t)(w & 63) * 4096 + t * 64;
    const int*   rrow = rel + t * 64;

    float mx = -1e30f;
    for (int s = 0; s < 64; s++) {
        float dot = 0.f;
#pragma unroll
        for (int d = 0; d < 32; d++) dot = fmaf(qr[d], ks[s][d], dot);
        dot += rpe[rrow[s] * NHEAD + head] + mrow[s];
        lgs[t][s] = dot;
        mx = fmaxf(mx, dot);
    }
    float sum = 0.f;
    for (int s = 0; s < 64; s++) {
        float e = expf(lgs[t][s] - mx);
        lgs[t][s] = e;
        sum += e;
    }
    const float inv = 1.f / sum;

    float ov[32];
#pragma unroll
    for (int d = 0; d < 32; d++) ov[d] = 0.f;
    for (int s = 0; s < 64; s++) {
        float p = lgs[t][s];
#pragma unroll
        for (int d = 0; d < 32; d++) ov[d] = fmaf(p, vs[s][d], ov[d]);
    }
    float* op = o + base + (size_t)t * 256;
#pragma unroll
    for (int d = 0; d < 32; d++) op[d] = ov[d] * inv;
}

// ---------------- LayerNorm (+residual) kernels --------------------------------
// block = one token row (256 channels, 256 threads)
__device__ __forceinline__ void block_stats(float val, float& mean, float& var) {
    float s = val, s2 = val * val;
#pragma unroll
    for (int off = 16; off; off >>= 1) {
        s  += __shfl_xor_sync(0xffffffffu, s,  off);
        s2 += __shfl_xor_sync(0xffffffffu, s2, off);
    }
    __shared__ float sh[8], sh2[8];
    int lane = threadIdx.x & 31, warp = threadIdx.x >> 5;
    if (lane == 0) { sh[warp] = s; sh2[warp] = s2; }
    __syncthreads();
    float sum = 0.f, sq = 0.f;
#pragma unroll
    for (int i = 0; i < 8; i++) { sum += sh[i]; sq += sh2[i]; }
    mean = sum * (1.f / 256.f);
    var  = sq * (1.f / 256.f) - mean * mean;
}

// x2 = LN1(proj) + gather(query)
__global__ __launch_bounds__(256)
void ln1_kernel(const float* __restrict__ X, const float* __restrict__ g,
                const float* __restrict__ b, const float* __restrict__ query,
                float* __restrict__ out)
{
    const int row = blockIdx.x, c = threadIdx.x;
    const float val = X[(size_t)row * CH + c];
    float mean, var;
    block_stats(val, mean, var);
    const float y = (val - mean) * rsqrtf(var + 1e-5f) * g[c] + b[c];
    out[(size_t)row * CH + c] = y + query[(size_t)map_row(row) * CH + c];
}

// d_out[scatter(row)] = LN2(mlp) + x2
__global__ __launch_bounds__(256)
void ln2_kernel(const float* __restrict__ X, const float* __restrict__ g,
                const float* __restrict__ b, const float* __restrict__ x2,
                float* __restrict__ out)
{
    const int row = blockIdx.x, c = threadIdx.x;
    const float val = X[(size_t)row * CH + c];
    float mean, var;
    block_stats(val, mean, var);
    const float y = (val - mean) * rsqrtf(var + 1e-5f) * g[c] + b[c];
    out[(size_t)map_row(row) * CH + c] = y + x2[(size_t)row * CH + c];
}

// ---------------- launch --------------------------------------------------------
extern "C" void kernel_launch(void* const* d_in, const int* in_sizes, int n_in,
                              void* d_out, int out_size)
{
    const float* query = (const float*)d_in[0];
    const float* wq = (const float*)d_in[1];  const float* bq = (const float*)d_in[2];
    const float* wk = (const float*)d_in[3];  const float* bk = (const float*)d_in[4];
    const float* wv = (const float*)d_in[5];  const float* bv = (const float*)d_in[6];
    const float* wo = (const float*)d_in[7];  const float* bo = (const float*)d_in[8];
    const float* rpe = (const float*)d_in[9];
    const float* ln1g = (const float*)d_in[10]; const float* ln1b = (const float*)d_in[11];
    const float* ln2g = (const float*)d_in[12]; const float* ln2b = (const float*)d_in[13];
    const float* w1 = (const float*)d_in[14]; const float* b1 = (const float*)d_in[15];
    const float* w2 = (const float*)d_in[16]; const float* b2 = (const float*)d_in[17];
    const float* amask = (const float*)d_in[18];
    const int*   rel   = (const int*)d_in[19];
    float* out = (float*)d_out;

    float *q, *k, *v, *o, *x2, *h;
    cudaGetSymbolAddress((void**)&q,  g_q);
    cudaGetSymbolAddress((void**)&k,  g_k);
    cudaGetSymbolAddress((void**)&v,  g_v);
    cudaGetSymbolAddress((void**)&o,  g_o);
    cudaGetSymbolAddress((void**)&x2, g_x2);
    cudaGetSymbolAddress((void**)&h,  g_h);

    const dim3 blk(256);
    const dim3 g256(EMB / 128, MROWS / 128);   // (2, 1024)
    const dim3 g768(HID / 128, MROWS / 128);   // (6, 1024)

    // QKV projections with fused roll+window gather
    gemm_k<true,  false><<<g256, blk>>>(query, wq, bq, q, EMB, CH);
    gemm_k<true,  false><<<g256, blk>>>(query, wk, bk, k, EMB, CH);
    gemm_k<true,  false><<<g256, blk>>>(query, wv, bv, v, EMB, CH);

    // windowed attention with rpe bias + shift mask
    attn_kernel<<<dim3(TOTW, NHEAD), 64>>>(q, k, v, rpe, amask, rel, o);

    // output projection -> tmp (first [M,256] slab of g_h)
    gemm_k<false, false><<<g256, blk>>>(o, wo, bo, h, EMB, EMB);

    // LN1 + residual (re-gather query)
    ln1_kernel<<<MROWS, 256>>>(h, ln1g, ln1b, query, x2);

    // MLP: gelu(x2@w1+b1) @ w2 + b2
    gemm_k<false, true ><<<g768, blk>>>(x2, w1, b1, h, HID, CH);
    gemm_k<false, false><<<g256, blk>>>(h, w2, b2, o, CH, HID);

    // LN2 + residual, scatter with un-partition + un-roll directly into d_out
    ln2_kernel<<<MROWS, 256>>>(o, ln2g, ln2b, x2, out);
}

// round 3
// speedup vs baseline: 2.1384x; 2.1384x over previous
#include <cuda_runtime.h>
#include <math.h>
#include <stdint.h>

#define BATCH 32
#define CH    256
#define EMB   256
#define NHEAD 8
#define SHFT  4
#define TT    64
#define TOTW  2048
#define MROWS 131072
#define HID   768

// ---------------- scratch ----------------
__device__ float g_qkv[(size_t)MROWS * 768];   // qkv out; later mlp1 out
__device__ float g_o  [(size_t)MROWS * 256];   // attn out; later mlp2 out
__device__ float g_x2 [(size_t)MROWS * 256];
__device__ float g_h  [(size_t)MROWS * 256];   // proj out
__device__ float g_wqkvT[768 * 256];
__device__ float g_bqkv [768];
__device__ float g_woT  [256 * 256];
__device__ float g_w1T  [768 * 256];
__device__ float g_w2T  [256 * 768];

// row (window*64+token) -> pixel index in original query (folds roll by -S)
__device__ __forceinline__ int map_row(int row) {
    int w  = row >> 6;
    int t  = row & 63;
    int b  = w >> 6;
    int wi = w & 63;
    int hb = wi >> 3, wb = wi & 7;
    int i  = ((hb << 3) + (t >> 3) + SHFT) & 63;
    int j  = ((wb << 3) + (t & 7) + SHFT) & 63;
    return (b << 12) + (i << 6) + j;
}

__device__ __forceinline__ uint32_t smem_u32(const void* p) {
    uint32_t a;
    asm("{ .reg .u64 t; cvta.to.shared.u64 t, %1; cvt.u32.u64 %0, t; }" : "=r"(a) : "l"(p));
    return a;
}

__device__ __forceinline__ float4 tf32x4(float4 v) {
    asm("cvt.rn.tf32.f32 %0, %0;" : "+f"(v.x));
    asm("cvt.rn.tf32.f32 %0, %0;" : "+f"(v.y));
    asm("cvt.rn.tf32.f32 %0, %0;" : "+f"(v.z));
    asm("cvt.rn.tf32.f32 %0, %0;" : "+f"(v.w));
    return v;
}

#define LDMX4(r0, r1, r2, r3, addr) \
    asm volatile("ldmatrix.sync.aligned.m8n8.x4.shared.b16 {%0,%1,%2,%3}, [%4];" \
        : "=r"(r0), "=r"(r1), "=r"(r2), "=r"(r3) : "r"(addr))

#define MMA_TF32(d, a0, a1, a2, a3, b0, b1) \
    asm volatile("mma.sync.aligned.m16n8k8.row.col.f32.tf32.tf32.f32 " \
        "{%0,%1,%2,%3}, {%4,%5,%6,%7}, {%8,%9}, {%0,%1,%2,%3};" \
        : "+f"((d)[0]), "+f"((d)[1]), "+f"((d)[2]), "+f"((d)[3]) \
        : "r"(a0), "r"(a1), "r"(a2), "r"(a3), "r"(b0), "r"(b1))

// ---------------- tf32 mma.sync GEMM: C[M,N] = A[M,K] @ Bt[N,K]^T + bias -------
// CTA tile 128x128, BK=32, 8 warps (2m x 4n), warp tile 64x32 (4x4 m16n8k8).
// smem: double-buffered A/B tiles [128 rows][32 k floats], 128B rows, XOR swizzle.
#define STAGE_FLOATS 8192         // A(4096) + B(4096) floats = 32KB
#define GEMM_SMEM    (2 * STAGE_FLOATS * 4)

template<bool GATHER, bool GELU>
__global__ __launch_bounds__(256)
void gemm_mma(const float* __restrict__ A, const float* __restrict__ Bt,
              const float* __restrict__ bias, float* __restrict__ C,
              int N, int Kd)
{
    extern __shared__ float smem[];
    const uint32_t sbase = smem_u32(smem);
    const int tid  = threadIdx.x;
    const int lane = tid & 31;
    const int wid  = tid >> 5;
    const int warp_m = wid >> 2;          // 0..1
    const int warp_n = wid & 3;           // 0..3
    const int row0 = blockIdx.y * 128;
    const int col0 = blockIdx.x * 128;

    // ---- gmem->smem mapping: thread loads rows (tid>>3)+32i, 16B chunk tid&7
    const int mrow = tid >> 3;            // 0..31
    const int c8   = tid & 7;             // 16B chunk within 128B row
    const uint32_t swc = (uint32_t)((c8 ^ (mrow & 7)) << 4);  // swizzled byte chunk

    const float* arow[4];
    const float* brow[4];
    uint32_t stA[4], stB[4];
#pragma unroll
    for (int i = 0; i < 4; i++) {
        const int m = mrow + 32 * i;
        arow[i] = GATHER ? (A + (size_t)map_row(row0 + m) * CH)
                         : (A + (size_t)(row0 + m) * Kd);
        brow[i] = Bt + (size_t)(col0 + m) * Kd;
        stA[i] = (uint32_t)(m * 128) + swc;            // byte offsets within stage
        stB[i] = stA[i] + 16384;
    }

    // ---- ldmatrix address components (per lane)
    // A: lanes 0-7 rows 0-7, 8-15 rows 8-15 (chunk lo), 16-23 rows 0-7 (chunk hi), 24-31 rows 8-15 (hi)
    const int rA   = warp_m * 64 + (lane & 15);        // + mt*16
    const int hiA  = lane >> 4;                        // chunk +1 half
    const int xA   = lane & 7;
    // B: lanes 0-7 rows n0..7 lo, 8-15 same rows hi, 16-23 rows +8 lo, 24-31 rows +8 hi
    const int rB   = warp_n * 32 + ((lane >> 4) << 3) + (lane & 7);   // + p*16
    const int hiB  = (lane >> 3) & 1;
    const int xB   = lane & 7;

    float acc[4][4][4];
#pragma unroll
    for (int i = 0; i < 4; i++)
#pragma unroll
        for (int j = 0; j < 4; j++)
#pragma unroll
            for (int e = 0; e < 4; e++) acc[i][j][e] = 0.f;

    const int T = Kd >> 5;

    // prologue: tile 0 -> stage 0
#pragma unroll
    for (int i = 0; i < 4; i++) {
        float4 av = tf32x4(*(const float4*)(arow[i] + c8 * 4));
        float4 bv = tf32x4(*(const float4*)(brow[i] + c8 * 4));
        *(float4*)((char*)smem + stA[i]) = av;
        *(float4*)((char*)smem + stB[i]) = bv;
    }
    __syncthreads();

    for (int t = 0; t < T; ++t) {
        // prefetch next tile into registers
        float4 pa[4], pb[4];
        if (t + 1 < T) {
            const int k0 = (t + 1) * 32 + c8 * 4;
#pragma unroll
            for (int i = 0; i < 4; i++) {
                pa[i] = *(const float4*)(arow[i] + k0);
                pb[i] = *(const float4*)(brow[i] + k0);
            }
        }

        // compute current stage
        const uint32_t sa = sbase + (t & 1) * (STAGE_FLOATS * 4);
        const uint32_t sb = sa + 16384;
#pragma unroll
        for (int kc = 0; kc < 4; kc++) {
            uint32_t af[4][4];
#pragma unroll
            for (int mt = 0; mt < 4; mt++) {
                const uint32_t addr = sa + (uint32_t)((rA + mt * 16) * 128)
                                    + (uint32_t)((((kc << 1) + hiA) ^ xA) << 4);
                LDMX4(af[mt][0], af[mt][1], af[mt][2], af[mt][3], addr);
            }
            uint32_t bf[4][2];
#pragma unroll
            for (int p = 0; p < 2; p++) {
                const uint32_t addr = sb + (uint32_t)((rB + p * 16) * 128)
                                    + (uint32_t)((((kc << 1) + hiB) ^ xB) << 4);
                LDMX4(bf[2*p][0], bf[2*p][1], bf[2*p+1][0], bf[2*p+1][1], addr);
            }
#pragma unroll
            for (int mt = 0; mt < 4; mt++)
#pragma unroll
                for (int nt = 0; nt < 4; nt++)
                    MMA_TF32(acc[mt][nt], af[mt][0], af[mt][1], af[mt][2], af[mt][3],
                             bf[nt][0], bf[nt][1]);
        }

        // store next tile
        if (t + 1 < T) {
            const uint32_t so = ((t + 1) & 1) * (STAGE_FLOATS * 4);
#pragma unroll
            for (int i = 0; i < 4; i++) {
                *(float4*)((char*)smem + so + stA[i]) = tf32x4(pa[i]);
                *(float4*)((char*)smem + so + stB[i]) = tf32x4(pb[i]);
            }
        }
        __syncthreads();
    }

    // ---- epilogue: bias (+gelu), write C
    const int rbase = row0 + warp_m * 64 + (lane >> 2);
    const int cb0   = col0 + warp_n * 32 + 2 * (lane & 3);
#pragma unroll
    for (int nt = 0; nt < 4; nt++) {
        const int cc = cb0 + nt * 8;
        const float bv0 = bias[cc], bv1 = bias[cc + 1];
#pragma unroll
        for (int mt = 0; mt < 4; mt++) {
            const int r = rbase + mt * 16;
            float v[4];
#pragma unroll
            for (int e = 0; e < 4; e++) {
                float x = acc[mt][nt][e] + ((e & 1) ? bv1 : bv0);
                if (GELU) {
                    float x3 = x * x * x;
                    x = 0.5f * x * (1.f + tanhf(0.7978845608028654f * (x + 0.044715f * x3)));
                }
                v[e] = x;
            }
            *(float2*)(C + (size_t)r * N + cc)       = make_float2(v[0], v[1]);
            *(float2*)(C + (size_t)(r + 8) * N + cc) = make_float2(v[2], v[3]);
        }
    }
}

// ---------------- attention: online softmax, logits in regs --------------------
__global__ __launch_bounds__(64)
void attn_kernel(const float* __restrict__ qkv, const float* __restrict__ rpe,
                 const float* __restrict__ mask, const int* __restrict__ rel,
                 float* __restrict__ o)
{
    const int w = blockIdx.x, head = blockIdx.y, t = threadIdx.x;
    __shared__ __align__(16) float ks[64][32];
    __shared__ __align__(16) float vs[64][32];

    const size_t rbase = (size_t)(w * 64 + t) * 768 + head * 32;
    const float4* kr = (const float4*)(qkv + rbase + 256);
    const float4* vr = (const float4*)(qkv + rbase + 512);
#pragma unroll
    for (int i = 0; i < 8; i++) {
        ((float4*)ks[t])[i] = kr[i];
        ((float4*)vs[t])[i] = vr[i];
    }
    float qr[32];
    const float* qp = qkv + rbase;
#pragma unroll
    for (int d = 0; d < 32; d++) qr[d] = qp[d] * 0.17677669529663687f;
    __syncthreads();

    const float* mrow = mask + (size_t)(w & 63) * 4096 + t * 64;
    const int*   rrow = rel + t * 64;

    float mx = -1e30f, sum = 0.f;
    float ov[32];
#pragma unroll
    for (int d = 0; d < 32; d++) ov[d] = 0.f;

    for (int c = 0; c < 4; c++) {
        float lg[16];
        float cmx = -1e30f;
#pragma unroll
        for (int i = 0; i < 16; i++) {
            const int s = c * 16 + i;
            float dot = 0.f;
#pragma unroll
            for (int d = 0; d < 32; d++) dot = fmaf(qr[d], ks[s][d], dot);
            dot += rpe[rrow[s] * NHEAD + head] + mrow[s];
            lg[i] = dot;
            cmx = fmaxf(cmx, dot);
        }
        const float nmx = fmaxf(mx, cmx);
        const float scl = __expf(mx - nmx);
        sum *= scl;
#pragma unroll
        for (int d = 0; d < 32; d++) ov[d] *= scl;
#pragma unroll
        for (int i = 0; i < 16; i++) {
            float e = __expf(lg[i] - nmx);
            lg[i] = e;
            sum += e;
        }
#pragma unroll
        for (int i = 0; i < 16; i++) {
            const int s = c * 16 + i;
            const float p = lg[i];
#pragma unroll
            for (int d = 0; d < 32; d++) ov[d] = fmaf(p, vs[s][d], ov[d]);
        }
        mx = nmx;
    }
    const float inv = 1.f / sum;
    float* op = o + (size_t)(w * 64 + t) * 256 + head * 32;
#pragma unroll
    for (int d = 0; d < 32; d += 4)
        *(float4*)(op + d) = make_float4(ov[d]*inv, ov[d+1]*inv, ov[d+2]*inv, ov[d+3]*inv);
}

// ---------------- LayerNorm (+residual) ----------------------------------------
__device__ __forceinline__ void block_stats(float val, float& mean, float& var) {
    float s = val, s2 = val * val;
#pragma unroll
    for (int off = 16; off; off >>= 1) {
        s  += __shfl_xor_sync(0xffffffffu, s,  off);
        s2 += __shfl_xor_sync(0xffffffffu, s2, off);
    }
    __shared__ float sh[8], sh2[8];
    int lane = threadIdx.x & 31, warp = threadIdx.x >> 5;
    if (lane == 0) { sh[warp] = s; sh2[warp] = s2; }
    __syncthreads();
    float sum = 0.f, sq = 0.f;
#pragma unroll
    for (int i = 0; i < 8; i++) { sum += sh[i]; sq += sh2[i]; }
    mean = sum * (1.f / 256.f);
    var  = sq * (1.f / 256.f) - mean * mean;
}

__global__ __launch_bounds__(256)
void ln1_kernel(const float* __restrict__ X, const float* __restrict__ g,
                const float* __restrict__ b, const float* __restrict__ query,
                float* __restrict__ out)
{
    const int row = blockIdx.x, c = threadIdx.x;
    const float val = X[(size_t)row * CH + c];
    float mean, var;
    block_stats(val, mean, var);
    const float y = (val - mean) * rsqrtf(var + 1e-5f) * g[c] + b[c];
    out[(size_t)row * CH + c] = y + query[(size_t)map_row(row) * CH + c];
}

__global__ __launch_bounds__(256)
void ln2_kernel(const float* __restrict__ X, const float* __restrict__ g,
                const float* __restrict__ b, const float* __restrict__ x2,
                float* __restrict__ out)
{
    const int row = blockIdx.x, c = threadIdx.x;
    const float val = X[(size_t)row * CH + c];
    float mean, var;
    block_stats(val, mean, var);
    const float y = (val - mean) * rsqrtf(var + 1e-5f) * g[c] + b[c];
    out[(size_t)map_row(row) * CH + c] = y + x2[(size_t)row * CH + c];
}

// ---------------- weight prep: transpose to [N,K] ------------------------------
__global__ __launch_bounds__(256)
void prep_kernel(const float* __restrict__ wq, const float* __restrict__ wk,
                 const float* __restrict__ wv, const float* __restrict__ bq,
                 const float* __restrict__ bk, const float* __restrict__ bv,
                 const float* __restrict__ wo, const float* __restrict__ w1,
                 const float* __restrict__ w2,
                 float* __restrict__ wqkvT, float* __restrict__ bqkv,
                 float* __restrict__ woT, float* __restrict__ w1T,
                 float* __restrict__ w2T)
{
    int i = blockIdx.x * 256 + threadIdx.x;
    if (i < 196608) {                       // wqkvT [768][256]
        int n = i >> 8, k = i & 255;
        wqkvT[i] = (n < 256) ? wq[k * 256 + n]
                 : (n < 512) ? wk[k * 256 + (n - 256)]
                             : wv[k * 256 + (n - 512)];
    } else if (i < 262144) {                // woT [256][256]
        int j = i - 196608; int n = j >> 8, k = j & 255;
        woT[j] = wo[k * 256 + n];
    } else if (i < 458752) {                // w1T [768][256]
        int j = i - 262144; int n = j >> 8, k = j & 255;
        w1T[j] = w1[k * 768 + n];
    } else if (i < 655360) {                // w2T [256][768]
        int j = i - 458752; int n = j / 768, k = j - n * 768;
        w2T[j] = w2[k * 256 + n];
    } else if (i < 656128) {                // bqkv [768]
        int n = i - 655360;
        bqkv[n] = (n < 256) ? bq[n] : (n < 512) ? bk[n - 256] : bv[n - 512];
    }
}

// ---------------- launch --------------------------------------------------------
extern "C" void kernel_launch(void* const* d_in, const int* in_sizes, int n_in,
                              void* d_out, int out_size)
{
    const float* query = (const float*)d_in[0];
    const float* wq = (const float*)d_in[1];  const float* bq = (const float*)d_in[2];
    const float* wk = (const float*)d_in[3];  const float* bk = (const float*)d_in[4];
    const float* wv = (const float*)d_in[5];  const float* bv = (const float*)d_in[6];
    const float* wo = (const float*)d_in[7];  const float* bo = (const float*)d_in[8];
    const float* rpe = (const float*)d_in[9];
    const float* ln1g = (const float*)d_in[10]; const float* ln1b = (const float*)d_in[11];
    const float* ln2g = (const float*)d_in[12]; const float* ln2b = (const float*)d_in[13];
    const float* w1 = (const float*)d_in[14]; const float* b1 = (const float*)d_in[15];
    const float* w2 = (const float*)d_in[16]; const float* b2 = (const float*)d_in[17];
    const float* amask = (const float*)d_in[18];
    const int*   rel   = (const int*)d_in[19];
    float* out = (float*)d_out;

    float *qkv, *o, *x2, *h, *wqkvT, *bqkv, *woT, *w1T, *w2T;
    cudaGetSymbolAddress((void**)&qkv,   g_qkv);
    cudaGetSymbolAddress((void**)&o,     g_o);
    cudaGetSymbolAddress((void**)&x2,    g_x2);
    cudaGetSymbolAddress((void**)&h,     g_h);
    cudaGetSymbolAddress((void**)&wqkvT, g_wqkvT);
    cudaGetSymbolAddress((void**)&bqkv,  g_bqkv);
    cudaGetSymbolAddress((void**)&woT,   g_woT);
    cudaGetSymbolAddress((void**)&w1T,   g_w1T);
    cudaGetSymbolAddress((void**)&w2T,   g_w2T);

    cudaFuncSetAttribute(gemm_mma<true,  false>, cudaFuncAttributeMaxDynamicSharedMemorySize, GEMM_SMEM);
    cudaFuncSetAttribute(gemm_mma<false, false>, cudaFuncAttributeMaxDynamicSharedMemorySize, GEMM_SMEM);
    cudaFuncSetAttribute(gemm_mma<false, true >, cudaFuncAttributeMaxDynamicSharedMemorySize, GEMM_SMEM);

    // weight transposes + fused qkv weights
    prep_kernel<<<2563, 256>>>(wq, wk, wv, bq, bk, bv, wo, w1, w2,
                               wqkvT, bqkv, woT, w1T, w2T);

    // fused QKV projection (gather of roll+window-partition on A rows)
    gemm_mma<true,  false><<<dim3(6, 1024), 256, GEMM_SMEM>>>(query, wqkvT, bqkv, qkv, 768, 256);

    // windowed attention
    attn_kernel<<<dim3(TOTW, NHEAD), 64>>>(qkv, rpe, amask, rel, o);

    // output projection
    gemm_mma<false, false><<<dim3(2, 1024), 256, GEMM_SMEM>>>(o, woT, bo, h, 256, 256);

    // LN1 + residual
    ln1_kernel<<<MROWS, 256>>>(h, ln1g, ln1b, query, x2);

    // MLP
    gemm_mma<false, true ><<<dim3(6, 1024), 256, GEMM_SMEM>>>(x2, w1T, b1, qkv, 768, 256);
    gemm_mma<false, false><<<dim3(2, 1024), 256, GEMM_SMEM>>>(qkv, w2T, b2, o, 256, 768);

    // LN2 + residual, scatter to output
    ln2_kernel<<<MROWS, 256>>>(o, ln2g, ln2b, x2, out);
}

// round 4
// speedup vs baseline: 2.4386x; 1.1404x over previous
#include <cuda_runtime.h>
#include <math.h>
#include <stdint.h>

#define BATCH 32
#define CH    256
#define EMB   256
#define NHEAD 8
#define SHFT  4
#define TT    64
#define TOTW  2048
#define MROWS 131072
#define HID   768

// ---------------- scratch ----------------
__device__ float g_qkv[(size_t)MROWS * 768];   // qkv out; later mlp1 out
__device__ float g_o  [(size_t)MROWS * 256];   // attn out; later mlp2 out
__device__ float g_x2 [(size_t)MROWS * 256];
__device__ float g_h  [(size_t)MROWS * 256];   // proj out
__device__ float g_wqkvT[768 * 256];
__device__ float g_bqkv [768];
__device__ float g_woT  [256 * 256];
__device__ float g_w1T  [768 * 256];
__device__ float g_w2T  [256 * 768];

// row (window*64+token) -> pixel index in original query (folds roll by -S)
__device__ __forceinline__ int map_row(int row) {
    int w  = row >> 6;
    int t  = row & 63;
    int b  = w >> 6;
    int wi = w & 63;
    int hb = wi >> 3, wb = wi & 7;
    int i  = ((hb << 3) + (t >> 3) + SHFT) & 63;
    int j  = ((wb << 3) + (t & 7) + SHFT) & 63;
    return (b << 12) + (i << 6) + j;
}

__device__ __forceinline__ uint32_t smem_u32(const void* p) {
    uint32_t a;
    asm("{ .reg .u64 t; cvta.to.shared.u64 t, %1; cvt.u32.u64 %0, t; }" : "=r"(a) : "l"(p));
    return a;
}

__device__ __forceinline__ void cvt_tf32(uint32_t& x) {
    asm("{.reg .f32 f; mov.b32 f, %0; cvt.rn.tf32.f32 %0, f;}" : "+r"(x));
}

__device__ __forceinline__ float tanh_fast(float x) {
    float r;
    asm("tanh.approx.f32 %0, %1;" : "=f"(r) : "f"(x));
    return r;
}

#define LDMX4(r0, r1, r2, r3, addr) \
    asm volatile("ldmatrix.sync.aligned.m8n8.x4.shared.b16 {%0,%1,%2,%3}, [%4];" \
        : "=r"(r0), "=r"(r1), "=r"(r2), "=r"(r3) : "r"(addr))

#define MMA_TF32(d, a0, a1, a2, a3, b0, b1) \
    asm volatile("mma.sync.aligned.m16n8k8.row.col.f32.tf32.tf32.f32 " \
        "{%0,%1,%2,%3}, {%4,%5,%6,%7}, {%8,%9}, {%0,%1,%2,%3};" \
        : "+f"((d)[0]), "+f"((d)[1]), "+f"((d)[2]), "+f"((d)[3]) \
        : "r"(a0), "r"(a1), "r"(a2), "r"(a3), "r"(b0), "r"(b1))

#define CP_ASYNC16(dst, src) \
    asm volatile("cp.async.cg.shared.global [%0], [%1], 16;" :: "r"(dst), "l"(src))
#define CP_COMMIT()  asm volatile("cp.async.commit_group;" ::: "memory")
#define CP_WAIT1()   asm volatile("cp.async.wait_group 1;" ::: "memory")

// ---------------- tf32 mma.sync GEMM: C[M,N] = A[M,K] @ Bt[N,K]^T + bias -------
// CTA tile 128x128, BK=32, 8 warps (2m x 4n), warp tile 64x32 (4x4 m16n8k8).
// 3-stage cp.async pipeline; smem stage = A(16KB) + B(16KB), XOR-16B swizzle.
#define STAGE_BYTES 32768
#define NSTAGE      3
#define GEMM_SMEM   (NSTAGE * STAGE_BYTES)

template<bool GATHER, bool GELU>
__global__ __launch_bounds__(256, 2)
void gemm_mma(const float* __restrict__ A, const float* __restrict__ Bt,
              const float* __restrict__ bias, float* __restrict__ C,
              int N, int Kd)
{
    extern __shared__ float smem[];
    const uint32_t sbase = smem_u32(smem);
    const int tid  = threadIdx.x;
    const int lane = tid & 31;
    const int wid  = tid >> 5;
    const int warp_m = wid >> 2;          // 0..1
    const int warp_n = wid & 3;           // 0..3
    const int row0 = blockIdx.y * 128;
    const int col0 = blockIdx.x * 128;

    // ---- gmem->smem mapping: thread loads rows (tid>>3)+32i, 16B chunk tid&7
    const int mrow = tid >> 3;            // 0..31
    const int c8   = tid & 7;             // 16B chunk within 128B row
    const uint32_t swc = (uint32_t)((c8 ^ (mrow & 7)) << 4);

    const float* arow[4];
    const float* brow[4];
    uint32_t stA[4];
#pragma unroll
    for (int i = 0; i < 4; i++) {
        const int m = mrow + 32 * i;
        arow[i] = (GATHER ? (A + (size_t)map_row(row0 + m) * CH)
                          : (A + (size_t)(row0 + m) * Kd)) + c8 * 4;
        brow[i] = Bt + (size_t)(col0 + m) * Kd + c8 * 4;
        stA[i] = (uint32_t)(m * 128) + swc;    // byte offset within stage (A); B = +16384
    }

    // ---- ldmatrix address components
    const int rA  = warp_m * 64 + (lane & 15);
    const int hiA = lane >> 4;
    const int xA  = lane & 7;
    const int rB  = warp_n * 32 + ((lane >> 4) << 3) + (lane & 7);
    const int hiB = (lane >> 3) & 1;
    const int xB  = lane & 7;

    float acc[4][4][4];
#pragma unroll
    for (int i = 0; i < 4; i++)
#pragma unroll
        for (int j = 0; j < 4; j++)
#pragma unroll
            for (int e = 0; e < 4; e++) acc[i][j][e] = 0.f;

    const int T = Kd >> 5;

    // prologue: issue stages 0 and 1
#pragma unroll
    for (int s = 0; s < NSTAGE - 1; s++) {
        const int k0 = s * 32;
        const uint32_t so = sbase + s * STAGE_BYTES;
#pragma unroll
        for (int i = 0; i < 4; i++) {
            CP_ASYNC16(so + stA[i],         arow[i] + k0);
            CP_ASYNC16(so + stA[i] + 16384, brow[i] + k0);
        }
        CP_COMMIT();
    }

    for (int t = 0; t < T; ++t) {
        CP_WAIT1();
        __syncthreads();

        // issue stage t+2 (overwrites stage computed in iteration t-1)
        const int kt = t + NSTAGE - 1;
        if (kt < T) {
            const int k0 = kt * 32;
            const uint32_t so = sbase + (kt % NSTAGE) * STAGE_BYTES;
#pragma unroll
            for (int i = 0; i < 4; i++) {
                CP_ASYNC16(so + stA[i],         arow[i] + k0);
                CP_ASYNC16(so + stA[i] + 16384, brow[i] + k0);
            }
        }
        CP_COMMIT();

        // compute stage t
        const uint32_t sa = sbase + (t % NSTAGE) * STAGE_BYTES;
        const uint32_t sb = sa + 16384;
#pragma unroll
        for (int kc = 0; kc < 4; kc++) {
            uint32_t af[4][4];
#pragma unroll
            for (int mt = 0; mt < 4; mt++) {
                const uint32_t addr = sa + (uint32_t)((rA + mt * 16) * 128)
                                    + (uint32_t)((((kc << 1) + hiA) ^ xA) << 4);
                LDMX4(af[mt][0], af[mt][1], af[mt][2], af[mt][3], addr);
                cvt_tf32(af[mt][0]); cvt_tf32(af[mt][1]);
                cvt_tf32(af[mt][2]); cvt_tf32(af[mt][3]);
            }
            uint32_t bf[4][2];
#pragma unroll
            for (int p = 0; p < 2; p++) {
                const uint32_t addr = sb + (uint32_t)((rB + p * 16) * 128)
                                    + (uint32_t)((((kc << 1) + hiB) ^ xB) << 4);
                LDMX4(bf[2*p][0], bf[2*p][1], bf[2*p+1][0], bf[2*p+1][1], addr);
                cvt_tf32(bf[2*p][0]);   cvt_tf32(bf[2*p][1]);
                cvt_tf32(bf[2*p+1][0]); cvt_tf32(bf[2*p+1][1]);
            }
#pragma unroll
            for (int mt = 0; mt < 4; mt++)
#pragma unroll
                for (int nt = 0; nt < 4; nt++)
                    MMA_TF32(acc[mt][nt], af[mt][0], af[mt][1], af[mt][2], af[mt][3],
                             bf[nt][0], bf[nt][1]);
        }
    }

    // ---- epilogue: bias (+gelu), write C
    const int rbase = row0 + warp_m * 64 + (lane >> 2);
    const int cb0   = col0 + warp_n * 32 + 2 * (lane & 3);
#pragma unroll
    for (int nt = 0; nt < 4; nt++) {
        const int cc = cb0 + nt * 8;
        const float bv0 = bias[cc], bv1 = bias[cc + 1];
#pragma unroll
        for (int mt = 0; mt < 4; mt++) {
            const int r = rbase + mt * 16;
            float v[4];
#pragma unroll
            for (int e = 0; e < 4; e++) {
                float x = acc[mt][nt][e] + ((e & 1) ? bv1 : bv0);
                if (GELU) {
                    float x3 = x * x * x;
                    x = 0.5f * x * (1.f + tanh_fast(0.7978845608028654f * (x + 0.044715f * x3)));
                }
                v[e] = x;
            }
            *(float2*)(C + (size_t)r * N + cc)       = make_float2(v[0], v[1]);
            *(float2*)(C + (size_t)(r + 8) * N + cc) = make_float2(v[2], v[3]);
        }
    }
}

// ---------------- attention: online softmax, logits in regs --------------------
__global__ __launch_bounds__(64)
void attn_kernel(const float* __restrict__ qkv, const float* __restrict__ rpe,
                 const float* __restrict__ mask, const int* __restrict__ rel,
                 float* __restrict__ o)
{
    const int w = blockIdx.x, head = blockIdx.y, t = threadIdx.x;
    __shared__ __align__(16) float ks[64][32];
    __shared__ __align__(16) float vs[64][32];

    const size_t rbase = (size_t)(w * 64 + t) * 768 + head * 32;
    const float4* kr = (const float4*)(qkv + rbase + 256);
    const float4* vr = (const float4*)(qkv + rbase + 512);
#pragma unroll
    for (int i = 0; i < 8; i++) {
        ((float4*)ks[t])[i] = kr[i];
        ((float4*)vs[t])[i] = vr[i];
    }
    float qr[32];
    const float* qp = qkv + rbase;
#pragma unroll
    for (int d = 0; d < 32; d++) qr[d] = qp[d] * 0.17677669529663687f;
    __syncthreads();

    const float* mrow = mask + (size_t)(w & 63) * 4096 + t * 64;
    const int*   rrow = rel + t * 64;

    float mx = -1e30f, sum = 0.f;
    float ov[32];
#pragma unroll
    for (int d = 0; d < 32; d++) ov[d] = 0.f;

    for (int c = 0; c < 4; c++) {
        float lg[16];
        float cmx = -1e30f;
#pragma unroll
        for (int i = 0; i < 16; i++) {
            const int s = c * 16 + i;
            float dot = 0.f;
#pragma unroll
            for (int d = 0; d < 32; d++) dot = fmaf(qr[d], ks[s][d], dot);
            dot += rpe[rrow[s] * NHEAD + head] + mrow[s];
            lg[i] = dot;
            cmx = fmaxf(cmx, dot);
        }
        const float nmx = fmaxf(mx, cmx);
        const float scl = __expf(mx - nmx);
        sum *= scl;
#pragma unroll
        for (int d = 0; d < 32; d++) ov[d] *= scl;
#pragma unroll
        for (int i = 0; i < 16; i++) {
            float e = __expf(lg[i] - nmx);
            lg[i] = e;
            sum += e;
        }
#pragma unroll
        for (int i = 0; i < 16; i++) {
            const int s = c * 16 + i;
            const float p = lg[i];
#pragma unroll
            for (int d = 0; d < 32; d++) ov[d] = fmaf(p, vs[s][d], ov[d]);
        }
        mx = nmx;
    }
    const float inv = 1.f / sum;
    float* op = o + (size_t)(w * 64 + t) * 256 + head * 32;
#pragma unroll
    for (int d = 0; d < 32; d += 4)
        *(float4*)(op + d) = make_float4(ov[d]*inv, ov[d+1]*inv, ov[d+2]*inv, ov[d+3]*inv);
}

// ---------------- LayerNorm (+residual) ----------------------------------------
__device__ __forceinline__ void block_stats(float val, float& mean, float& var) {
    float s = val, s2 = val * val;
#pragma unroll
    for (int off = 16; off; off >>= 1) {
        s  += __shfl_xor_sync(0xffffffffu, s,  off);
        s2 += __shfl_xor_sync(0xffffffffu, s2, off);
    }
    __shared__ float sh[8], sh2[8];
    int lane = threadIdx.x & 31, warp = threadIdx.x >> 5;
    if (lane == 0) { sh[warp] = s; sh2[warp] = s2; }
    __syncthreads();
    float sum = 0.f, sq = 0.f;
#pragma unroll
    for (int i = 0; i < 8; i++) { sum += sh[i]; sq += sh2[i]; }
    mean = sum * (1.f / 256.f);
    var  = sq * (1.f / 256.f) - mean * mean;
}

__global__ __launch_bounds__(256)
void ln1_kernel(const float* __restrict__ X, const float* __restrict__ g,
                const float* __restrict__ b, const float* __restrict__ query,
                float* __restrict__ out)
{
    const int row = blockIdx.x, c = threadIdx.x;
    const float val = X[(size_t)row * CH + c];
    float mean, var;
    block_stats(val, mean, var);
    const float y = (val - mean) * rsqrtf(var + 1e-5f) * g[c] + b[c];
    out[(size_t)row * CH + c] = y + query[(size_t)map_row(row) * CH + c];
}

__global__ __launch_bounds__(256)
void ln2_kernel(const float* __restrict__ X, const float* __restrict__ g,
                const float* __restrict__ b, const float* __restrict__ x2,
                float* __restrict__ out)
{
    const int row = blockIdx.x, c = threadIdx.x;
    const float val = X[(size_t)row * CH + c];
    float mean, var;
    block_stats(val, mean, var);
    const float y = (val - mean) * rsqrtf(var + 1e-5f) * g[c] + b[c];
    out[(size_t)map_row(row) * CH + c] = y + x2[(size_t)row * CH + c];
}

// ---------------- weight prep: transpose to [N,K] ------------------------------
__global__ __launch_bounds__(256)
void prep_kernel(const float* __restrict__ wq, const float* __restrict__ wk,
                 const float* __restrict__ wv, const float* __restrict__ bq,
                 const float* __restrict__ bk, const float* __restrict__ bv,
                 const float* __restrict__ wo, const float* __restrict__ w1,
                 const float* __restrict__ w2,
                 float* __restrict__ wqkvT, float* __restrict__ bqkv,
                 float* __restrict__ woT, float* __restrict__ w1T,
                 float* __restrict__ w2T)
{
    int i = blockIdx.x * 256 + threadIdx.x;
    if (i < 196608) {                       // wqkvT [768][256]
        int n = i >> 8, k = i & 255;
        wqkvT[i] = (n < 256) ? wq[k * 256 + n]
                 : (n < 512) ? wk[k * 256 + (n - 256)]
                             : wv[k * 256 + (n - 512)];
    } else if (i < 262144) {                // woT [256][256]
        int j = i - 196608; int n = j >> 8, k = j & 255;
        woT[j] = wo[k * 256 + n];
    } else if (i < 458752) {                // w1T [768][256]
        int j = i - 262144; int n = j >> 8, k = j & 255;
        w1T[j] = w1[k * 768 + n];
    } else if (i < 655360) {                // w2T [256][768]
        int j = i - 458752; int n = j / 768, k = j - n * 768;
        w2T[j] = w2[k * 256 + n];
    } else if (i < 656128) {                // bqkv [768]
        int n = i - 655360;
        bqkv[n] = (n < 256) ? bq[n] : (n < 512) ? bk[n - 256] : bv[n - 512];
    }
}

// ---------------- launch --------------------------------------------------------
extern "C" void kernel_launch(void* const* d_in, const int* in_sizes, int n_in,
                              void* d_out, int out_size)
{
    const float* query = (const float*)d_in[0];
    const float* wq = (const float*)d_in[1];  const float* bq = (const float*)d_in[2];
    const float* wk = (const float*)d_in[3];  const float* bk = (const float*)d_in[4];
    const float* wv = (const float*)d_in[5];  const float* bv = (const float*)d_in[6];
    const float* wo = (const float*)d_in[7];  const float* bo = (const float*)d_in[8];
    const float* rpe = (const float*)d_in[9];
    const float* ln1g = (const float*)d_in[10]; const float* ln1b = (const float*)d_in[11];
    const float* ln2g = (const float*)d_in[12]; const float* ln2b = (const float*)d_in[13];
    const float* w1 = (const float*)d_in[14]; const float* b1 = (const float*)d_in[15];
    const float* w2 = (const float*)d_in[16]; const float* b2 = (const float*)d_in[17];
    const float* amask = (const float*)d_in[18];
    const int*   rel   = (const int*)d_in[19];
    float* out = (float*)d_out;

    float *qkv, *o, *x2, *h, *wqkvT, *bqkv, *woT, *w1T, *w2T;
    cudaGetSymbolAddress((void**)&qkv,   g_qkv);
    cudaGetSymbolAddress((void**)&o,     g_o);
    cudaGetSymbolAddress((void**)&x2,    g_x2);
    cudaGetSymbolAddress((void**)&h,     g_h);
    cudaGetSymbolAddress((void**)&wqkvT, g_wqkvT);
    cudaGetSymbolAddress((void**)&bqkv,  g_bqkv);
    cudaGetSymbolAddress((void**)&woT,   g_woT);
    cudaGetSymbolAddress((void**)&w1T,   g_w1T);
    cudaGetSymbolAddress((void**)&w2T,   g_w2T);

    cudaFuncSetAttribute(gemm_mma<true,  false>, cudaFuncAttributeMaxDynamicSharedMemorySize, GEMM_SMEM);
    cudaFuncSetAttribute(gemm_mma<false, false>, cudaFuncAttributeMaxDynamicSharedMemorySize, GEMM_SMEM);
    cudaFuncSetAttribute(gemm_mma<false, true >, cudaFuncAttributeMaxDynamicSharedMemorySize, GEMM_SMEM);

    // weight transposes + fused qkv weights
    prep_kernel<<<2563, 256>>>(wq, wk, wv, bq, bk, bv, wo, w1, w2,
                               wqkvT, bqkv, woT, w1T, w2T);

    // fused QKV projection (gather of roll+window-partition on A rows)
    gemm_mma<true,  false><<<dim3(6, 1024), 256, GEMM_SMEM>>>(query, wqkvT, bqkv, qkv, 768, 256);

    // windowed attention
    attn_kernel<<<dim3(TOTW, NHEAD), 64>>>(qkv, rpe, amask, rel, o);

    // output projection
    gemm_mma<false, false><<<dim3(2, 1024), 256, GEMM_SMEM>>>(o, woT, bo, h, 256, 256);

    // LN1 + residual
    ln1_kernel<<<MROWS, 256>>>(h, ln1g, ln1b, query, x2);

    // MLP
    gemm_mma<false, true ><<<dim3(6, 1024), 256, GEMM_SMEM>>>(x2, w1T, b1, qkv, 768, 256);
    gemm_mma<false, false><<<dim3(2, 1024), 256, GEMM_SMEM>>>(qkv, w2T, b2, o, 256, 768);

    // LN2 + residual, scatter to output
    ln2_kernel<<<MROWS, 256>>>(o, ln2g, ln2b, x2, out);
}

// round 5
// speedup vs baseline: 2.4629x; 1.0100x over previous
#include <cuda_runtime.h>
#include <math.h>
#include <stdint.h>

#define BATCH 32
#define CH    256
#define EMB   256
#define NHEAD 8
#define SHFT  4
#define TT    64
#define TOTW  2048
#define MROWS 131072
#define HID   768

// ---------------- scratch ----------------
__device__ float g_qkv[(size_t)MROWS * 768];   // qkv out; later mlp1 out
__device__ float g_o  [(size_t)MROWS * 256];   // attn out; later mlp2 out
__device__ float g_x2 [(size_t)MROWS * 256];
__device__ float g_h  [(size_t)MROWS * 256];   // proj out
__device__ float g_wqkvT[768 * 256];
__device__ float g_bqkv [768];
__device__ float g_woT  [256 * 256];
__device__ float g_w1T  [768 * 256];
__device__ float g_w2T  [256 * 768];

// row (window*64+token) -> pixel index in original query (folds roll by -S)
__device__ __forceinline__ int map_row(int row) {
    int w  = row >> 6;
    int t  = row & 63;
    int b  = w >> 6;
    int wi = w & 63;
    int hb = wi >> 3, wb = wi & 7;
    int i  = ((hb << 3) + (t >> 3) + SHFT) & 63;
    int j  = ((wb << 3) + (t & 7) + SHFT) & 63;
    return (b << 12) + (i << 6) + j;
}

__device__ __forceinline__ uint32_t smem_u32(const void* p) {
    uint32_t a;
    asm("{ .reg .u64 t; cvta.to.shared.u64 t, %1; cvt.u32.u64 %0, t; }" : "=r"(a) : "l"(p));
    return a;
}

__device__ __forceinline__ void cvt_tf32(uint32_t& x) {
    asm("{.reg .f32 f; mov.b32 f, %0; cvt.rn.tf32.f32 %0, f;}" : "+r"(x));
}
__device__ __forceinline__ float round_tf32(float x) {
    asm("cvt.rn.tf32.f32 %0, %0;" : "+f"(x));
    return x;
}

__device__ __forceinline__ float tanh_fast(float x) {
    float r;
    asm("tanh.approx.f32 %0, %1;" : "=f"(r) : "f"(x));
    return r;
}

#define LDMX4(r0, r1, r2, r3, addr) \
    asm volatile("ldmatrix.sync.aligned.m8n8.x4.shared.b16 {%0,%1,%2,%3}, [%4];" \
        : "=r"(r0), "=r"(r1), "=r"(r2), "=r"(r3) : "r"(addr))

#define MMA_TF32(d, a0, a1, a2, a3, b0, b1) \
    asm volatile("mma.sync.aligned.m16n8k8.row.col.f32.tf32.tf32.f32 " \
        "{%0,%1,%2,%3}, {%4,%5,%6,%7}, {%8,%9}, {%0,%1,%2,%3};" \
        : "+f"((d)[0]), "+f"((d)[1]), "+f"((d)[2]), "+f"((d)[3]) \
        : "r"(a0), "r"(a1), "r"(a2), "r"(a3), "r"(b0), "r"(b1))

#define CP_ASYNC16(dst, src) \
    asm volatile("cp.async.cg.shared.global [%0], [%1], 16;" :: "r"(dst), "l"(src))
#define CP_COMMIT()  asm volatile("cp.async.commit_group;" ::: "memory")
#define CP_WAIT1()   asm volatile("cp.async.wait_group 1;" ::: "memory")

// ---------------- tf32 mma.sync GEMM: C[M,N] = A[M,K] @ Bt[N,K]^T + bias -------
// CTA tile 128x128, BK=32, 8 warps (2m x 4n), warp tile 64x32 (4x4 m16n8k8).
// 3-stage cp.async pipeline; smem stage = A(16KB) + B(16KB), XOR-16B swizzle.
// B is ALWAYS pre-rounded to tf32 (prep_kernel). A is pre-rounded by its
// producer unless CVTA=1 (then fragments are rounded in-loop).
#define STAGE_BYTES 32768
#define NSTAGE      3
#define GEMM_SMEM   (NSTAGE * STAGE_BYTES)

template<bool GATHER, bool GELU, bool CVTA>
__global__ __launch_bounds__(256, 2)
void gemm_mma(const float* __restrict__ A, const float* __restrict__ Bt,
              const float* __restrict__ bias, float* __restrict__ C,
              int N, int Kd)
{
    extern __shared__ float smem[];
    const uint32_t sbase = smem_u32(smem);
    const int tid  = threadIdx.x;
    const int lane = tid & 31;
    const int wid  = tid >> 5;
    const int warp_m = wid >> 2;          // 0..1
    const int warp_n = wid & 3;           // 0..3
    const int row0 = blockIdx.y * 128;
    const int col0 = blockIdx.x * 128;

    // ---- gmem->smem mapping: thread loads rows (tid>>3)+32i, 16B chunk tid&7
    const int mrow = tid >> 3;            // 0..31
    const int c8   = tid & 7;             // 16B chunk within 128B row
    const uint32_t swc = (uint32_t)((c8 ^ (mrow & 7)) << 4);

    const float* arow[4];
    const float* brow[4];
    uint32_t stA[4];
#pragma unroll
    for (int i = 0; i < 4; i++) {
        const int m = mrow + 32 * i;
        arow[i] = (GATHER ? (A + (size_t)map_row(row0 + m) * CH)
                          : (A + (size_t)(row0 + m) * Kd)) + c8 * 4;
        brow[i] = Bt + (size_t)(col0 + m) * Kd + c8 * 4;
        stA[i] = (uint32_t)(m * 128) + swc;    // byte offset within stage (A); B = +16384
    }

    // ---- ldmatrix address components
    const int rA  = warp_m * 64 + (lane & 15);
    const int hiA = lane >> 4;
    const int xA  = lane & 7;
    const int rB  = warp_n * 32 + ((lane >> 4) << 3) + (lane & 7);
    const int hiB = (lane >> 3) & 1;
    const int xB  = lane & 7;

    float acc[4][4][4];
#pragma unroll
    for (int i = 0; i < 4; i++)
#pragma unroll
        for (int j = 0; j < 4; j++)
#pragma unroll
            for (int e = 0; e < 4; e++) acc[i][j][e] = 0.f;

    const int T = Kd >> 5;

    // prologue: issue stages 0 and 1
#pragma unroll
    for (int s = 0; s < NSTAGE - 1; s++) {
        const int k0 = s * 32;
        const uint32_t so = sbase + s * STAGE_BYTES;
#pragma unroll
        for (int i = 0; i < 4; i++) {
            CP_ASYNC16(so + stA[i],         arow[i] + k0);
            CP_ASYNC16(so + stA[i] + 16384, brow[i] + k0);
        }
        CP_COMMIT();
    }

    for (int t = 0; t < T; ++t) {
        CP_WAIT1();
        __syncthreads();

        // issue stage t+2 (overwrites stage computed in iteration t-1)
        const int kt = t + NSTAGE - 1;
        if (kt < T) {
            const int k0 = kt * 32;
            const uint32_t so = sbase + (kt % NSTAGE) * STAGE_BYTES;
#pragma unroll
            for (int i = 0; i < 4; i++) {
                CP_ASYNC16(so + stA[i],         arow[i] + k0);
                CP_ASYNC16(so + stA[i] + 16384, brow[i] + k0);
            }
        }
        CP_COMMIT();

        // compute stage t
        const uint32_t sa = sbase + (t % NSTAGE) * STAGE_BYTES;
        const uint32_t sb = sa + 16384;
#pragma unroll
        for (int kc = 0; kc < 4; kc++) {
            uint32_t af[4][4];
#pragma unroll
            for (int mt = 0; mt < 4; mt++) {
                const uint32_t addr = sa + (uint32_t)((rA + mt * 16) * 128)
                                    + (uint32_t)((((kc << 1) + hiA) ^ xA) << 4);
                LDMX4(af[mt][0], af[mt][1], af[mt][2], af[mt][3], addr);
                if (CVTA) {
                    cvt_tf32(af[mt][0]); cvt_tf32(af[mt][1]);
                    cvt_tf32(af[mt][2]); cvt_tf32(af[mt][3]);
                }
            }
            uint32_t bf[4][2];
#pragma unroll
            for (int p = 0; p < 2; p++) {
                const uint32_t addr = sb + (uint32_t)((rB + p * 16) * 128)
                                    + (uint32_t)((((kc << 1) + hiB) ^ xB) << 4);
                LDMX4(bf[2*p][0], bf[2*p][1], bf[2*p+1][0], bf[2*p+1][1], addr);
            }
#pragma unroll
            for (int mt = 0; mt < 4; mt++)
#pragma unroll
                for (int nt = 0; nt < 4; nt++)
                    MMA_TF32(acc[mt][nt], af[mt][0], af[mt][1], af[mt][2], af[mt][3],
                             bf[nt][0], bf[nt][1]);
        }
    }

    // ---- epilogue: bias (+gelu), write C
    const int rbase = row0 + warp_m * 64 + (lane >> 2);
    const int cb0   = col0 + warp_n * 32 + 2 * (lane & 3);
#pragma unroll
    for (int nt = 0; nt < 4; nt++) {
        const int cc = cb0 + nt * 8;
        const float bv0 = bias[cc], bv1 = bias[cc + 1];
#pragma unroll
        for (int mt = 0; mt < 4; mt++) {
            const int r = rbase + mt * 16;
            float v[4];
#pragma unroll
            for (int e = 0; e < 4; e++) {
                float x = acc[mt][nt][e] + ((e & 1) ? bv1 : bv0);
                if (GELU) {
                    float x3 = x * x * x;
                    x = 0.5f * x * (1.f + tanh_fast(0.7978845608028654f * (x + 0.044715f * x3)));
                    x = round_tf32(x);   // feeds mlp2 A operand
                }
                v[e] = x;
            }
            *(float2*)(C + (size_t)r * N + cc)       = make_float2(v[0], v[1]);
            *(float2*)(C + (size_t)(r + 8) * N + cc) = make_float2(v[2], v[3]);
        }
    }
}

// ---------------- attention: online softmax, logits in regs --------------------
__global__ __launch_bounds__(64)
void attn_kernel(const float* __restrict__ qkv, const float* __restrict__ rpe,
                 const float* __restrict__ mask, const int* __restrict__ rel,
                 float* __restrict__ o)
{
    const int w = blockIdx.x, head = blockIdx.y, t = threadIdx.x;
    __shared__ __align__(16) float ks[64][32];
    __shared__ __align__(16) float vs[64][32];

    const size_t rbase = (size_t)(w * 64 + t) * 768 + head * 32;
    const float4* kr = (const float4*)(qkv + rbase + 256);
    const float4* vr = (const float4*)(qkv + rbase + 512);
#pragma unroll
    for (int i = 0; i < 8; i++) {
        ((float4*)ks[t])[i] = kr[i];
        ((float4*)vs[t])[i] = vr[i];
    }
    float qr[32];
    const float* qp = qkv + rbase;
#pragma unroll
    for (int d = 0; d < 32; d++) qr[d] = qp[d] * 0.17677669529663687f;
    __syncthreads();

    const float* mrow = mask + (size_t)(w & 63) * 4096 + t * 64;
    const int*   rrow = rel + t * 64;

    float mx = -1e30f, sum = 0.f;
    float ov[32];
#pragma unroll
    for (int d = 0; d < 32; d++) ov[d] = 0.f;

    for (int c = 0; c < 4; c++) {
        float lg[16];
        float cmx = -1e30f;
#pragma unroll
        for (int i = 0; i < 16; i++) {
            const int s = c * 16 + i;
            float dot = 0.f;
#pragma unroll
            for (int d = 0; d < 32; d++) dot = fmaf(qr[d], ks[s][d], dot);
            dot += rpe[rrow[s] * NHEAD + head] + mrow[s];
            lg[i] = dot;
            cmx = fmaxf(cmx, dot);
        }
        const float nmx = fmaxf(mx, cmx);
        const float scl = __expf(mx - nmx);
        sum *= scl;
#pragma unroll
        for (int d = 0; d < 32; d++) ov[d] *= scl;
#pragma unroll
        for (int i = 0; i < 16; i++) {
            float e = __expf(lg[i] - nmx);
            lg[i] = e;
            sum += e;
        }
#pragma unroll
        for (int i = 0; i < 16; i++) {
            const int s = c * 16 + i;
            const float p = lg[i];
#pragma unroll
            for (int d = 0; d < 32; d++) ov[d] = fmaf(p, vs[s][d], ov[d]);
        }
        mx = nmx;
    }
    const float inv = 1.f / sum;
    float* op = o + (size_t)(w * 64 + t) * 256 + head * 32;
#pragma unroll
    for (int d = 0; d < 32; d += 4)
        *(float4*)(op + d) = make_float4(round_tf32(ov[d]*inv),   round_tf32(ov[d+1]*inv),
                                         round_tf32(ov[d+2]*inv), round_tf32(ov[d+3]*inv));
}

// ---------------- LayerNorm (+residual) ----------------------------------------
__device__ __forceinline__ void block_stats(float val, float& mean, float& var) {
    float s = val, s2 = val * val;
#pragma unroll
    for (int off = 16; off; off >>= 1) {
        s  += __shfl_xor_sync(0xffffffffu, s,  off);
        s2 += __shfl_xor_sync(0xffffffffu, s2, off);
    }
    __shared__ float sh[8], sh2[8];
    int lane = threadIdx.x & 31, warp = threadIdx.x >> 5;
    if (lane == 0) { sh[warp] = s; sh2[warp] = s2; }
    __syncthreads();
    float sum = 0.f, sq = 0.f;
#pragma unroll
    for (int i = 0; i < 8; i++) { sum += sh[i]; sq += sh2[i]; }
    mean = sum * (1.f / 256.f);
    var  = sq * (1.f / 256.f) - mean * mean;
}

// x2 = round_tf32( LN1(proj) + gather(query) )   (x2 feeds mlp1 A + ln2 residual)
__global__ __launch_bounds__(256)
void ln1_kernel(const float* __restrict__ X, const float* __restrict__ g,
                const float* __restrict__ b, const float* __restrict__ query,
                float* __restrict__ out)
{
    const int row = blockIdx.x, c = threadIdx.x;
    const float val = X[(size_t)row * CH + c];
    float mean, var;
    block_stats(val, mean, var);
    const float y = (val - mean) * rsqrtf(var + 1e-5f) * g[c] + b[c];
    out[(size_t)row * CH + c] = round_tf32(y + query[(size_t)map_row(row) * CH + c]);
}

__global__ __launch_bounds__(256)
void ln2_kernel(const float* __restrict__ X, const float* __restrict__ g,
                const float* __restrict__ b, const float* __restrict__ x2,
                float* __restrict__ out)
{
    const int row = blockIdx.x, c = threadIdx.x;
    const float val = X[(size_t)row * CH + c];
    float mean, var;
    block_stats(val, mean, var);
    const float y = (val - mean) * rsqrtf(var + 1e-5f) * g[c] + b[c];
    out[(size_t)map_row(row) * CH + c] = y + x2[(size_t)row * CH + c];
}

// ---------------- weight prep: transpose to [N,K], pre-round to tf32 -----------
__global__ __launch_bounds__(256)
void prep_kernel(const float* __restrict__ wq, const float* __restrict__ wk,
                 const float* __restrict__ wv, const float* __restrict__ bq,
                 const float* __restrict__ bk, const float* __restrict__ bv,
                 const float* __restrict__ wo, const float* __restrict__ w1,
                 const float* __restrict__ w2,
                 float* __restrict__ wqkvT, float* __restrict__ bqkv,
                 float* __restrict__ woT, float* __restrict__ w1T,
                 float* __restrict__ w2T)
{
    int i = blockIdx.x * 256 + threadIdx.x;
    if (i < 196608) {                       // wqkvT [768][256]
        int n = i >> 8, k = i & 255;
        float v = (n < 256) ? wq[k * 256 + n]
                : (n < 512) ? wk[k * 256 + (n - 256)]
                            : wv[k * 256 + (n - 512)];
        wqkvT[i] = round_tf32(v);
    } else if (i < 262144) {                // woT [256][256]
        int j = i - 196608; int n = j >> 8, k = j & 255;
        woT[j] = round_tf32(wo[k * 256 + n]);
    } else if (i < 458752) {                // w1T [768][256]
        int j = i - 262144; int n = j >> 8, k = j & 255;
        w1T[j] = round_tf32(w1[k * 768 + n]);
    } else if (i < 655360) {                // w2T [256][768]
        int j = i - 458752; int n = j / 768, k = j - n * 768;
        w2T[j] = round_tf32(w2[k * 256 + n]);
    } else if (i < 656128) {                // bqkv [768]
        int n = i - 655360;
        bqkv[n] = (n < 256) ? bq[n] : (n < 512) ? bk[n - 256] : bv[n - 512];
    }
}

// ---------------- launch --------------------------------------------------------
extern "C" void kernel_launch(void* const* d_in, const int* in_sizes, int n_in,
                              void* d_out, int out_size)
{
    const float* query = (const float*)d_in[0];
    const float* wq = (const float*)d_in[1];  const float* bq = (const float*)d_in[2];
    const float* wk = (const float*)d_in[3];  const float* bk = (const float*)d_in[4];
    const float* wv = (const float*)d_in[5];  const float* bv = (const float*)d_in[6];
    const float* wo = (const float*)d_in[7];  const float* bo = (const float*)d_in[8];
    const float* rpe = (const float*)d_in[9];
    const float* ln1g = (const float*)d_in[10]; const float* ln1b = (const float*)d_in[11];
    const float* ln2g = (const float*)d_in[12]; const float* ln2b = (const float*)d_in[13];
    const float* w1 = (const float*)d_in[14]; const float* b1 = (const float*)d_in[15];
    const float* w2 = (const float*)d_in[16]; const float* b2 = (const float*)d_in[17];
    const float* amask = (const float*)d_in[18];
    const int*   rel   = (const int*)d_in[19];
    float* out = (float*)d_out;

    float *qkv, *o, *x2, *h, *wqkvT, *bqkv, *woT, *w1T, *w2T;
    cudaGetSymbolAddress((void**)&qkv,   g_qkv);
    cudaGetSymbolAddress((void**)&o,     g_o);
    cudaGetSymbolAddress((void**)&x2,    g_x2);
    cudaGetSymbolAddress((void**)&h,     g_h);
    cudaGetSymbolAddress((void**)&wqkvT, g_wqkvT);
    cudaGetSymbolAddress((void**)&bqkv,  g_bqkv);
    cudaGetSymbolAddress((void**)&woT,   g_woT);
    cudaGetSymbolAddress((void**)&w1T,   g_w1T);
    cudaGetSymbolAddress((void**)&w2T,   g_w2T);

    cudaFuncSetAttribute(gemm_mma<true,  false, true >, cudaFuncAttributeMaxDynamicSharedMemorySize, GEMM_SMEM);
    cudaFuncSetAttribute(gemm_mma<false, false, false>, cudaFuncAttributeMaxDynamicSharedMemorySize, GEMM_SMEM);
    cudaFuncSetAttribute(gemm_mma<false, true,  false>, cudaFuncAttributeMaxDynamicSharedMemorySize, GEMM_SMEM);

    // weight transposes + fused qkv weights (pre-rounded to tf32)
    prep_kernel<<<2563, 256>>>(wq, wk, wv, bq, bk, bv, wo, w1, w2,
                               wqkvT, bqkv, woT, w1T, w2T);

    // fused QKV projection (gather; A=raw query -> CVTA)
    gemm_mma<true,  false, true ><<<dim3(6, 1024), 256, GEMM_SMEM>>>(query, wqkvT, bqkv, qkv, 768, 256);

    // windowed attention (output pre-rounded to tf32)
    attn_kernel<<<dim3(TOTW, NHEAD), 64>>>(qkv, rpe, amask, rel, o);

    // output projection (A=o pre-rounded)
    gemm_mma<false, false, false><<<dim3(2, 1024), 256, GEMM_SMEM>>>(o, woT, bo, h, 256, 256);

    // LN1 + residual (x2 pre-rounded)
    ln1_kernel<<<MROWS, 256>>>(h, ln1g, ln1b, query, x2);

    // MLP (mlp1 output pre-rounded in gelu epilogue)
    gemm_mma<false, true,  false><<<dim3(6, 1024), 256, GEMM_SMEM>>>(x2, w1T, b1, qkv, 768, 256);
    gemm_mma<false, false, false><<<dim3(2, 1024), 256, GEMM_SMEM>>>(qkv, w2T, b2, o, 256, 768);

    // LN2 + residual, scatter to output
    ln2_kernel<<<MROWS, 256>>>(o, ln2g, ln2b, x2, out);
}

// round 6
// speedup vs baseline: 3.0767x; 1.2492x over previous
#include <cuda_runtime.h>
#include <math.h>
#include <stdint.h>

#define BATCH 32
#define CH    256
#define EMB   256
#define NHEAD 8
#define SHFT  4
#define TT    64
#define TOTW  2048
#define MROWS 131072
#define HID   768

// ---------------- scratch ----------------
__device__ float g_qkv[(size_t)MROWS * 768];   // qkv out; later mlp1 out
__device__ float g_o  [(size_t)MROWS * 256];   // attn out; later mlp2 out
__device__ float g_x2 [(size_t)MROWS * 256];
__device__ float g_h  [(size_t)MROWS * 256];   // proj out
__device__ float g_wqkvT[768 * 256];
__device__ float g_bqkv [768];
__device__ float g_woT  [256 * 256];
__device__ float g_w1T  [768 * 256];
__device__ float g_w2T  [256 * 768];
__device__ float g_bm   [64 * 8 * 64 * 64];    // bias+mask table [win][head][t][s]

// row (window*64+token) -> pixel index in original query (folds roll by -S)
__device__ __forceinline__ int map_row(int row) {
    int w  = row >> 6;
    int t  = row & 63;
    int b  = w >> 6;
    int wi = w & 63;
    int hb = wi >> 3, wb = wi & 7;
    int i  = ((hb << 3) + (t >> 3) + SHFT) & 63;
    int j  = ((wb << 3) + (t & 7) + SHFT) & 63;
    return (b << 12) + (i << 6) + j;
}

__device__ __forceinline__ uint32_t smem_u32(const void* p) {
    uint32_t a;
    asm("{ .reg .u64 t; cvta.to.shared.u64 t, %1; cvt.u32.u64 %0, t; }" : "=r"(a) : "l"(p));
    return a;
}

__device__ __forceinline__ void cvt_tf32(uint32_t& x) {
    asm("{.reg .f32 f; mov.b32 f, %0; cvt.rn.tf32.f32 %0, f;}" : "+r"(x));
}
__device__ __forceinline__ float round_tf32(float x) {
    asm("cvt.rn.tf32.f32 %0, %0;" : "+f"(x));
    return x;
}

__device__ __forceinline__ float tanh_fast(float x) {
    float r;
    asm("tanh.approx.f32 %0, %1;" : "=f"(r) : "f"(x));
    return r;
}

// ---- packed f32x2 helpers (Blackwell FFMA2) ----
typedef unsigned long long u64t;
__device__ __forceinline__ u64t pack2(float lo, float hi) {
    u64t r; asm("mov.b64 %0, {%1, %2};" : "=l"(r) : "f"(lo), "f"(hi)); return r;
}
__device__ __forceinline__ void unpack2(u64t v, float& lo, float& hi) {
    asm("mov.b64 {%0, %1}, %2;" : "=f"(lo), "=f"(hi) : "l"(v));
}
__device__ __forceinline__ u64t fma2(u64t a, u64t b, u64t c) {
    u64t d; asm("fma.rn.f32x2 %0, %1, %2, %3;" : "=l"(d) : "l"(a), "l"(b), "l"(c)); return d;
}
__device__ __forceinline__ u64t mul2(u64t a, u64t b) {
    u64t d; asm("mul.rn.f32x2 %0, %1, %2;" : "=l"(d) : "l"(a), "l"(b)); return d;
}

#define LDMX4(r0, r1, r2, r3, addr) \
    asm volatile("ldmatrix.sync.aligned.m8n8.x4.shared.b16 {%0,%1,%2,%3}, [%4];" \
        : "=r"(r0), "=r"(r1), "=r"(r2), "=r"(r3) : "r"(addr))

#define MMA_TF32(d, a0, a1, a2, a3, b0, b1) \
    asm volatile("mma.sync.aligned.m16n8k8.row.col.f32.tf32.tf32.f32 " \
        "{%0,%1,%2,%3}, {%4,%5,%6,%7}, {%8,%9}, {%0,%1,%2,%3};" \
        : "+f"((d)[0]), "+f"((d)[1]), "+f"((d)[2]), "+f"((d)[3]) \
        : "r"(a0), "r"(a1), "r"(a2), "r"(a3), "r"(b0), "r"(b1))

#define CP_ASYNC16(dst, src) \
    asm volatile("cp.async.cg.shared.global [%0], [%1], 16;" :: "r"(dst), "l"(src))
#define CP_COMMIT()  asm volatile("cp.async.commit_group;" ::: "memory")
#define CP_WAIT1()   asm volatile("cp.async.wait_group 1;" ::: "memory")

// ---------------- tf32 mma.sync GEMM (unchanged from R5) -----------------------
#define STAGE_BYTES 32768
#define NSTAGE      3
#define GEMM_SMEM   (NSTAGE * STAGE_BYTES)

template<bool GATHER, bool GELU, bool CVTA>
__global__ __launch_bounds__(256, 2)
void gemm_mma(const float* __restrict__ A, const float* __restrict__ Bt,
              const float* __restrict__ bias, float* __restrict__ C,
              int N, int Kd)
{
    extern __shared__ float smem[];
    const uint32_t sbase = smem_u32(smem);
    const int tid  = threadIdx.x;
    const int lane = tid & 31;
    const int wid  = tid >> 5;
    const int warp_m = wid >> 2;
    const int warp_n = wid & 3;
    const int row0 = blockIdx.y * 128;
    const int col0 = blockIdx.x * 128;

    const int mrow = tid >> 3;
    const int c8   = tid & 7;
    const uint32_t swc = (uint32_t)((c8 ^ (mrow & 7)) << 4);

    const float* arow[4];
    const float* brow[4];
    uint32_t stA[4];
#pragma unroll
    for (int i = 0; i < 4; i++) {
        const int m = mrow + 32 * i;
        arow[i] = (GATHER ? (A + (size_t)map_row(row0 + m) * CH)
                          : (A + (size_t)(row0 + m) * Kd)) + c8 * 4;
        brow[i] = Bt + (size_t)(col0 + m) * Kd + c8 * 4;
        stA[i] = (uint32_t)(m * 128) + swc;
    }

    const int rA  = warp_m * 64 + (lane & 15);
    const int hiA = lane >> 4;
    const int xA  = lane & 7;
    const int rB  = warp_n * 32 + ((lane >> 4) << 3) + (lane & 7);
    const int hiB = (lane >> 3) & 1;
    const int xB  = lane & 7;

    float acc[4][4][4];
#pragma unroll
    for (int i = 0; i < 4; i++)
#pragma unroll
        for (int j = 0; j < 4; j++)
#pragma unroll
            for (int e = 0; e < 4; e++) acc[i][j][e] = 0.f;

    const int T = Kd >> 5;

#pragma unroll
    for (int s = 0; s < NSTAGE - 1; s++) {
        const int k0 = s * 32;
        const uint32_t so = sbase + s * STAGE_BYTES;
#pragma unroll
        for (int i = 0; i < 4; i++) {
            CP_ASYNC16(so + stA[i],         arow[i] + k0);
            CP_ASYNC16(so + stA[i] + 16384, brow[i] + k0);
        }
        CP_COMMIT();
    }

    for (int t = 0; t < T; ++t) {
        CP_WAIT1();
        __syncthreads();

        const int kt = t + NSTAGE - 1;
        if (kt < T) {
            const int k0 = kt * 32;
            const uint32_t so = sbase + (kt % NSTAGE) * STAGE_BYTES;
#pragma unroll
            for (int i = 0; i < 4; i++) {
                CP_ASYNC16(so + stA[i],         arow[i] + k0);
                CP_ASYNC16(so + stA[i] + 16384, brow[i] + k0);
            }
        }
        CP_COMMIT();

        const uint32_t sa = sbase + (t % NSTAGE) * STAGE_BYTES;
        const uint32_t sb = sa + 16384;
#pragma unroll
        for (int kc = 0; kc < 4; kc++) {
            uint32_t af[4][4];
#pragma unroll
            for (int mt = 0; mt < 4; mt++) {
                const uint32_t addr = sa + (uint32_t)((rA + mt * 16) * 128)
                                    + (uint32_t)((((kc << 1) + hiA) ^ xA) << 4);
                LDMX4(af[mt][0], af[mt][1], af[mt][2], af[mt][3], addr);
                if (CVTA) {
                    cvt_tf32(af[mt][0]); cvt_tf32(af[mt][1]);
                    cvt_tf32(af[mt][2]); cvt_tf32(af[mt][3]);
                }
            }
            uint32_t bf[4][2];
#pragma unroll
            for (int p = 0; p < 2; p++) {
                const uint32_t addr = sb + (uint32_t)((rB + p * 16) * 128)
                                    + (uint32_t)((((kc << 1) + hiB) ^ xB) << 4);
                LDMX4(bf[2*p][0], bf[2*p][1], bf[2*p+1][0], bf[2*p+1][1], addr);
            }
#pragma unroll
            for (int mt = 0; mt < 4; mt++)
#pragma unroll
                for (int nt = 0; nt < 4; nt++)
                    MMA_TF32(acc[mt][nt], af[mt][0], af[mt][1], af[mt][2], af[mt][3],
                             bf[nt][0], bf[nt][1]);
        }
    }

    const int rbase = row0 + warp_m * 64 + (lane >> 2);
    const int cb0   = col0 + warp_n * 32 + 2 * (lane & 3);
#pragma unroll
    for (int nt = 0; nt < 4; nt++) {
        const int cc = cb0 + nt * 8;
        const float bv0 = bias[cc], bv1 = bias[cc + 1];
#pragma unroll
        for (int mt = 0; mt < 4; mt++) {
            const int r = rbase + mt * 16;
            float v[4];
#pragma unroll
            for (int e = 0; e < 4; e++) {
                float x = acc[mt][nt][e] + ((e & 1) ? bv1 : bv0);
                if (GELU) {
                    float x3 = x * x * x;
                    x = 0.5f * x * (1.f + tanh_fast(0.7978845608028654f * (x + 0.044715f * x3)));
                    x = round_tf32(x);
                }
                v[e] = x;
            }
            *(float2*)(C + (size_t)r * N + cc)       = make_float2(v[0], v[1]);
            *(float2*)(C + (size_t)(r + 8) * N + cc) = make_float2(v[2], v[3]);
        }
    }
}

// ---------------- attention v3: f32x2 FMA, LDS.128, fused bias table -----------
__global__ __launch_bounds__(64)
void attn_kernel(const float* __restrict__ qkv, const float* __restrict__ bm,
                 float* __restrict__ o)
{
    const int w = blockIdx.x, head = blockIdx.y, t = threadIdx.x;
    __shared__ __align__(16) float ks[64][32];
    __shared__ __align__(16) float vs[64][32];

    const size_t rbase = (size_t)(w * 64 + t) * 768 + head * 32;
    const float4* kr = (const float4*)(qkv + rbase + 256);
    const float4* vr = (const float4*)(qkv + rbase + 512);
#pragma unroll
    for (int i = 0; i < 8; i++) {
        ((float4*)ks[t])[i] = kr[i];
        ((float4*)vs[t])[i] = vr[i];
    }
    // q packed into f32x2 pairs, pre-scaled
    u64t qr2[16];
    {
        const float4* q4 = (const float4*)(qkv + rbase);
#pragma unroll
        for (int i = 0; i < 8; i++) {
            float4 qv = q4[i];
            const float s = 0.17677669529663687f;
            qr2[2*i]   = pack2(qv.x * s, qv.y * s);
            qr2[2*i+1] = pack2(qv.z * s, qv.w * s);
        }
    }
    __syncthreads();

    // fused bias+mask row for this (window, head, t): 64 contiguous floats
    const float4* brow = (const float4*)(bm + ((size_t)((w & 63) * 8 + head) * 4096) + t * 64);

    float mx = -1e30f, sum = 0.f;
    u64t ov2[16];
#pragma unroll
    for (int j = 0; j < 16; j++) ov2[j] = 0ull;

#pragma unroll
    for (int c = 0; c < 4; c++) {
        float lg[16];
        float cmx = -1e30f;
#pragma unroll
        for (int i = 0; i < 16; i++) {
            const int s = c * 16 + i;
            const float4* k4 = (const float4*)ks[s];
            u64t acc2 = 0ull;
#pragma unroll
            for (int j = 0; j < 8; j++) {
                float4 kv = k4[j];
                acc2 = fma2(qr2[2*j],   pack2(kv.x, kv.y), acc2);
                acc2 = fma2(qr2[2*j+1], pack2(kv.z, kv.w), acc2);
            }
            float lo, hi; unpack2(acc2, lo, hi);
            lg[i] = lo + hi;
        }
        // add bias+mask (vectorized)
#pragma unroll
        for (int i4 = 0; i4 < 4; i4++) {
            float4 bb = brow[c * 4 + i4];
            lg[i4*4+0] += bb.x; lg[i4*4+1] += bb.y;
            lg[i4*4+2] += bb.z; lg[i4*4+3] += bb.w;
        }
#pragma unroll
        for (int i = 0; i < 16; i++) cmx = fmaxf(cmx, lg[i]);

        const float nmx = fmaxf(mx, cmx);
        const float scl = __expf(mx - nmx);
        sum *= scl;
        const u64t scl2 = pack2(scl, scl);
#pragma unroll
        for (int j = 0; j < 16; j++) ov2[j] = mul2(ov2[j], scl2);
#pragma unroll
        for (int i = 0; i < 16; i++) {
            float e = __expf(lg[i] - nmx);
            lg[i] = e;
            sum += e;
        }
#pragma unroll
        for (int i = 0; i < 16; i++) {
            const int s = c * 16 + i;
            const u64t p2 = pack2(lg[i], lg[i]);
            const float4* v4 = (const float4*)vs[s];
#pragma unroll
            for (int j = 0; j < 8; j++) {
                float4 vv = v4[j];
                ov2[2*j]   = fma2(p2, pack2(vv.x, vv.y), ov2[2*j]);
                ov2[2*j+1] = fma2(p2, pack2(vv.z, vv.w), ov2[2*j+1]);
            }
        }
        mx = nmx;
    }
    const float inv = 1.f / sum;
    float* op = o + (size_t)(w * 64 + t) * 256 + head * 32;
#pragma unroll
    for (int j = 0; j < 8; j++) {
        float a, b, c2, d;
        unpack2(ov2[2*j], a, b);
        unpack2(ov2[2*j+1], c2, d);
        *(float4*)(op + 4*j) = make_float4(round_tf32(a * inv), round_tf32(b * inv),
                                           round_tf32(c2 * inv), round_tf32(d * inv));
    }
}

// ---------------- LayerNorm (+residual) ----------------------------------------
__device__ __forceinline__ void block_stats(float val, float& mean, float& var) {
    float s = val, s2 = val * val;
#pragma unroll
    for (int off = 16; off; off >>= 1) {
        s  += __shfl_xor_sync(0xffffffffu, s,  off);
        s2 += __shfl_xor_sync(0xffffffffu, s2, off);
    }
    __shared__ float sh[8], sh2[8];
    int lane = threadIdx.x & 31, warp = threadIdx.x >> 5;
    if (lane == 0) { sh[warp] = s; sh2[warp] = s2; }
    __syncthreads();
    float sum = 0.f, sq = 0.f;
#pragma unroll
    for (int i = 0; i < 8; i++) { sum += sh[i]; sq += sh2[i]; }
    mean = sum * (1.f / 256.f);
    var  = sq * (1.f / 256.f) - mean * mean;
}

__global__ __launch_bounds__(256)
void ln1_kernel(const float* __restrict__ X, const float* __restrict__ g,
                const float* __restrict__ b, const float* __restrict__ query,
                float* __restrict__ out)
{
    const int row = blockIdx.x, c = threadIdx.x;
    const float val = X[(size_t)row * CH + c];
    float mean, var;
    block_stats(val, mean, var);
    const float y = (val - mean) * rsqrtf(var + 1e-5f) * g[c] + b[c];
    out[(size_t)row * CH + c] = round_tf32(y + query[(size_t)map_row(row) * CH + c]);
}

__global__ __launch_bounds__(256)
void ln2_kernel(const float* __restrict__ X, const float* __restrict__ g,
                const float* __restrict__ b, const float* __restrict__ x2,
                float* __restrict__ out)
{
    const int row = blockIdx.x, c = threadIdx.x;
    const float val = X[(size_t)row * CH + c];
    float mean, var;
    block_stats(val, mean, var);
    const float y = (val - mean) * rsqrtf(var + 1e-5f) * g[c] + b[c];
    out[(size_t)map_row(row) * CH + c] = y + x2[(size_t)row * CH + c];
}

// ---------------- weight prep: transpose to [N,K], pre-round to tf32 -----------
__global__ __launch_bounds__(256)
void prep_kernel(const float* __restrict__ wq, const float* __restrict__ wk,
                 const float* __restrict__ wv, const float* __restrict__ bq,
                 const float* __restrict__ bk, const float* __restrict__ bv,
                 const float* __restrict__ wo, const float* __restrict__ w1,
                 const float* __restrict__ w2,
                 float* __restrict__ wqkvT, float* __restrict__ bqkv,
                 float* __restrict__ woT, float* __restrict__ w1T,
                 float* __restrict__ w2T)
{
    int i = blockIdx.x * 256 + threadIdx.x;
    if (i < 196608) {
        int n = i >> 8, k = i & 255;
        float v = (n < 256) ? wq[k * 256 + n]
                : (n < 512) ? wk[k * 256 + (n - 256)]
                            : wv[k * 256 + (n - 512)];
        wqkvT[i] = round_tf32(v);
    } else if (i < 262144) {
        int j = i - 196608; int n = j >> 8, k = j & 255;
        woT[j] = round_tf32(wo[k * 256 + n]);
    } else if (i < 458752) {
        int j = i - 262144; int n = j >> 8, k = j & 255;
        w1T[j] = round_tf32(w1[k * 768 + n]);
    } else if (i < 655360) {
        int j = i - 458752; int n = j / 768, k = j - n * 768;
        w2T[j] = round_tf32(w2[k * 256 + n]);
    } else if (i < 656128) {
        int n = i - 655360;
        bqkv[n] = (n < 256) ? bq[n] : (n < 512) ? bk[n - 256] : bv[n - 512];
    }
}

// ---------------- bias+mask table: bm[wi][h][t][s] = rpe[rel[t][s]][h] + mask[wi][t][s]
__global__ __launch_bounds__(256)
void prep_bm_kernel(const float* __restrict__ rpe, const float* __restrict__ mask,
                    const int* __restrict__ rel, float* __restrict__ bm)
{
    int idx = blockIdx.x * 256 + threadIdx.x;      // 0 .. 2M-1
    int wi  = idx >> 15;                           // /(8*4096)
    int rem = idx & 32767;
    int h   = rem >> 12;
    int ts  = rem & 4095;
    bm[idx] = rpe[rel[ts] * NHEAD + h] + mask[wi * 4096 + ts];
}

// ---------------- launch --------------------------------------------------------
extern "C" void kernel_launch(void* const* d_in, const int* in_sizes, int n_in,
                              void* d_out, int out_size)
{
    const float* query = (const float*)d_in[0];
    const float* wq = (const float*)d_in[1];  const float* bq = (const float*)d_in[2];
    const float* wk = (const float*)d_in[3];  const float* bk = (const float*)d_in[4];
    const float* wv = (const float*)d_in[5];  const float* bv = (const float*)d_in[6];
    const float* wo = (const float*)d_in[7];  const float* bo = (const float*)d_in[8];
    const float* rpe = (const float*)d_in[9];
    const float* ln1g = (const float*)d_in[10]; const float* ln1b = (const float*)d_in[11];
    const float* ln2g = (const float*)d_in[12]; const float* ln2b = (const float*)d_in[13];
    const float* w1 = (const float*)d_in[14]; const float* b1 = (const float*)d_in[15];
    const float* w2 = (const float*)d_in[16]; const float* b2 = (const float*)d_in[17];
    const float* amask = (const float*)d_in[18];
    const int*   rel   = (const int*)d_in[19];
    float* out = (float*)d_out;

    float *qkv, *o, *x2, *h, *wqkvT, *bqkv, *woT, *w1T, *w2T, *bm;
    cudaGetSymbolAddress((void**)&qkv,   g_qkv);
    cudaGetSymbolAddress((void**)&o,     g_o);
    cudaGetSymbolAddress((void**)&x2,    g_x2);
    cudaGetSymbolAddress((void**)&h,     g_h);
    cudaGetSymbolAddress((void**)&wqkvT, g_wqkvT);
    cudaGetSymbolAddress((void**)&bqkv,  g_bqkv);
    cudaGetSymbolAddress((void**)&woT,   g_woT);
    cudaGetSymbolAddress((void**)&w1T,   g_w1T);
    cudaGetSymbolAddress((void**)&w2T,   g_w2T);
    cudaGetSymbolAddress((void**)&bm,    g_bm);

    cudaFuncSetAttribute(gemm_mma<true,  false, true >, cudaFuncAttributeMaxDynamicSharedMemorySize, GEMM_SMEM);
    cudaFuncSetAttribute(gemm_mma<false, false, false>, cudaFuncAttributeMaxDynamicSharedMemorySize, GEMM_SMEM);
    cudaFuncSetAttribute(gemm_mma<false, true,  false>, cudaFuncAttributeMaxDynamicSharedMemorySize, GEMM_SMEM);

    // prep: weight transposes (tf32-rounded) + fused bias/mask table
    prep_kernel<<<2563, 256>>>(wq, wk, wv, bq, bk, bv, wo, w1, w2,
                               wqkvT, bqkv, woT, w1T, w2T);
    prep_bm_kernel<<<8192, 256>>>(rpe, amask, rel, bm);

    // fused QKV projection (gather; A=raw query -> CVTA)
    gemm_mma<true,  false, true ><<<dim3(6, 1024), 256, GEMM_SMEM>>>(query, wqkvT, bqkv, qkv, 768, 256);

    // windowed attention (f32x2, bias table)
    attn_kernel<<<dim3(TOTW, NHEAD), 64>>>(qkv, bm, o);

    // output projection
    gemm_mma<false, false, false><<<dim3(2, 1024), 256, GEMM_SMEM>>>(o, woT, bo, h, 256, 256);

    // LN1 + residual
    ln1_kernel<<<MROWS, 256>>>(h, ln1g, ln1b, query, x2);

    // MLP
    gemm_mma<false, true,  false><<<dim3(6, 1024), 256, GEMM_SMEM>>>(x2, w1T, b1, qkv, 768, 256);
    gemm_mma<false, false, false><<<dim3(2, 1024), 256, GEMM_SMEM>>>(qkv, w2T, b2, o, 256, 768);

    // LN2 + residual, scatter to output
    ln2_kernel<<<MROWS, 256>>>(o, ln2g, ln2b, x2, out);
}

// round 7
// speedup vs baseline: 3.6469x; 1.1853x over previous
#include <cuda_runtime.h>
#include <math.h>
#include <stdint.h>

#define BATCH 32
#define CH    256
#define EMB   256
#define NHEAD 8
#define SHFT  4
#define TT    64
#define TOTW  2048
#define MROWS 131072
#define HID   768

// ---------------- scratch ----------------
__device__ float g_qkv[(size_t)MROWS * 768];   // qkv out; later mlp1 out
__device__ float g_o  [(size_t)MROWS * 256];   // attn out; later mlp2 out
__device__ float g_x2 [(size_t)MROWS * 256];
__device__ float g_h  [(size_t)MROWS * 256];   // proj out
__device__ float g_wqkvT[768 * 256];
__device__ float g_bqkv [768];
__device__ float g_woT  [256 * 256];
__device__ float g_w1T  [768 * 256];
__device__ float g_w2T  [256 * 768];
__device__ float g_bm   [64 * 8 * 64 * 64];    // bias+mask table [win][head][t][s]

// row (window*64+token) -> pixel index in original query (folds roll by -S)
__device__ __forceinline__ int map_row(int row) {
    int w  = row >> 6;
    int t  = row & 63;
    int b  = w >> 6;
    int wi = w & 63;
    int hb = wi >> 3, wb = wi & 7;
    int i  = ((hb << 3) + (t >> 3) + SHFT) & 63;
    int j  = ((wb << 3) + (t & 7) + SHFT) & 63;
    return (b << 12) + (i << 6) + j;
}

__device__ __forceinline__ uint32_t smem_u32(const void* p) {
    uint32_t a;
    asm("{ .reg .u64 t; cvta.to.shared.u64 t, %1; cvt.u32.u64 %0, t; }" : "=r"(a) : "l"(p));
    return a;
}

__device__ __forceinline__ void cvt_tf32(uint32_t& x) {
    asm("{.reg .f32 f; mov.b32 f, %0; cvt.rn.tf32.f32 %0, f;}" : "+r"(x));
}
__device__ __forceinline__ float round_tf32(float x) {
    asm("cvt.rn.tf32.f32 %0, %0;" : "+f"(x));
    return x;
}

__device__ __forceinline__ float tanh_fast(float x) {
    float r;
    asm("tanh.approx.f32 %0, %1;" : "=f"(r) : "f"(x));
    return r;
}

#define LDMX4(r0, r1, r2, r3, addr) \
    asm volatile("ldmatrix.sync.aligned.m8n8.x4.shared.b16 {%0,%1,%2,%3}, [%4];" \
        : "=r"(r0), "=r"(r1), "=r"(r2), "=r"(r3) : "r"(addr))

#define MMA_TF32(d, a0, a1, a2, a3, b0, b1) \
    asm volatile("mma.sync.aligned.m16n8k8.row.col.f32.tf32.tf32.f32 " \
        "{%0,%1,%2,%3}, {%4,%5,%6,%7}, {%8,%9}, {%0,%1,%2,%3};" \
        : "+f"((d)[0]), "+f"((d)[1]), "+f"((d)[2]), "+f"((d)[3]) \
        : "r"(a0), "r"(a1), "r"(a2), "r"(a3), "r"(b0), "r"(b1))

#define CP_ASYNC16(dst, src) \
    asm volatile("cp.async.cg.shared.global [%0], [%1], 16;" :: "r"(dst), "l"(src))
#define CP_COMMIT()  asm volatile("cp.async.commit_group;" ::: "memory")
#define CP_WAIT1()   asm volatile("cp.async.wait_group 1;" ::: "memory")

// ---------------- tf32 mma.sync GEMM (frozen since R5) -------------------------
#define STAGE_BYTES 32768
#define NSTAGE      3
#define GEMM_SMEM   (NSTAGE * STAGE_BYTES)

template<bool GATHER, bool GELU, bool CVTA>
__global__ __launch_bounds__(256, 2)
void gemm_mma(const float* __restrict__ A, const float* __restrict__ Bt,
              const float* __restrict__ bias, float* __restrict__ C,
              int N, int Kd)
{
    extern __shared__ float smem[];
    const uint32_t sbase = smem_u32(smem);
    const int tid  = threadIdx.x;
    const int lane = tid & 31;
    const int wid  = tid >> 5;
    const int warp_m = wid >> 2;
    const int warp_n = wid & 3;
    const int row0 = blockIdx.y * 128;
    const int col0 = blockIdx.x * 128;

    const int mrow = tid >> 3;
    const int c8   = tid & 7;
    const uint32_t swc = (uint32_t)((c8 ^ (mrow & 7)) << 4);

    const float* arow[4];
    const float* brow[4];
    uint32_t stA[4];
#pragma unroll
    for (int i = 0; i < 4; i++) {
        const int m = mrow + 32 * i;
        arow[i] = (GATHER ? (A + (size_t)map_row(row0 + m) * CH)
                          : (A + (size_t)(row0 + m) * Kd)) + c8 * 4;
        brow[i] = Bt + (size_t)(col0 + m) * Kd + c8 * 4;
        stA[i] = (uint32_t)(m * 128) + swc;
    }

    const int rA  = warp_m * 64 + (lane & 15);
    const int hiA = lane >> 4;
    const int xA  = lane & 7;
    const int rB  = warp_n * 32 + ((lane >> 4) << 3) + (lane & 7);
    const int hiB = (lane >> 3) & 1;
    const int xB  = lane & 7;

    float acc[4][4][4];
#pragma unroll
    for (int i = 0; i < 4; i++)
#pragma unroll
        for (int j = 0; j < 4; j++)
#pragma unroll
            for (int e = 0; e < 4; e++) acc[i][j][e] = 0.f;

    const int T = Kd >> 5;

#pragma unroll
    for (int s = 0; s < NSTAGE - 1; s++) {
        const int k0 = s * 32;
        const uint32_t so = sbase + s * STAGE_BYTES;
#pragma unroll
        for (int i = 0; i < 4; i++) {
            CP_ASYNC16(so + stA[i],         arow[i] + k0);
            CP_ASYNC16(so + stA[i] + 16384, brow[i] + k0);
        }
        CP_COMMIT();
    }

    for (int t = 0; t < T; ++t) {
        CP_WAIT1();
        __syncthreads();

        const int kt = t + NSTAGE - 1;
        if (kt < T) {
            const int k0 = kt * 32;
            const uint32_t so = sbase + (kt % NSTAGE) * STAGE_BYTES;
#pragma unroll
            for (int i = 0; i < 4; i++) {
                CP_ASYNC16(so + stA[i],         arow[i] + k0);
                CP_ASYNC16(so + stA[i] + 16384, brow[i] + k0);
            }
        }
        CP_COMMIT();

        const uint32_t sa = sbase + (t % NSTAGE) * STAGE_BYTES;
        const uint32_t sb = sa + 16384;
#pragma unroll
        for (int kc = 0; kc < 4; kc++) {
            uint32_t af[4][4];
#pragma unroll
            for (int mt = 0; mt < 4; mt++) {
                const uint32_t addr = sa + (uint32_t)((rA + mt * 16) * 128)
                                    + (uint32_t)((((kc << 1) + hiA) ^ xA) << 4);
                LDMX4(af[mt][0], af[mt][1], af[mt][2], af[mt][3], addr);
                if (CVTA) {
                    cvt_tf32(af[mt][0]); cvt_tf32(af[mt][1]);
                    cvt_tf32(af[mt][2]); cvt_tf32(af[mt][3]);
                }
            }
            uint32_t bf[4][2];
#pragma unroll
            for (int p = 0; p < 2; p++) {
                const uint32_t addr = sb + (uint32_t)((rB + p * 16) * 128)
                                    + (uint32_t)((((kc << 1) + hiB) ^ xB) << 4);
                LDMX4(bf[2*p][0], bf[2*p][1], bf[2*p+1][0], bf[2*p+1][1], addr);
            }
#pragma unroll
            for (int mt = 0; mt < 4; mt++)
#pragma unroll
                for (int nt = 0; nt < 4; nt++)
                    MMA_TF32(acc[mt][nt], af[mt][0], af[mt][1], af[mt][2], af[mt][3],
                             bf[nt][0], bf[nt][1]);
        }
    }

    const int rbase = row0 + warp_m * 64 + (lane >> 2);
    const int cb0   = col0 + warp_n * 32 + 2 * (lane & 3);
#pragma unroll
    for (int nt = 0; nt < 4; nt++) {
        const int cc = cb0 + nt * 8;
        const float bv0 = bias[cc], bv1 = bias[cc + 1];
#pragma unroll
        for (int mt = 0; mt < 4; mt++) {
            const int r = rbase + mt * 16;
            float v[4];
#pragma unroll
            for (int e = 0; e < 4; e++) {
                float x = acc[mt][nt][e] + ((e & 1) ? bv1 : bv0);
                if (GELU) {
                    float x3 = x * x * x;
                    x = 0.5f * x * (1.f + tanh_fast(0.7978845608028654f * (x + 0.044715f * x3)));
                    x = round_tf32(x);
                }
                v[e] = x;
            }
            *(float2*)(C + (size_t)r * N + cc)       = make_float2(v[0], v[1]);
            *(float2*)(C + (size_t)(r + 8) * N + cc) = make_float2(v[2], v[3]);
        }
    }
}

// ---------------- attention v4: tensor-core (mma.sync tf32) --------------------
// one CTA per (window, head); 4 warps, each owns 16 query rows.
// smem strides: 36 / 68 floats (== 4 mod 32 banks -> conflict-free ldmatrix).
#define SQ_STRIDE 36
#define SP_STRIDE 68

__global__ __launch_bounds__(128)
void attn_kernel(const float* __restrict__ qkv, const float* __restrict__ bm,
                 float* __restrict__ o)
{
    const int w = blockIdx.x, head = blockIdx.y;
    const int tid = threadIdx.x;
    const int lane = tid & 31;
    const int wid  = tid >> 5;         // 0..3

    __shared__ __align__(16) float sQ[64 * SQ_STRIDE];
    __shared__ __align__(16) float sK[64 * SQ_STRIDE];
    __shared__ __align__(16) float sVt[32 * SP_STRIDE];   // transposed V: [d][s]
    __shared__ __align__(16) float sP[64 * SP_STRIDE];

    // ---- load Q,K (row-major) and V (transposed), rounding to tf32
    {
        const int row  = tid >> 1;              // 0..63
        const int half = (tid & 1) * 16;        // col base 0 or 16
        const float* base = qkv + (size_t)(w * 64 + row) * 768 + head * 32 + half;
        const float qscale = 0.17677669529663687f;
#pragma unroll
        for (int c = 0; c < 16; c += 4) {
            float4 qv = *(const float4*)(base + c);
            float4 kv = *(const float4*)(base + 256 + c);
            float4 vv = *(const float4*)(base + 512 + c);
            qv.x = round_tf32(qv.x * qscale); qv.y = round_tf32(qv.y * qscale);
            qv.z = round_tf32(qv.z * qscale); qv.w = round_tf32(qv.w * qscale);
            kv.x = round_tf32(kv.x); kv.y = round_tf32(kv.y);
            kv.z = round_tf32(kv.z); kv.w = round_tf32(kv.w);
            *(float4*)(sQ + row * SQ_STRIDE + half + c) = qv;
            *(float4*)(sK + row * SQ_STRIDE + half + c) = kv;
            const int d = half + c;
            sVt[(d + 0) * SP_STRIDE + row] = round_tf32(vv.x);
            sVt[(d + 1) * SP_STRIDE + row] = round_tf32(vv.y);
            sVt[(d + 2) * SP_STRIDE + row] = round_tf32(vv.z);
            sVt[(d + 3) * SP_STRIDE + row] = round_tf32(vv.w);
        }
    }
    __syncthreads();

    const uint32_t sQb  = smem_u32(sQ);
    const uint32_t sKb  = smem_u32(sK);
    const uint32_t sVtb = smem_u32(sVt);
    const uint32_t sPb  = smem_u32(sP);

    // ldmatrix lane components (same mapping as the verified GEMM)
    const int rA  = (lane & 15);         // A-tile row within 16
    const int hiA = lane >> 4;           // +4 col chunk
    const int rBl = ((lane >> 4) << 3) + (lane & 7);  // B rows within 16-row pair
    const int hiB = (lane >> 3) & 1;

    // ---- QK^T: logits[16 x 64] per warp -> acc[8 ntiles][4]
    float acc[8][4];
#pragma unroll
    for (int nt = 0; nt < 8; nt++)
#pragma unroll
        for (int e = 0; e < 4; e++) acc[nt][e] = 0.f;

#pragma unroll
    for (int kc = 0; kc < 4; kc++) {
        uint32_t a0, a1, a2, a3;
        {
            const uint32_t addr = sQb + (uint32_t)(((wid * 16 + rA) * SQ_STRIDE
                                   + kc * 8 + hiA * 4) * 4);
            LDMX4(a0, a1, a2, a3, addr);
        }
#pragma unroll
        for (int p = 0; p < 4; p++) {
            uint32_t b00, b01, b10, b11;
            const uint32_t addr = sKb + (uint32_t)(((p * 16 + rBl) * SQ_STRIDE
                                   + kc * 8 + hiB * 4) * 4);
            LDMX4(b00, b01, b10, b11, addr);
            MMA_TF32(acc[2*p],   a0, a1, a2, a3, b00, b01);
            MMA_TF32(acc[2*p+1], a0, a1, a2, a3, b10, b11);
        }
    }

    // ---- bias+mask, softmax on fragments
    const float* bmr = bm + (size_t)((w & 63) * 8 + head) * 4096;
    const int r0 = wid * 16 + (lane >> 2);   // fragment row (and r0+8)
    const int cb = 2 * (lane & 3);
#pragma unroll
    for (int nt = 0; nt < 8; nt++) {
        const float2 blo = *(const float2*)(bmr + r0 * 64 + 8 * nt + cb);
        const float2 bhi = *(const float2*)(bmr + (r0 + 8) * 64 + 8 * nt + cb);
        acc[nt][0] += blo.x; acc[nt][1] += blo.y;
        acc[nt][2] += bhi.x; acc[nt][3] += bhi.y;
    }
    float m0 = -1e30f, m1 = -1e30f;
#pragma unroll
    for (int nt = 0; nt < 8; nt++) {
        m0 = fmaxf(m0, fmaxf(acc[nt][0], acc[nt][1]));
        m1 = fmaxf(m1, fmaxf(acc[nt][2], acc[nt][3]));
    }
    m0 = fmaxf(m0, __shfl_xor_sync(0xffffffffu, m0, 1));
    m0 = fmaxf(m0, __shfl_xor_sync(0xffffffffu, m0, 2));
    m1 = fmaxf(m1, __shfl_xor_sync(0xffffffffu, m1, 1));
    m1 = fmaxf(m1, __shfl_xor_sync(0xffffffffu, m1, 2));

    float s0 = 0.f, s1 = 0.f;
#pragma unroll
    for (int nt = 0; nt < 8; nt++) {
        acc[nt][0] = __expf(acc[nt][0] - m0); s0 += acc[nt][0];
        acc[nt][1] = __expf(acc[nt][1] - m0); s0 += acc[nt][1];
        acc[nt][2] = __expf(acc[nt][2] - m1); s1 += acc[nt][2];
        acc[nt][3] = __expf(acc[nt][3] - m1); s1 += acc[nt][3];
    }
    s0 += __shfl_xor_sync(0xffffffffu, s0, 1);
    s0 += __shfl_xor_sync(0xffffffffu, s0, 2);
    s1 += __shfl_xor_sync(0xffffffffu, s1, 1);
    s1 += __shfl_xor_sync(0xffffffffu, s1, 2);
    const float inv0 = 1.f / s0, inv1 = 1.f / s1;

    // ---- P -> smem (tf32-rounded); warp-private rows
#pragma unroll
    for (int nt = 0; nt < 8; nt++) {
        float2 plo = make_float2(round_tf32(acc[nt][0] * inv0), round_tf32(acc[nt][1] * inv0));
        float2 phi = make_float2(round_tf32(acc[nt][2] * inv1), round_tf32(acc[nt][3] * inv1));
        *(float2*)(sP + r0 * SP_STRIDE + 8 * nt + cb)       = plo;
        *(float2*)(sP + (r0 + 8) * SP_STRIDE + 8 * nt + cb) = phi;
    }
    __syncwarp();

    // ---- P @ V: O[16 x 32] per warp
    float oacc[4][4];
#pragma unroll
    for (int nt = 0; nt < 4; nt++)
#pragma unroll
        for (int e = 0; e < 4; e++) oacc[nt][e] = 0.f;

#pragma unroll
    for (int kc = 0; kc < 8; kc++) {
        uint32_t a0, a1, a2, a3;
        {
            const uint32_t addr = sPb + (uint32_t)(((wid * 16 + rA) * SP_STRIDE
                                   + kc * 8 + hiA * 4) * 4);
            LDMX4(a0, a1, a2, a3, addr);
        }
#pragma unroll
        for (int p = 0; p < 2; p++) {
            uint32_t b00, b01, b10, b11;
            const uint32_t addr = sVtb + (uint32_t)(((p * 16 + rBl) * SP_STRIDE
                                   + kc * 8 + hiB * 4) * 4);
            LDMX4(b00, b01, b10, b11, addr);
            MMA_TF32(oacc[2*p],   a0, a1, a2, a3, b00, b01);
            MMA_TF32(oacc[2*p+1], a0, a1, a2, a3, b10, b11);
        }
    }

    // ---- write O (rounded: feeds proj GEMM with CVTA=false)
    float* obase = o + (size_t)(w * 64 + r0) * 256 + head * 32;
#pragma unroll
    for (int nt = 0; nt < 4; nt++) {
        *(float2*)(obase + 8 * nt + cb) =
            make_float2(round_tf32(oacc[nt][0]), round_tf32(oacc[nt][1]));
        *(float2*)(obase + 8 * 256 + 8 * nt + cb) =
            make_float2(round_tf32(oacc[nt][2]), round_tf32(oacc[nt][3]));
    }
}

// ---------------- LayerNorm (+residual) ----------------------------------------
__device__ __forceinline__ void block_stats(float val, float& mean, float& var) {
    float s = val, s2 = val * val;
#pragma unroll
    for (int off = 16; off; off >>= 1) {
        s  += __shfl_xor_sync(0xffffffffu, s,  off);
        s2 += __shfl_xor_sync(0xffffffffu, s2, off);
    }
    __shared__ float sh[8], sh2[8];
    int lane = threadIdx.x & 31, warp = threadIdx.x >> 5;
    if (lane == 0) { sh[warp] = s; sh2[warp] = s2; }
    __syncthreads();
    float sum = 0.f, sq = 0.f;
#pragma unroll
    for (int i = 0; i < 8; i++) { sum += sh[i]; sq += sh2[i]; }
    mean = sum * (1.f / 256.f);
    var  = sq * (1.f / 256.f) - mean * mean;
}

__global__ __launch_bounds__(256)
void ln1_kernel(const float* __restrict__ X, const float* __restrict__ g,
                const float* __restrict__ b, const float* __restrict__ query,
                float* __restrict__ out)
{
    const int row = blockIdx.x, c = threadIdx.x;
    const float val = X[(size_t)row * CH + c];
    float mean, var;
    block_stats(val, mean, var);
    const float y = (val - mean) * rsqrtf(var + 1e-5f) * g[c] + b[c];
    out[(size_t)row * CH + c] = round_tf32(y + query[(size_t)map_row(row) * CH + c]);
}

__global__ __launch_bounds__(256)
void ln2_kernel(const float* __restrict__ X, const float* __restrict__ g,
                const float* __restrict__ b, const float* __restrict__ x2,
                float* __restrict__ out)
{
    const int row = blockIdx.x, c = threadIdx.x;
    const float val = X[(size_t)row * CH + c];
    float mean, var;
    block_stats(val, mean, var);
    const float y = (val - mean) * rsqrtf(var + 1e-5f) * g[c] + b[c];
    out[(size_t)map_row(row) * CH + c] = y + x2[(size_t)row * CH + c];
}

// ---------------- weight prep: transpose to [N,K], pre-round to tf32 -----------
__global__ __launch_bounds__(256)
void prep_kernel(const float* __restrict__ wq, const float* __restrict__ wk,
                 const float* __restrict__ wv, const float* __restrict__ bq,
                 const float* __restrict__ bk, const float* __restrict__ bv,
                 const float* __restrict__ wo, const float* __restrict__ w1,
                 const float* __restrict__ w2,
                 float* __restrict__ wqkvT, float* __restrict__ bqkv,
                 float* __restrict__ woT, float* __restrict__ w1T,
                 float* __restrict__ w2T)
{
    int i = blockIdx.x * 256 + threadIdx.x;
    if (i < 196608) {
        int n = i >> 8, k = i & 255;
        float v = (n < 256) ? wq[k * 256 + n]
                : (n < 512) ? wk[k * 256 + (n - 256)]
                            : wv[k * 256 + (n - 512)];
        wqkvT[i] = round_tf32(v);
    } else if (i < 262144) {
        int j = i - 196608; int n = j >> 8, k = j & 255;
        woT[j] = round_tf32(wo[k * 256 + n]);
    } else if (i < 458752) {
        int j = i - 262144; int n = j >> 8, k = j & 255;
        w1T[j] = round_tf32(w1[k * 768 + n]);
    } else if (i < 655360) {
        int j = i - 458752; int n = j / 768, k = j - n * 768;
        w2T[j] = round_tf32(w2[k * 256 + n]);
    } else if (i < 656128) {
        int n = i - 655360;
        bqkv[n] = (n < 256) ? bq[n] : (n < 512) ? bk[n - 256] : bv[n - 512];
    }
}

// ---------------- bias+mask table ----------------------------------------------
__global__ __launch_bounds__(256)
void prep_bm_kernel(const float* __restrict__ rpe, const float* __restrict__ mask,
                    const int* __restrict__ rel, float* __restrict__ bm)
{
    int idx = blockIdx.x * 256 + threadIdx.x;
    int wi  = idx >> 15;
    int rem = idx & 32767;
    int h   = rem >> 12;
    int ts  = rem & 4095;
    bm[idx] = rpe[rel[ts] * NHEAD + h] + mask[wi * 4096 + ts];
}

// ---------------- launch --------------------------------------------------------
extern "C" void kernel_launch(void* const* d_in, const int* in_sizes, int n_in,
                              void* d_out, int out_size)
{
    const float* query = (const float*)d_in[0];
    const float* wq = (const float*)d_in[1];  const float* bq = (const float*)d_in[2];
    const float* wk = (const float*)d_in[3];  const float* bk = (const float*)d_in[4];
    const float* wv = (const float*)d_in[5];  const float* bv = (const float*)d_in[6];
    const float* wo = (const float*)d_in[7];  const float* bo = (const float*)d_in[8];
    const float* rpe = (const float*)d_in[9];
    const float* ln1g = (const float*)d_in[10]; const float* ln1b = (const float*)d_in[11];
    const float* ln2g = (const float*)d_in[12]; const float* ln2b = (const float*)d_in[13];
    const float* w1 = (const float*)d_in[14]; const float* b1 = (const float*)d_in[15];
    const float* w2 = (const float*)d_in[16]; const float* b2 = (const float*)d_in[17];
    const float* amask = (const float*)d_in[18];
    const int*   rel   = (const int*)d_in[19];
    float* out = (float*)d_out;

    float *qkv, *o, *x2, *h, *wqkvT, *bqkv, *woT, *w1T, *w2T, *bm;
    cudaGetSymbolAddress((void**)&qkv,   g_qkv);
    cudaGetSymbolAddress((void**)&o,     g_o);
    cudaGetSymbolAddress((void**)&x2,    g_x2);
    cudaGetSymbolAddress((void**)&h,     g_h);
    cudaGetSymbolAddress((void**)&wqkvT, g_wqkvT);
    cudaGetSymbolAddress((void**)&bqkv,  g_bqkv);
    cudaGetSymbolAddress((void**)&woT,   g_woT);
    cudaGetSymbolAddress((void**)&w1T,   g_w1T);
    cudaGetSymbolAddress((void**)&w2T,   g_w2T);
    cudaGetSymbolAddress((void**)&bm,    g_bm);

    cudaFuncSetAttribute(gemm_mma<true,  false, true >, cudaFuncAttributeMaxDynamicSharedMemorySize, GEMM_SMEM);
    cudaFuncSetAttribute(gemm_mma<false, false, false>, cudaFuncAttributeMaxDynamicSharedMemorySize, GEMM_SMEM);
    cudaFuncSetAttribute(gemm_mma<false, true,  false>, cudaFuncAttributeMaxDynamicSharedMemorySize, GEMM_SMEM);

    // prep: weight transposes (tf32-rounded) + fused bias/mask table
    prep_kernel<<<2563, 256>>>(wq, wk, wv, bq, bk, bv, wo, w1, w2,
                               wqkvT, bqkv, woT, w1T, w2T);
    prep_bm_kernel<<<8192, 256>>>(rpe, amask, rel, bm);

    // fused QKV projection (gather; A=raw query -> CVTA)
    gemm_mma<true,  false, true ><<<dim3(6, 1024), 256, GEMM_SMEM>>>(query, wqkvT, bqkv, qkv, 768, 256);

    // windowed attention (tensor-core)
    attn_kernel<<<dim3(TOTW, NHEAD), 128>>>(qkv, bm, o);

    // output projection
    gemm_mma<false, false, false><<<dim3(2, 1024), 256, GEMM_SMEM>>>(o, woT, bo, h, 256, 256);

    // LN1 + residual
    ln1_kernel<<<MROWS, 256>>>(h, ln1g, ln1b, query, x2);

    // MLP
    gemm_mma<false, true,  false><<<dim3(6, 1024), 256, GEMM_SMEM>>>(x2, w1T, b1, qkv, 768, 256);
    gemm_mma<false, false, false><<<dim3(2, 1024), 256, GEMM_SMEM>>>(qkv, w2T, b2, o, 256, 768);

    // LN2 + residual, scatter to output
    ln2_kernel<<<MROWS, 256>>>(o, ln2g, ln2b, x2, out);
}

// round 8
// speedup vs baseline: 4.8176x; 1.3210x over previous
#include <cuda_runtime.h>
#include <cuda_fp16.h>
#include <math.h>
#include <stdint.h>

#define BATCH 32
#define CH    256
#define EMB   256
#define NHEAD 8
#define SHFT  4
#define TT    64
#define TOTW  2048
#define MROWS 131072
#define HID   768

// ---------------- scratch ----------------
__device__ float  g_qkv[(size_t)MROWS * 768];   // qkv out (fp32); later aliased as fp16 mlp1 out
__device__ float  g_o  [(size_t)MROWS * 256];   // mlp2 out (fp32)
__device__ float  g_h  [(size_t)MROWS * 256];   // proj out (fp32)
__device__ __half g_qh [(size_t)MROWS * 256];   // fp16 copy of query (pixel layout)
__device__ __half g_oh [(size_t)MROWS * 256];   // attn out (fp16)
__device__ __half g_x2h[(size_t)MROWS * 256];   // ln1 out / residual (fp16)
__device__ __half g_wqkvT[768 * 256];
__device__ float  g_bqkv [768];
__device__ __half g_woT  [256 * 256];
__device__ __half g_w1T  [768 * 256];
__device__ __half g_w2T  [256 * 768];
__device__ float  g_bm   [64 * 8 * 64 * 64];    // bias+mask table [win][head][t][s]

// row (window*64+token) -> pixel index in original query (folds roll by -S)
__device__ __forceinline__ int map_row(int row) {
    int w  = row >> 6;
    int t  = row & 63;
    int b  = w >> 6;
    int wi = w & 63;
    int hb = wi >> 3, wb = wi & 7;
    int i  = ((hb << 3) + (t >> 3) + SHFT) & 63;
    int j  = ((wb << 3) + (t & 7) + SHFT) & 63;
    return (b << 12) + (i << 6) + j;
}

__device__ __forceinline__ uint32_t smem_u32(const void* p) {
    uint32_t a;
    asm("{ .reg .u64 t; cvta.to.shared.u64 t, %1; cvt.u32.u64 %0, t; }" : "=r"(a) : "l"(p));
    return a;
}

__device__ __forceinline__ float round_tf32(float x) {
    asm("cvt.rn.tf32.f32 %0, %0;" : "+f"(x));
    return x;
}

__device__ __forceinline__ float tanh_fast(float x) {
    float r;
    asm("tanh.approx.f32 %0, %1;" : "=f"(r) : "f"(x));
    return r;
}

#define LDMX4(r0, r1, r2, r3, addr) \
    asm volatile("ldmatrix.sync.aligned.m8n8.x4.shared.b16 {%0,%1,%2,%3}, [%4];" \
        : "=r"(r0), "=r"(r1), "=r"(r2), "=r"(r3) : "r"(addr))

#define MMA_TF32(d, a0, a1, a2, a3, b0, b1) \
    asm volatile("mma.sync.aligned.m16n8k8.row.col.f32.tf32.tf32.f32 " \
        "{%0,%1,%2,%3}, {%4,%5,%6,%7}, {%8,%9}, {%0,%1,%2,%3};" \
        : "+f"((d)[0]), "+f"((d)[1]), "+f"((d)[2]), "+f"((d)[3]) \
        : "r"(a0), "r"(a1), "r"(a2), "r"(a3), "r"(b0), "r"(b1))

#define MMA_F16(d, a0, a1, a2, a3, b0, b1) \
    asm volatile("mma.sync.aligned.m16n8k16.row.col.f32.f16.f16.f32 " \
        "{%0,%1,%2,%3}, {%4,%5,%6,%7}, {%8,%9}, {%0,%1,%2,%3};" \
        : "+f"((d)[0]), "+f"((d)[1]), "+f"((d)[2]), "+f"((d)[3]) \
        : "r"(a0), "r"(a1), "r"(a2), "r"(a3), "r"(b0), "r"(b1))

#define CP_ASYNC16(dst, src) \
    asm volatile("cp.async.cg.shared.global [%0], [%1], 16;" :: "r"(dst), "l"(src))
#define CP_COMMIT()  asm volatile("cp.async.commit_group;" ::: "memory")
#define CP_WAIT1()   asm volatile("cp.async.wait_group 1;" ::: "memory")

// ---------------- fp16 mma.sync GEMM: C[M,N] = A[M,K] @ Bt[N,K]^T + bias -------
// CTA tile 128x128, BK=64 halves (128B rows), 8 warps (2m x 4n), warp 64x32.
// Byte-level smem layout/swizzle identical to the verified tf32 version.
#define STAGE_BYTES 32768
#define NSTAGE      3
#define GEMM_SMEM   (NSTAGE * STAGE_BYTES)

template<bool GATHER, bool GELU, bool HOUT>
__global__ __launch_bounds__(256, 2)
void gemm_mma(const __half* __restrict__ A, const __half* __restrict__ Bt,
              const float* __restrict__ bias, void* __restrict__ Cv,
              int N, int Kd)
{
    extern __shared__ float smem[];
    const uint32_t sbase = smem_u32(smem);
    const int tid  = threadIdx.x;
    const int lane = tid & 31;
    const int wid  = tid >> 5;
    const int warp_m = wid >> 2;
    const int warp_n = wid & 3;
    const int row0 = blockIdx.y * 128;
    const int col0 = blockIdx.x * 128;

    const int mrow = tid >> 3;            // 0..31
    const int c8   = tid & 7;             // 16B chunk within 128B row
    const uint32_t swc = (uint32_t)((c8 ^ (mrow & 7)) << 4);

    const __half* arow[4];
    const __half* brow[4];
    uint32_t stA[4];
#pragma unroll
    for (int i = 0; i < 4; i++) {
        const int m = mrow + 32 * i;
        arow[i] = (GATHER ? (A + (size_t)map_row(row0 + m) * CH)
                          : (A + (size_t)(row0 + m) * Kd)) + c8 * 8;
        brow[i] = Bt + (size_t)(col0 + m) * Kd + c8 * 8;
        stA[i] = (uint32_t)(m * 128) + swc;
    }

    const int rA  = warp_m * 64 + (lane & 15);
    const int hiA = lane >> 4;
    const int xA  = lane & 7;
    const int rB  = warp_n * 32 + ((lane >> 4) << 3) + (lane & 7);
    const int hiB = (lane >> 3) & 1;
    const int xB  = lane & 7;

    float acc[4][4][4];
#pragma unroll
    for (int i = 0; i < 4; i++)
#pragma unroll
        for (int j = 0; j < 4; j++)
#pragma unroll
            for (int e = 0; e < 4; e++) acc[i][j][e] = 0.f;

    const int T = Kd >> 6;                // k64 per stage

#pragma unroll
    for (int s = 0; s < NSTAGE - 1; s++) {
        const int k0 = s * 64;
        const uint32_t so = sbase + s * STAGE_BYTES;
#pragma unroll
        for (int i = 0; i < 4; i++) {
            CP_ASYNC16(so + stA[i],         arow[i] + k0);
            CP_ASYNC16(so + stA[i] + 16384, brow[i] + k0);
        }
        CP_COMMIT();
    }

    for (int t = 0; t < T; ++t) {
        CP_WAIT1();
        __syncthreads();

        const int kt = t + NSTAGE - 1;
        if (kt < T) {
            const int k0 = kt * 64;
            const uint32_t so = sbase + (kt % NSTAGE) * STAGE_BYTES;
#pragma unroll
            for (int i = 0; i < 4; i++) {
                CP_ASYNC16(so + stA[i],         arow[i] + k0);
                CP_ASYNC16(so + stA[i] + 16384, brow[i] + k0);
            }
        }
        CP_COMMIT();

        const uint32_t sa = sbase + (t % NSTAGE) * STAGE_BYTES;
        const uint32_t sb = sa + 16384;
#pragma unroll
        for (int kc = 0; kc < 4; kc++) {          // k16 per kc
            uint32_t af[4][4];
#pragma unroll
            for (int mt = 0; mt < 4; mt++) {
                const uint32_t addr = sa + (uint32_t)((rA + mt * 16) * 128)
                                    + (uint32_t)((((kc << 1) + hiA) ^ xA) << 4);
                LDMX4(af[mt][0], af[mt][1], af[mt][2], af[mt][3], addr);
            }
            uint32_t bf[4][2];
#pragma unroll
            for (int p = 0; p < 2; p++) {
                const uint32_t addr = sb + (uint32_t)((rB + p * 16) * 128)
                                    + (uint32_t)((((kc << 1) + hiB) ^ xB) << 4);
                LDMX4(bf[2*p][0], bf[2*p][1], bf[2*p+1][0], bf[2*p+1][1], addr);
            }
#pragma unroll
            for (int mt = 0; mt < 4; mt++)
#pragma unroll
                for (int nt = 0; nt < 4; nt++)
                    MMA_F16(acc[mt][nt], af[mt][0], af[mt][1], af[mt][2], af[mt][3],
                            bf[nt][0], bf[nt][1]);
        }
    }

    // ---- epilogue: bias (+gelu), write C (fp32 or fp16)
    const int rbase = row0 + warp_m * 64 + (lane >> 2);
    const int cb0   = col0 + warp_n * 32 + 2 * (lane & 3);
#pragma unroll
    for (int nt = 0; nt < 4; nt++) {
        const int cc = cb0 + nt * 8;
        const float bv0 = bias[cc], bv1 = bias[cc + 1];
#pragma unroll
        for (int mt = 0; mt < 4; mt++) {
            const int r = rbase + mt * 16;
            float v[4];
#pragma unroll
            for (int e = 0; e < 4; e++) {
                float x = acc[mt][nt][e] + ((e & 1) ? bv1 : bv0);
                if (GELU) {
                    float x3 = x * x * x;
                    x = 0.5f * x * (1.f + tanh_fast(0.7978845608028654f * (x + 0.044715f * x3)));
                }
                v[e] = x;
            }
            if (HOUT) {
                __half* Ch = (__half*)Cv;
                *(__half2*)(Ch + (size_t)r * N + cc)       = __floats2half2_rn(v[0], v[1]);
                *(__half2*)(Ch + (size_t)(r + 8) * N + cc) = __floats2half2_rn(v[2], v[3]);
            } else {
                float* C = (float*)Cv;
                *(float2*)(C + (size_t)r * N + cc)       = make_float2(v[0], v[1]);
                *(float2*)(C + (size_t)(r + 8) * N + cc) = make_float2(v[2], v[3]);
            }
        }
    }
}

// ---------------- attention (tensor-core tf32, frozen R7; fp16 output) ---------
#define SQ_STRIDE 36
#define SP_STRIDE 68

__global__ __launch_bounds__(128)
void attn_kernel(const float* __restrict__ qkv, const float* __restrict__ bm,
                 __half* __restrict__ o)
{
    const int w = blockIdx.x, head = blockIdx.y;
    const int tid = threadIdx.x;
    const int lane = tid & 31;
    const int wid  = tid >> 5;

    __shared__ __align__(16) float sQ[64 * SQ_STRIDE];
    __shared__ __align__(16) float sK[64 * SQ_STRIDE];
    __shared__ __align__(16) float sVt[32 * SP_STRIDE];
    __shared__ __align__(16) float sP[64 * SP_STRIDE];

    {
        const int row  = tid >> 1;
        const int half = (tid & 1) * 16;
        const float* base = qkv + (size_t)(w * 64 + row) * 768 + head * 32 + half;
        const float qscale = 0.17677669529663687f;
#pragma unroll
        for (int c = 0; c < 16; c += 4) {
            float4 qv = *(const float4*)(base + c);
            float4 kv = *(const float4*)(base + 256 + c);
            float4 vv = *(const float4*)(base + 512 + c);
            qv.x = round_tf32(qv.x * qscale); qv.y = round_tf32(qv.y * qscale);
            qv.z = round_tf32(qv.z * qscale); qv.w = round_tf32(qv.w * qscale);
            kv.x = round_tf32(kv.x); kv.y = round_tf32(kv.y);
            kv.z = round_tf32(kv.z); kv.w = round_tf32(kv.w);
            *(float4*)(sQ + row * SQ_STRIDE + half + c) = qv;
            *(float4*)(sK + row * SQ_STRIDE + half + c) = kv;
            const int d = half + c;
            sVt[(d + 0) * SP_STRIDE + row] = round_tf32(vv.x);
            sVt[(d + 1) * SP_STRIDE + row] = round_tf32(vv.y);
            sVt[(d + 2) * SP_STRIDE + row] = round_tf32(vv.z);
            sVt[(d + 3) * SP_STRIDE + row] = round_tf32(vv.w);
        }
    }
    __syncthreads();

    const uint32_t sQb  = smem_u32(sQ);
    const uint32_t sKb  = smem_u32(sK);
    const uint32_t sVtb = smem_u32(sVt);
    const uint32_t sPb  = smem_u32(sP);

    const int rA  = (lane & 15);
    const int hiA = lane >> 4;
    const int rBl = ((lane >> 4) << 3) + (lane & 7);
    const int hiB = (lane >> 3) & 1;

    float acc[8][4];
#pragma unroll
    for (int nt = 0; nt < 8; nt++)
#pragma unroll
        for (int e = 0; e < 4; e++) acc[nt][e] = 0.f;

#pragma unroll
    for (int kc = 0; kc < 4; kc++) {
        uint32_t a0, a1, a2, a3;
        {
            const uint32_t addr = sQb + (uint32_t)(((wid * 16 + rA) * SQ_STRIDE
                                   + kc * 8 + hiA * 4) * 4);
            LDMX4(a0, a1, a2, a3, addr);
        }
#pragma unroll
        for (int p = 0; p < 4; p++) {
            uint32_t b00, b01, b10, b11;
            const uint32_t addr = sKb + (uint32_t)(((p * 16 + rBl) * SQ_STRIDE
                                   + kc * 8 + hiB * 4) * 4);
            LDMX4(b00, b01, b10, b11, addr);
            MMA_TF32(acc[2*p],   a0, a1, a2, a3, b00, b01);
            MMA_TF32(acc[2*p+1], a0, a1, a2, a3, b10, b11);
        }
    }

    const float* bmr = bm + (size_t)((w & 63) * 8 + head) * 4096;
    const int r0 = wid * 16 + (lane >> 2);
    const int cb = 2 * (lane & 3);
#pragma unroll
    for (int nt = 0; nt < 8; nt++) {
        const float2 blo = *(const float2*)(bmr + r0 * 64 + 8 * nt + cb);
        const float2 bhi = *(const float2*)(bmr + (r0 + 8) * 64 + 8 * nt + cb);
        acc[nt][0] += blo.x; acc[nt][1] += blo.y;
        acc[nt][2] += bhi.x; acc[nt][3] += bhi.y;
    }
    float m0 = -1e30f, m1 = -1e30f;
#pragma unroll
    for (int nt = 0; nt < 8; nt++) {
        m0 = fmaxf(m0, fmaxf(acc[nt][0], acc[nt][1]));
        m1 = fmaxf(m1, fmaxf(acc[nt][2], acc[nt][3]));
    }
    m0 = fmaxf(m0, __shfl_xor_sync(0xffffffffu, m0, 1));
    m0 = fmaxf(m0, __shfl_xor_sync(0xffffffffu, m0, 2));
    m1 = fmaxf(m1, __shfl_xor_sync(0xffffffffu, m1, 1));
    m1 = fmaxf(m1, __shfl_xor_sync(0xffffffffu, m1, 2));

    float s0 = 0.f, s1 = 0.f;
#pragma unroll
    for (int nt = 0; nt < 8; nt++) {
        acc[nt][0] = __expf(acc[nt][0] - m0); s0 += acc[nt][0];
        acc[nt][1] = __expf(acc[nt][1] - m0); s0 += acc[nt][1];
        acc[nt][2] = __expf(acc[nt][2] - m1); s1 += acc[nt][2];
        acc[nt][3] = __expf(acc[nt][3] - m1); s1 += acc[nt][3];
    }
    s0 += __shfl_xor_sync(0xffffffffu, s0, 1);
    s0 += __shfl_xor_sync(0xffffffffu, s0, 2);
    s1 += __shfl_xor_sync(0xffffffffu, s1, 1);
    s1 += __shfl_xor_sync(0xffffffffu, s1, 2);
    const float inv0 = 1.f / s0, inv1 = 1.f / s1;

#pragma unroll
    for (int nt = 0; nt < 8; nt++) {
        float2 plo = make_float2(round_tf32(acc[nt][0] * inv0), round_tf32(acc[nt][1] * inv0));
        float2 phi = make_float2(round_tf32(acc[nt][2] * inv1), round_tf32(acc[nt][3] * inv1));
        *(float2*)(sP + r0 * SP_STRIDE + 8 * nt + cb)       = plo;
        *(float2*)(sP + (r0 + 8) * SP_STRIDE + 8 * nt + cb) = phi;
    }
    __syncwarp();

    float oacc[4][4];
#pragma unroll
    for (int nt = 0; nt < 4; nt++)
#pragma unroll
        for (int e = 0; e < 4; e++) oacc[nt][e] = 0.f;

#pragma unroll
    for (int kc = 0; kc < 8; kc++) {
        uint32_t a0, a1, a2, a3;
        {
            const uint32_t addr = sPb + (uint32_t)(((wid * 16 + rA) * SP_STRIDE
                                   + kc * 8 + hiA * 4) * 4);
            LDMX4(a0, a1, a2, a3, addr);
        }
#pragma unroll
        for (int p = 0; p < 2; p++) {
            uint32_t b00, b01, b10, b11;
            const uint32_t addr = sVtb + (uint32_t)(((p * 16 + rBl) * SP_STRIDE
                                   + kc * 8 + hiB * 4) * 4);
            LDMX4(b00, b01, b10, b11, addr);
            MMA_TF32(oacc[2*p],   a0, a1, a2, a3, b00, b01);
            MMA_TF32(oacc[2*p+1], a0, a1, a2, a3, b10, b11);
        }
    }

    // write O as fp16 (feeds proj GEMM)
    __half* obase = o + (size_t)(w * 64 + r0) * 256 + head * 32;
#pragma unroll
    for (int nt = 0; nt < 4; nt++) {
        *(__half2*)(obase + 8 * nt + cb) = __floats2half2_rn(oacc[nt][0], oacc[nt][1]);
        *(__half2*)(obase + 8 * 256 + 8 * nt + cb) = __floats2half2_rn(oacc[nt][2], oacc[nt][3]);
    }
}

// ---------------- LayerNorm (+residual) ----------------------------------------
__device__ __forceinline__ void block_stats(float val, float& mean, float& var) {
    float s = val, s2 = val * val;
#pragma unroll
    for (int off = 16; off; off >>= 1) {
        s  += __shfl_xor_sync(0xffffffffu, s,  off);
        s2 += __shfl_xor_sync(0xffffffffu, s2, off);
    }
    __shared__ float sh[8], sh2[8];
    int lane = threadIdx.x & 31, warp = threadIdx.x >> 5;
    if (lane == 0) { sh[warp] = s; sh2[warp] = s2; }
    __syncthreads();
    float sum = 0.f, sq = 0.f;
#pragma unroll
    for (int i = 0; i < 8; i++) { sum += sh[i]; sq += sh2[i]; }
    mean = sum * (1.f / 256.f);
    var  = sq * (1.f / 256.f) - mean * mean;
}

// x2h = fp16( LN1(proj) + gather(query) )
__global__ __launch_bounds__(256)
void ln1_kernel(const float* __restrict__ X, const float* __restrict__ g,
                const float* __restrict__ b, const float* __restrict__ query,
                __half* __restrict__ out)
{
    const int row = blockIdx.x, c = threadIdx.x;
    const float val = X[(size_t)row * CH + c];
    float mean, var;
    block_stats(val, mean, var);
    const float y = (val - mean) * rsqrtf(var + 1e-5f) * g[c] + b[c];
    out[(size_t)row * CH + c] = __float2half(y + query[(size_t)map_row(row) * CH + c]);
}

__global__ __launch_bounds__(256)
void ln2_kernel(const float* __restrict__ X, const float* __restrict__ g,
                const float* __restrict__ b, const __half* __restrict__ x2,
                float* __restrict__ out)
{
    const int row = blockIdx.x, c = threadIdx.x;
    const float val = X[(size_t)row * CH + c];
    float mean, var;
    block_stats(val, mean, var);
    const float y = (val - mean) * rsqrtf(var + 1e-5f) * g[c] + b[c];
    out[(size_t)map_row(row) * CH + c] = y + __half2float(x2[(size_t)row * CH + c]);
}

// ---------------- weight prep: transpose to [N,K] fp16 -------------------------
__global__ __launch_bounds__(256)
void prep_kernel(const float* __restrict__ wq, const float* __restrict__ wk,
                 const float* __restrict__ wv, const float* __restrict__ bq,
                 const float* __restrict__ bk, const float* __restrict__ bv,
                 const float* __restrict__ wo, const float* __restrict__ w1,
                 const float* __restrict__ w2,
                 __half* __restrict__ wqkvT, float* __restrict__ bqkv,
                 __half* __restrict__ woT, __half* __restrict__ w1T,
                 __half* __restrict__ w2T)
{
    int i = blockIdx.x * 256 + threadIdx.x;
    if (i < 196608) {
        int n = i >> 8, k = i & 255;
        float v = (n < 256) ? wq[k * 256 + n]
                : (n < 512) ? wk[k * 256 + (n - 256)]
                            : wv[k * 256 + (n - 512)];
        wqkvT[i] = __float2half(v);
    } else if (i < 262144) {
        int j = i - 196608; int n = j >> 8, k = j & 255;
        woT[j] = __float2half(wo[k * 256 + n]);
    } else if (i < 458752) {
        int j = i - 262144; int n = j >> 8, k = j & 255;
        w1T[j] = __float2half(w1[k * 768 + n]);
    } else if (i < 655360) {
        int j = i - 458752; int n = j / 768, k = j - n * 768;
        w2T[j] = __float2half(w2[k * 256 + n]);
    } else if (i < 656128) {
        int n = i - 655360;
        bqkv[n] = (n < 256) ? bq[n] : (n < 512) ? bk[n - 256] : bv[n - 512];
    }
}

// ---------------- query fp32 -> fp16 copy ---------------------------------------
__global__ __launch_bounds__(256)
void conv_query_kernel(const float* __restrict__ q, __half* __restrict__ qh)
{
    const int i = (blockIdx.x * 256 + threadIdx.x) * 4;
    float4 v = *(const float4*)(q + i);
    *(__half2*)(qh + i)     = __floats2half2_rn(v.x, v.y);
    *(__half2*)(qh + i + 2) = __floats2half2_rn(v.z, v.w);
}

// ---------------- bias+mask table ----------------------------------------------
__global__ __launch_bounds__(256)
void prep_bm_kernel(const float* __restrict__ rpe, const float* __restrict__ mask,
                    const int* __restrict__ rel, float* __restrict__ bm)
{
    int idx = blockIdx.x * 256 + threadIdx.x;
    int wi  = idx >> 15;
    int rem = idx & 32767;
    int h   = rem >> 12;
    int ts  = rem & 4095;
    bm[idx] = rpe[rel[ts] * NHEAD + h] + mask[wi * 4096 + ts];
}

// ---------------- launch --------------------------------------------------------
extern "C" void kernel_launch(void* const* d_in, const int* in_sizes, int n_in,
                              void* d_out, int out_size)
{
    const float* query = (const float*)d_in[0];
    const float* wq = (const float*)d_in[1];  const float* bq = (const float*)d_in[2];
    const float* wk = (const float*)d_in[3];  const float* bk = (const float*)d_in[4];
    const float* wv = (const float*)d_in[5];  const float* bv = (const float*)d_in[6];
    const float* wo = (const float*)d_in[7];  const float* bo = (const float*)d_in[8];
    const float* rpe = (const float*)d_in[9];
    const float* ln1g = (const float*)d_in[10]; const float* ln1b = (const float*)d_in[11];
    const float* ln2g = (const float*)d_in[12]; const float* ln2b = (const float*)d_in[13];
    const float* w1 = (const float*)d_in[14]; const float* b1 = (const float*)d_in[15];
    const float* w2 = (const float*)d_in[16]; const float* b2 = (const float*)d_in[17];
    const float* amask = (const float*)d_in[18];
    const int*   rel   = (const int*)d_in[19];
    float* out = (float*)d_out;

    float *qkv, *o, *h, *bqkv, *bm;
    __half *qh, *oh, *x2h, *wqkvT, *woT, *w1T, *w2T;
    cudaGetSymbolAddress((void**)&qkv,   g_qkv);
    cudaGetSymbolAddress((void**)&o,     g_o);
    cudaGetSymbolAddress((void**)&h,     g_h);
    cudaGetSymbolAddress((void**)&qh,    g_qh);
    cudaGetSymbolAddress((void**)&oh,    g_oh);
    cudaGetSymbolAddress((void**)&x2h,   g_x2h);
    cudaGetSymbolAddress((void**)&wqkvT, g_wqkvT);
    cudaGetSymbolAddress((void**)&bqkv,  g_bqkv);
    cudaGetSymbolAddress((void**)&woT,   g_woT);
    cudaGetSymbolAddress((void**)&w1T,   g_w1T);
    cudaGetSymbolAddress((void**)&w2T,   g_w2T);
    cudaGetSymbolAddress((void**)&bm,    g_bm);
    __half* mlph = (__half*)qkv;   // alias: qkv buffer is dead after attention

    cudaFuncSetAttribute(gemm_mma<true,  false, false>, cudaFuncAttributeMaxDynamicSharedMemorySize, GEMM_SMEM);
    cudaFuncSetAttribute(gemm_mma<false, false, false>, cudaFuncAttributeMaxDynamicSharedMemorySize, GEMM_SMEM);
    cudaFuncSetAttribute(gemm_mma<false, true,  true >, cudaFuncAttributeMaxDynamicSharedMemorySize, GEMM_SMEM);

    // prep: weights->fp16, bias/mask table, query->fp16
    prep_kernel<<<2563, 256>>>(wq, wk, wv, bq, bk, bv, wo, w1, w2,
                               wqkvT, bqkv, woT, w1T, w2T);
    prep_bm_kernel<<<8192, 256>>>(rpe, amask, rel, bm);
    conv_query_kernel<<<32768, 256>>>(query, qh);

    // fused QKV projection (gather on fp16 query copy) -> fp32 qkv
    gemm_mma<true,  false, false><<<dim3(6, 1024), 256, GEMM_SMEM>>>(qh, wqkvT, bqkv, qkv, 768, 256);

    // windowed attention -> fp16 o
    attn_kernel<<<dim3(TOTW, NHEAD), 128>>>(qkv, bm, oh);

    // output projection -> fp32 h
    gemm_mma<false, false, false><<<dim3(2, 1024), 256, GEMM_SMEM>>>(oh, woT, bo, h, 256, 256);

    // LN1 + residual -> fp16 x2
    ln1_kernel<<<MROWS, 256>>>(h, ln1g, ln1b, query, x2h);

    // MLP: gelu(x2@w1+b1) -> fp16 (alias of qkv buf); @w2+b2 -> fp32 o
    gemm_mma<false, true,  true ><<<dim3(6, 1024), 256, GEMM_SMEM>>>(x2h, w1T, b1, mlph, 768, 256);
    gemm_mma<false, false, false><<<dim3(2, 1024), 256, GEMM_SMEM>>>(mlph, w2T, b2, o, 256, 768);

    // LN2 + residual, scatter to output
    ln2_kernel<<<MROWS, 256>>>(o, ln2g, ln2b, x2h, out);
}

// round 9
// speedup vs baseline: 6.3938x; 1.3272x over previous
#include <cuda_runtime.h>
#include <cuda_fp16.h>
#include <math.h>
#include <stdint.h>

#define BATCH 32
#define CH    256
#define EMB   256
#define NHEAD 8
#define SHFT  4
#define TT    64
#define TOTW  2048
#define MROWS 131072
#define HID   768

// ---------------- scratch ----------------
__device__ float  g_qkv[(size_t)MROWS * 768];   // fp16 alias: qkv out; later mlp1 out
__device__ float  g_o  [(size_t)MROWS * 256];   // mlp2 out (fp32)
__device__ float  g_h  [(size_t)MROWS * 256];   // proj out (fp32)
__device__ __half g_qh [(size_t)MROWS * 256];   // fp16 copy of query (pixel layout)
__device__ __half g_oh [(size_t)MROWS * 256];   // attn out (fp16)
__device__ __half g_x2h[(size_t)MROWS * 256];   // ln1 out / residual (fp16)
__device__ __half g_wqkvT[768 * 256];
__device__ float  g_bqkv [768];
__device__ __half g_woT  [256 * 256];
__device__ __half g_w1T  [768 * 256];
__device__ __half g_w2T  [256 * 768];
__device__ float  g_bm   [64 * 8 * 64 * 64];    // bias+mask table [win][head][t][s]

// row (window*64+token) -> pixel index in original query (folds roll by -S)
__device__ __forceinline__ int map_row(int row) {
    int w  = row >> 6;
    int t  = row & 63;
    int b  = w >> 6;
    int wi = w & 63;
    int hb = wi >> 3, wb = wi & 7;
    int i  = ((hb << 3) + (t >> 3) + SHFT) & 63;
    int j  = ((wb << 3) + (t & 7) + SHFT) & 63;
    return (b << 12) + (i << 6) + j;
}

__device__ __forceinline__ uint32_t smem_u32(const void* p) {
    uint32_t a;
    asm("{ .reg .u64 t; cvta.to.shared.u64 t, %1; cvt.u32.u64 %0, t; }" : "=r"(a) : "l"(p));
    return a;
}

__device__ __forceinline__ float tanh_fast(float x) {
    float r;
    asm("tanh.approx.f32 %0, %1;" : "=f"(r) : "f"(x));
    return r;
}

#define LDMX4(r0, r1, r2, r3, addr) \
    asm volatile("ldmatrix.sync.aligned.m8n8.x4.shared.b16 {%0,%1,%2,%3}, [%4];" \
        : "=r"(r0), "=r"(r1), "=r"(r2), "=r"(r3) : "r"(addr))

#define MMA_F16(d, a0, a1, a2, a3, b0, b1) \
    asm volatile("mma.sync.aligned.m16n8k16.row.col.f32.f16.f16.f32 " \
        "{%0,%1,%2,%3}, {%4,%5,%6,%7}, {%8,%9}, {%0,%1,%2,%3};" \
        : "+f"((d)[0]), "+f"((d)[1]), "+f"((d)[2]), "+f"((d)[3]) \
        : "r"(a0), "r"(a1), "r"(a2), "r"(a3), "r"(b0), "r"(b1))

#define CP_ASYNC16(dst, src) \
    asm volatile("cp.async.cg.shared.global [%0], [%1], 16;" :: "r"(dst), "l"(src))
#define CP_COMMIT()  asm volatile("cp.async.commit_group;" ::: "memory")
#define CP_WAIT1()   asm volatile("cp.async.wait_group 1;" ::: "memory")

// ---------------- fp16 mma.sync GEMM (frozen R8 + q-scale epilogue) ------------
#define STAGE_BYTES 32768
#define NSTAGE      3
#define GEMM_SMEM   (NSTAGE * STAGE_BYTES)
#define QSCALE      0.17677669529663687f

template<bool GATHER, bool GELU, bool HOUT>
__global__ __launch_bounds__(256, 2)
void gemm_mma(const __half* __restrict__ A, const __half* __restrict__ Bt,
              const float* __restrict__ bias, void* __restrict__ Cv,
              int N, int Kd)
{
    extern __shared__ float smem[];
    const uint32_t sbase = smem_u32(smem);
    const int tid  = threadIdx.x;
    const int lane = tid & 31;
    const int wid  = tid >> 5;
    const int warp_m = wid >> 2;
    const int warp_n = wid & 3;
    const int row0 = blockIdx.y * 128;
    const int col0 = blockIdx.x * 128;

    const int mrow = tid >> 3;
    const int c8   = tid & 7;
    const uint32_t swc = (uint32_t)((c8 ^ (mrow & 7)) << 4);

    const __half* arow[4];
    const __half* brow[4];
    uint32_t stA[4];
#pragma unroll
    for (int i = 0; i < 4; i++) {
        const int m = mrow + 32 * i;
        arow[i] = (GATHER ? (A + (size_t)map_row(row0 + m) * CH)
                          : (A + (size_t)(row0 + m) * Kd)) + c8 * 8;
        brow[i] = Bt + (size_t)(col0 + m) * Kd + c8 * 8;
        stA[i] = (uint32_t)(m * 128) + swc;
    }

    const int rA  = warp_m * 64 + (lane & 15);
    const int hiA = lane >> 4;
    const int xA  = lane & 7;
    const int rB  = warp_n * 32 + ((lane >> 4) << 3) + (lane & 7);
    const int hiB = (lane >> 3) & 1;
    const int xB  = lane & 7;

    float acc[4][4][4];
#pragma unroll
    for (int i = 0; i < 4; i++)
#pragma unroll
        for (int j = 0; j < 4; j++)
#pragma unroll
            for (int e = 0; e < 4; e++) acc[i][j][e] = 0.f;

    const int T = Kd >> 6;

#pragma unroll
    for (int s = 0; s < NSTAGE - 1; s++) {
        const int k0 = s * 64;
        const uint32_t so = sbase + s * STAGE_BYTES;
#pragma unroll
        for (int i = 0; i < 4; i++) {
            CP_ASYNC16(so + stA[i],         arow[i] + k0);
            CP_ASYNC16(so + stA[i] + 16384, brow[i] + k0);
        }
        CP_COMMIT();
    }

    for (int t = 0; t < T; ++t) {
        CP_WAIT1();
        __syncthreads();

        const int kt = t + NSTAGE - 1;
        if (kt < T) {
            const int k0 = kt * 64;
            const uint32_t so = sbase + (kt % NSTAGE) * STAGE_BYTES;
#pragma unroll
            for (int i = 0; i < 4; i++) {
                CP_ASYNC16(so + stA[i],         arow[i] + k0);
                CP_ASYNC16(so + stA[i] + 16384, brow[i] + k0);
            }
        }
        CP_COMMIT();

        const uint32_t sa = sbase + (t % NSTAGE) * STAGE_BYTES;
        const uint32_t sb = sa + 16384;
#pragma unroll
        for (int kc = 0; kc < 4; kc++) {
            uint32_t af[4][4];
#pragma unroll
            for (int mt = 0; mt < 4; mt++) {
                const uint32_t addr = sa + (uint32_t)((rA + mt * 16) * 128)
                                    + (uint32_t)((((kc << 1) + hiA) ^ xA) << 4);
                LDMX4(af[mt][0], af[mt][1], af[mt][2], af[mt][3], addr);
            }
            uint32_t bf[4][2];
#pragma unroll
            for (int p = 0; p < 2; p++) {
                const uint32_t addr = sb + (uint32_t)((rB + p * 16) * 128)
                                    + (uint32_t)((((kc << 1) + hiB) ^ xB) << 4);
                LDMX4(bf[2*p][0], bf[2*p][1], bf[2*p+1][0], bf[2*p+1][1], addr);
            }
#pragma unroll
            for (int mt = 0; mt < 4; mt++)
#pragma unroll
                for (int nt = 0; nt < 4; nt++)
                    MMA_F16(acc[mt][nt], af[mt][0], af[mt][1], af[mt][2], af[mt][3],
                            bf[nt][0], bf[nt][1]);
        }
    }

    // ---- epilogue: bias (+gelu) (+q-scale for QKV), write fp32 or fp16
    const int rbase = row0 + warp_m * 64 + (lane >> 2);
    const int cb0   = col0 + warp_n * 32 + 2 * (lane & 3);
#pragma unroll
    for (int nt = 0; nt < 4; nt++) {
        const int cc = cb0 + nt * 8;
        const float bv0 = bias[cc], bv1 = bias[cc + 1];
        const float post = (GATHER && cc < 256) ? QSCALE : 1.f;  // scale q cols
#pragma unroll
        for (int mt = 0; mt < 4; mt++) {
            const int r = rbase + mt * 16;
            float v[4];
#pragma unroll
            for (int e = 0; e < 4; e++) {
                float x = acc[mt][nt][e] + ((e & 1) ? bv1 : bv0);
                if (GELU) {
                    float x3 = x * x * x;
                    x = 0.5f * x * (1.f + tanh_fast(0.7978845608028654f * (x + 0.044715f * x3)));
                }
                v[e] = x * post;
            }
            if (HOUT) {
                __half* Ch = (__half*)Cv;
                *(__half2*)(Ch + (size_t)r * N + cc)       = __floats2half2_rn(v[0], v[1]);
                *(__half2*)(Ch + (size_t)(r + 8) * N + cc) = __floats2half2_rn(v[2], v[3]);
            } else {
                float* C = (float*)Cv;
                *(float2*)(C + (size_t)r * N + cc)       = make_float2(v[0], v[1]);
                *(float2*)(C + (size_t)(r + 8) * N + cc) = make_float2(v[2], v[3]);
            }
        }
    }
}

// ---------------- attention v5: full fp16 mma (m16n8k16) -----------------------
// strides in halves: 40 (80B) and 72 (144B) -> conflict-free ldmatrix
#define AQ_STR 40
#define AP_STR 72

__global__ __launch_bounds__(128)
void attn_kernel(const __half* __restrict__ qkv, const float* __restrict__ bm,
                 __half* __restrict__ o)
{
    const int w = blockIdx.x, head = blockIdx.y;
    const int tid = threadIdx.x;
    const int lane = tid & 31;
    const int wid  = tid >> 5;

    __shared__ __align__(16) __half sQ[64 * AQ_STR];
    __shared__ __align__(16) __half sK[64 * AQ_STR];
    __shared__ __align__(16) __half sVt[32 * AP_STR];   // [d][s]
    __shared__ __align__(16) __half sP[64 * AP_STR];

    // ---- load Q,K rows + V transpose (qkv already fp16; q pre-scaled in GEMM)
    {
        const int row  = tid >> 1;
        const int half16 = (tid & 1) * 16;
        const __half* base = qkv + (size_t)(w * 64 + row) * 768 + head * 32 + half16;
        uint4 qv0 = *(const uint4*)(base);
        uint4 qv1 = *(const uint4*)(base + 8);
        uint4 kv0 = *(const uint4*)(base + 256);
        uint4 kv1 = *(const uint4*)(base + 264);
        *(uint4*)(sQ + row * AQ_STR + half16)     = qv0;
        *(uint4*)(sQ + row * AQ_STR + half16 + 8) = qv1;
        *(uint4*)(sK + row * AQ_STR + half16)     = kv0;
        *(uint4*)(sK + row * AQ_STR + half16 + 8) = kv1;
        __half vv[16];
        *(uint4*)(vv)     = *(const uint4*)(base + 512);
        *(uint4*)(vv + 8) = *(const uint4*)(base + 520);
#pragma unroll
        for (int j = 0; j < 16; j++)
            sVt[(half16 + j) * AP_STR + row] = vv[j];
    }
    __syncthreads();

    const uint32_t sQb  = smem_u32(sQ);
    const uint32_t sKb  = smem_u32(sK);
    const uint32_t sVtb = smem_u32(sVt);
    const uint32_t sPb  = smem_u32(sP);

    const int rA  = (lane & 15);
    const int hiA = lane >> 4;
    const int rBl = ((lane >> 4) << 3) + (lane & 7);
    const int hiB = (lane >> 3) & 1;

    // ---- QK^T (k=32 -> 2 kc of k16)
    float acc[8][4];
#pragma unroll
    for (int nt = 0; nt < 8; nt++)
#pragma unroll
        for (int e = 0; e < 4; e++) acc[nt][e] = 0.f;

#pragma unroll
    for (int kc = 0; kc < 2; kc++) {
        uint32_t a0, a1, a2, a3;
        {
            const uint32_t addr = sQb + (uint32_t)(((wid * 16 + rA) * AQ_STR
                                   + kc * 16 + hiA * 8) * 2);
            LDMX4(a0, a1, a2, a3, addr);
        }
#pragma unroll
        for (int p = 0; p < 4; p++) {
            uint32_t b00, b01, b10, b11;
            const uint32_t addr = sKb + (uint32_t)(((p * 16 + rBl) * AQ_STR
                                   + kc * 16 + hiB * 8) * 2);
            LDMX4(b00, b01, b10, b11, addr);
            MMA_F16(acc[2*p],   a0, a1, a2, a3, b00, b01);
            MMA_F16(acc[2*p+1], a0, a1, a2, a3, b10, b11);
        }
    }

    // ---- bias+mask, softmax on fragments (fp32)
    const float* bmr = bm + (size_t)((w & 63) * 8 + head) * 4096;
    const int r0 = wid * 16 + (lane >> 2);
    const int cb = 2 * (lane & 3);
#pragma unroll
    for (int nt = 0; nt < 8; nt++) {
        const float2 blo = *(const float2*)(bmr + r0 * 64 + 8 * nt + cb);
        const float2 bhi = *(const float2*)(bmr + (r0 + 8) * 64 + 8 * nt + cb);
        acc[nt][0] += blo.x; acc[nt][1] += blo.y;
        acc[nt][2] += bhi.x; acc[nt][3] += bhi.y;
    }
    float m0 = -1e30f, m1 = -1e30f;
#pragma unroll
    for (int nt = 0; nt < 8; nt++) {
        m0 = fmaxf(m0, fmaxf(acc[nt][0], acc[nt][1]));
        m1 = fmaxf(m1, fmaxf(acc[nt][2], acc[nt][3]));
    }
    m0 = fmaxf(m0, __shfl_xor_sync(0xffffffffu, m0, 1));
    m0 = fmaxf(m0, __shfl_xor_sync(0xffffffffu, m0, 2));
    m1 = fmaxf(m1, __shfl_xor_sync(0xffffffffu, m1, 1));
    m1 = fmaxf(m1, __shfl_xor_sync(0xffffffffu, m1, 2));

    float s0 = 0.f, s1 = 0.f;
#pragma unroll
    for (int nt = 0; nt < 8; nt++) {
        acc[nt][0] = __expf(acc[nt][0] - m0); s0 += acc[nt][0];
        acc[nt][1] = __expf(acc[nt][1] - m0); s0 += acc[nt][1];
        acc[nt][2] = __expf(acc[nt][2] - m1); s1 += acc[nt][2];
        acc[nt][3] = __expf(acc[nt][3] - m1); s1 += acc[nt][3];
    }
    s0 += __shfl_xor_sync(0xffffffffu, s0, 1);
    s0 += __shfl_xor_sync(0xffffffffu, s0, 2);
    s1 += __shfl_xor_sync(0xffffffffu, s1, 1);
    s1 += __shfl_xor_sync(0xffffffffu, s1, 2);
    const float inv0 = 1.f / s0, inv1 = 1.f / s1;

    // ---- P -> smem fp16 (warp-private rows)
#pragma unroll
    for (int nt = 0; nt < 8; nt++) {
        *(__half2*)(sP + r0 * AP_STR + 8 * nt + cb) =
            __floats2half2_rn(acc[nt][0] * inv0, acc[nt][1] * inv0);
        *(__half2*)(sP + (r0 + 8) * AP_STR + 8 * nt + cb) =
            __floats2half2_rn(acc[nt][2] * inv1, acc[nt][3] * inv1);
    }
    __syncwarp();

    // ---- P @ V (k=64 -> 4 kc of k16; n=32 -> 2 p-tiles)
    float oacc[4][4];
#pragma unroll
    for (int nt = 0; nt < 4; nt++)
#pragma unroll
        for (int e = 0; e < 4; e++) oacc[nt][e] = 0.f;

#pragma unroll
    for (int kc = 0; kc < 4; kc++) {
        uint32_t a0, a1, a2, a3;
        {
            const uint32_t addr = sPb + (uint32_t)(((wid * 16 + rA) * AP_STR
                                   + kc * 16 + hiA * 8) * 2);
            LDMX4(a0, a1, a2, a3, addr);
        }
#pragma unroll
        for (int p = 0; p < 2; p++) {
            uint32_t b00, b01, b10, b11;
            const uint32_t addr = sVtb + (uint32_t)(((p * 16 + rBl) * AP_STR
                                   + kc * 16 + hiB * 8) * 2);
            LDMX4(b00, b01, b10, b11, addr);
            MMA_F16(oacc[2*p],   a0, a1, a2, a3, b00, b01);
            MMA_F16(oacc[2*p+1], a0, a1, a2, a3, b10, b11);
        }
    }

    // ---- write O fp16
    __half* obase = o + (size_t)(w * 64 + r0) * 256 + head * 32;
#pragma unroll
    for (int nt = 0; nt < 4; nt++) {
        *(__half2*)(obase + 8 * nt + cb) = __floats2half2_rn(oacc[nt][0], oacc[nt][1]);
        *(__half2*)(obase + 8 * 256 + 8 * nt + cb) = __floats2half2_rn(oacc[nt][2], oacc[nt][3]);
    }
}

// ---------------- LayerNorm: warp-per-row (8 rows / 256-thr block) -------------
__global__ __launch_bounds__(256)
void ln1_kernel(const float* __restrict__ X, const float* __restrict__ g,
                const float* __restrict__ b, const float* __restrict__ query,
                __half* __restrict__ out)
{
    const int row  = blockIdx.x * 8 + (threadIdx.x >> 5);
    const int lane = threadIdx.x & 31;
    const int c0   = lane * 8;

    const float* xr = X + (size_t)row * CH + c0;
    float v[8];
    *(float4*)(v)     = *(const float4*)(xr);
    *(float4*)(v + 4) = *(const float4*)(xr + 4);

    float s = 0.f, s2 = 0.f;
#pragma unroll
    for (int i = 0; i < 8; i++) { s += v[i]; s2 += v[i] * v[i]; }
#pragma unroll
    for (int off = 16; off; off >>= 1) {
        s  += __shfl_xor_sync(0xffffffffu, s,  off);
        s2 += __shfl_xor_sync(0xffffffffu, s2, off);
    }
    const float mean = s * (1.f / 256.f);
    const float rstd = rsqrtf(s2 * (1.f / 256.f) - mean * mean + 1e-5f);

    float gv[8], bv[8], qv[8];
    *(float4*)(gv)     = *(const float4*)(g + c0);
    *(float4*)(gv + 4) = *(const float4*)(g + c0 + 4);
    *(float4*)(bv)     = *(const float4*)(b + c0);
    *(float4*)(bv + 4) = *(const float4*)(b + c0 + 4);
    const float* qr = query + (size_t)map_row(row) * CH + c0;
    *(float4*)(qv)     = *(const float4*)(qr);
    *(float4*)(qv + 4) = *(const float4*)(qr + 4);

    __half h8[8];
#pragma unroll
    for (int i = 0; i < 8; i++)
        h8[i] = __float2half((v[i] - mean) * rstd * gv[i] + bv[i] + qv[i]);
    *(uint4*)(out + (size_t)row * CH + c0) = *(uint4*)h8;
}

__global__ __launch_bounds__(256)
void ln2_kernel(const float* __restrict__ X, const float* __restrict__ g,
                const float* __restrict__ b, const __half* __restrict__ x2,
                float* __restrict__ out)
{
    const int row  = blockIdx.x * 8 + (threadIdx.x >> 5);
    const int lane = threadIdx.x & 31;
    const int c0   = lane * 8;

    const float* xr = X + (size_t)row * CH + c0;
    float v[8];
    *(float4*)(v)     = *(const float4*)(xr);
    *(float4*)(v + 4) = *(const float4*)(xr + 4);

    float s = 0.f, s2 = 0.f;
#pragma unroll
    for (int i = 0; i < 8; i++) { s += v[i]; s2 += v[i] * v[i]; }
#pragma unroll
    for (int off = 16; off; off >>= 1) {
        s  += __shfl_xor_sync(0xffffffffu, s,  off);
        s2 += __shfl_xor_sync(0xffffffffu, s2, off);
    }
    const float mean = s * (1.f / 256.f);
    const float rstd = rsqrtf(s2 * (1.f / 256.f) - mean * mean + 1e-5f);

    float gv[8], bv[8];
    *(float4*)(gv)     = *(const float4*)(g + c0);
    *(float4*)(gv + 4) = *(const float4*)(g + c0 + 4);
    *(float4*)(bv)     = *(const float4*)(b + c0);
    *(float4*)(bv + 4) = *(const float4*)(b + c0 + 4);
    __half r8[8];
    *(uint4*)(r8) = *(const uint4*)(x2 + (size_t)row * CH + c0);

    float o8[8];
#pragma unroll
    for (int i = 0; i < 8; i++)
        o8[i] = (v[i] - mean) * rstd * gv[i] + bv[i] + __half2float(r8[i]);
    float* op = out + (size_t)map_row(row) * CH + c0;
    *(float4*)(op)     = *(float4*)(o8);
    *(float4*)(op + 4) = *(float4*)(o8 + 4);
}

// ---------------- weight prep: transpose to [N,K] fp16 -------------------------
__global__ __launch_bounds__(256)
void prep_kernel(const float* __restrict__ wq, const float* __restrict__ wk,
                 const float* __restrict__ wv, const float* __restrict__ bq,
                 const float* __restrict__ bk, const float* __restrict__ bv,
                 const float* __restrict__ wo, const float* __restrict__ w1,
                 const float* __restrict__ w2,
                 __half* __restrict__ wqkvT, float* __restrict__ bqkv,
                 __half* __restrict__ woT, __half* __restrict__ w1T,
                 __half* __restrict__ w2T)
{
    int i = blockIdx.x * 256 + threadIdx.x;
    if (i < 196608) {
        int n = i >> 8, k = i & 255;
        float v = (n < 256) ? wq[k * 256 + n]
                : (n < 512) ? wk[k * 256 + (n - 256)]
                            : wv[k * 256 + (n - 512)];
        wqkvT[i] = __float2half(v);
    } else if (i < 262144) {
        int j = i - 196608; int n = j >> 8, k = j & 255;
        woT[j] = __float2half(wo[k * 256 + n]);
    } else if (i < 458752) {
        int j = i - 262144; int n = j >> 8, k = j & 255;
        w1T[j] = __float2half(w1[k * 768 + n]);
    } else if (i < 655360) {
        int j = i - 458752; int n = j / 768, k = j - n * 768;
        w2T[j] = __float2half(w2[k * 256 + n]);
    } else if (i < 656128) {
        int n = i - 655360;
        bqkv[n] = (n < 256) ? bq[n] : (n < 512) ? bk[n - 256] : bv[n - 512];
    }
}

// ---------------- query fp32 -> fp16 copy ---------------------------------------
__global__ __launch_bounds__(256)
void conv_query_kernel(const float* __restrict__ q, __half* __restrict__ qh)
{
    const int i = (blockIdx.x * 256 + threadIdx.x) * 4;
    float4 v = *(const float4*)(q + i);
    *(__half2*)(qh + i)     = __floats2half2_rn(v.x, v.y);
    *(__half2*)(qh + i + 2) = __floats2half2_rn(v.z, v.w);
}

// ---------------- bias+mask table ----------------------------------------------
__global__ __launch_bounds__(256)
void prep_bm_kernel(const float* __restrict__ rpe, const float* __restrict__ mask,
                    const int* __restrict__ rel, float* __restrict__ bm)
{
    int idx = blockIdx.x * 256 + threadIdx.x;
    int wi  = idx >> 15;
    int rem = idx & 32767;
    int h   = rem >> 12;
    int ts  = rem & 4095;
    bm[idx] = rpe[rel[ts] * NHEAD + h] + mask[wi * 4096 + ts];
}

// ---------------- launch --------------------------------------------------------
extern "C" void kernel_launch(void* const* d_in, const int* in_sizes, int n_in,
                              void* d_out, int out_size)
{
    const float* query = (const float*)d_in[0];
    const float* wq = (const float*)d_in[1];  const float* bq = (const float*)d_in[2];
    const float* wk = (const float*)d_in[3];  const float* bk = (const float*)d_in[4];
    const float* wv = (const float*)d_in[5];  const float* bv = (const float*)d_in[6];
    const float* wo = (const float*)d_in[7];  const float* bo = (const float*)d_in[8];
    const float* rpe = (const float*)d_in[9];
    const float* ln1g = (const float*)d_in[10]; const float* ln1b = (const float*)d_in[11];
    const float* ln2g = (const float*)d_in[12]; const float* ln2b = (const float*)d_in[13];
    const float* w1 = (const float*)d_in[14]; const float* b1 = (const float*)d_in[15];
    const float* w2 = (const float*)d_in[16]; const float* b2 = (const float*)d_in[17];
    const float* amask = (const float*)d_in[18];
    const int*   rel   = (const int*)d_in[19];
    float* out = (float*)d_out;

    float *qkvf, *o, *h, *bqkv, *bm;
    __half *qh, *oh, *x2h, *wqkvT, *woT, *w1T, *w2T;
    cudaGetSymbolAddress((void**)&qkvf,  g_qkv);
    cudaGetSymbolAddress((void**)&o,     g_o);
    cudaGetSymbolAddress((void**)&h,     g_h);
    cudaGetSymbolAddress((void**)&qh,    g_qh);
    cudaGetSymbolAddress((void**)&oh,    g_oh);
    cudaGetSymbolAddress((void**)&x2h,   g_x2h);
    cudaGetSymbolAddress((void**)&wqkvT, g_wqkvT);
    cudaGetSymbolAddress((void**)&bqkv,  g_bqkv);
    cudaGetSymbolAddress((void**)&woT,   g_woT);
    cudaGetSymbolAddress((void**)&w1T,   g_w1T);
    cudaGetSymbolAddress((void**)&w2T,   g_w2T);
    cudaGetSymbolAddress((void**)&bm,    g_bm);
    __half* qkvh = (__half*)qkvf;   // fp16 qkv / mlp1 alias

    cudaFuncSetAttribute(gemm_mma<true,  false, true >, cudaFuncAttributeMaxDynamicSharedMemorySize, GEMM_SMEM);
    cudaFuncSetAttribute(gemm_mma<false, false, false>, cudaFuncAttributeMaxDynamicSharedMemorySize, GEMM_SMEM);
    cudaFuncSetAttribute(gemm_mma<false, true,  true >, cudaFuncAttributeMaxDynamicSharedMemorySize, GEMM_SMEM);

    // prep: weights->fp16, bias/mask table, query->fp16
    prep_kernel<<<2563, 256>>>(wq, wk, wv, bq, bk, bv, wo, w1, w2,
                               wqkvT, bqkv, woT, w1T, w2T);
    prep_bm_kernel<<<8192, 256>>>(rpe, amask, rel, bm);
    conv_query_kernel<<<32768, 256>>>(query, qh);

    // fused QKV projection -> fp16 qkv (q pre-scaled by 1/sqrt(D) in epilogue)
    gemm_mma<true,  false, true ><<<dim3(6, 1024), 256, GEMM_SMEM>>>(qh, wqkvT, bqkv, qkvh, 768, 256);

    // windowed attention (fp16 mma) -> fp16 o
    attn_kernel<<<dim3(TOTW, NHEAD), 128>>>(qkvh, bm, oh);

    // output projection -> fp32 h
    gemm_mma<false, false, false><<<dim3(2, 1024), 256, GEMM_SMEM>>>(oh, woT, bo, h, 256, 256);

    // LN1 + residual -> fp16 x2
    ln1_kernel<<<MROWS / 8, 256>>>(h, ln1g, ln1b, query, x2h);

    // MLP: gelu(x2@w1+b1) -> fp16 (alias); @w2+b2 -> fp32 o
    gemm_mma<false, true,  true ><<<dim3(6, 1024), 256, GEMM_SMEM>>>(x2h, w1T, b1, qkvh, 768, 256);
    gemm_mma<false, false, false><<<dim3(2, 1024), 256, GEMM_SMEM>>>(qkvh, w2T, b2, o, 256, 768);

    // LN2 + residual, scatter to output
    ln2_kernel<<<MROWS / 8, 256>>>(o, ln2g, ln2b, x2h, out);
}

// round 10
// speedup vs baseline: 6.8014x; 1.0638x over previous
#include <cuda_runtime.h>
#include <cuda_fp16.h>
#include <math.h>
#include <stdint.h>

#define BATCH 32
#define CH    256
#define EMB   256
#define NHEAD 8
#define SHFT  4
#define TT    64
#define TOTW  2048
#define MROWS 131072
#define HID   768

// ---------------- scratch ----------------
__device__ float  g_qkv[(size_t)MROWS * 768];   // fp16 alias: qkv out; later mlp1 out
__device__ float  g_h  [(size_t)MROWS * 256];   // fp16 alias: proj out
__device__ __half g_qh [(size_t)MROWS * 256];   // fp16 copy of query (pixel layout)
__device__ __half g_oh [(size_t)MROWS * 256];   // attn out; later mlp2 out (fp16)
__device__ __half g_x2h[(size_t)MROWS * 256];   // ln1 out / residual (fp16)
__device__ __half g_wqkvT[768 * 256];
__device__ float  g_bqkv [768];
__device__ __half g_woT  [256 * 256];
__device__ __half g_w1T  [768 * 256];
__device__ __half g_w2T  [256 * 768];
__device__ float  g_bm   [64 * 8 * 64 * 64];    // bias+mask table [win][head][t][s]

// row (window*64+token) -> pixel index in original query (folds roll by -S)
__device__ __forceinline__ int map_row(int row) {
    int w  = row >> 6;
    int t  = row & 63;
    int b  = w >> 6;
    int wi = w & 63;
    int hb = wi >> 3, wb = wi & 7;
    int i  = ((hb << 3) + (t >> 3) + SHFT) & 63;
    int j  = ((wb << 3) + (t & 7) + SHFT) & 63;
    return (b << 12) + (i << 6) + j;
}

__device__ __forceinline__ uint32_t smem_u32(const void* p) {
    uint32_t a;
    asm("{ .reg .u64 t; cvta.to.shared.u64 t, %1; cvt.u32.u64 %0, t; }" : "=r"(a) : "l"(p));
    return a;
}

__device__ __forceinline__ float tanh_fast(float x) {
    float r;
    asm("tanh.approx.f32 %0, %1;" : "=f"(r) : "f"(x));
    return r;
}

__device__ __forceinline__ uint32_t h2pack(float lo, float hi) {
    __half2 h = __floats2half2_rn(lo, hi);
    return *(uint32_t*)&h;
}

#define LDMX4(r0, r1, r2, r3, addr) \
    asm volatile("ldmatrix.sync.aligned.m8n8.x4.shared.b16 {%0,%1,%2,%3}, [%4];" \
        : "=r"(r0), "=r"(r1), "=r"(r2), "=r"(r3) : "r"(addr))

#define MMA_F16(d, a0, a1, a2, a3, b0, b1) \
    asm volatile("mma.sync.aligned.m16n8k16.row.col.f32.f16.f16.f32 " \
        "{%0,%1,%2,%3}, {%4,%5,%6,%7}, {%8,%9}, {%0,%1,%2,%3};" \
        : "+f"((d)[0]), "+f"((d)[1]), "+f"((d)[2]), "+f"((d)[3]) \
        : "r"(a0), "r"(a1), "r"(a2), "r"(a3), "r"(b0), "r"(b1))

#define CP_ASYNC16(dst, src) \
    asm volatile("cp.async.cg.shared.global [%0], [%1], 16;" :: "r"(dst), "l"(src))
#define CP_COMMIT()  asm volatile("cp.async.commit_group;" ::: "memory")
#define CP_WAIT1()   asm volatile("cp.async.wait_group 1;" ::: "memory")

// ---------------- fp16 mma.sync GEMM (frozen R8/R9) ----------------------------
#define STAGE_BYTES 32768
#define NSTAGE      3
#define GEMM_SMEM   (NSTAGE * STAGE_BYTES)
#define QSCALE      0.17677669529663687f

template<bool GATHER, bool GELU, bool HOUT>
__global__ __launch_bounds__(256, 2)
void gemm_mma(const __half* __restrict__ A, const __half* __restrict__ Bt,
              const float* __restrict__ bias, void* __restrict__ Cv,
              int N, int Kd)
{
    extern __shared__ float smem[];
    const uint32_t sbase = smem_u32(smem);
    const int tid  = threadIdx.x;
    const int lane = tid & 31;
    const int wid  = tid >> 5;
    const int warp_m = wid >> 2;
    const int warp_n = wid & 3;
    const int row0 = blockIdx.y * 128;
    const int col0 = blockIdx.x * 128;

    const int mrow = tid >> 3;
    const int c8   = tid & 7;
    const uint32_t swc = (uint32_t)((c8 ^ (mrow & 7)) << 4);

    const __half* arow[4];
    const __half* brow[4];
    uint32_t stA[4];
#pragma unroll
    for (int i = 0; i < 4; i++) {
        const int m = mrow + 32 * i;
        arow[i] = (GATHER ? (A + (size_t)map_row(row0 + m) * CH)
                          : (A + (size_t)(row0 + m) * Kd)) + c8 * 8;
        brow[i] = Bt + (size_t)(col0 + m) * Kd + c8 * 8;
        stA[i] = (uint32_t)(m * 128) + swc;
    }

    const int rA  = warp_m * 64 + (lane & 15);
    const int hiA = lane >> 4;
    const int xA  = lane & 7;
    const int rB  = warp_n * 32 + ((lane >> 4) << 3) + (lane & 7);
    const int hiB = (lane >> 3) & 1;
    const int xB  = lane & 7;

    float acc[4][4][4];
#pragma unroll
    for (int i = 0; i < 4; i++)
#pragma unroll
        for (int j = 0; j < 4; j++)
#pragma unroll
            for (int e = 0; e < 4; e++) acc[i][j][e] = 0.f;

    const int T = Kd >> 6;

#pragma unroll
    for (int s = 0; s < NSTAGE - 1; s++) {
        const int k0 = s * 64;
        const uint32_t so = sbase + s * STAGE_BYTES;
#pragma unroll
        for (int i = 0; i < 4; i++) {
            CP_ASYNC16(so + stA[i],         arow[i] + k0);
            CP_ASYNC16(so + stA[i] + 16384, brow[i] + k0);
        }
        CP_COMMIT();
    }

    for (int t = 0; t < T; ++t) {
        CP_WAIT1();
        __syncthreads();

        const int kt = t + NSTAGE - 1;
        if (kt < T) {
            const int k0 = kt * 64;
            const uint32_t so = sbase + (kt % NSTAGE) * STAGE_BYTES;
#pragma unroll
            for (int i = 0; i < 4; i++) {
                CP_ASYNC16(so + stA[i],         arow[i] + k0);
                CP_ASYNC16(so + stA[i] + 16384, brow[i] + k0);
            }
        }
        CP_COMMIT();

        const uint32_t sa = sbase + (t % NSTAGE) * STAGE_BYTES;
        const uint32_t sb = sa + 16384;
#pragma unroll
        for (int kc = 0; kc < 4; kc++) {
            uint32_t af[4][4];
#pragma unroll
            for (int mt = 0; mt < 4; mt++) {
                const uint32_t addr = sa + (uint32_t)((rA + mt * 16) * 128)
                                    + (uint32_t)((((kc << 1) + hiA) ^ xA) << 4);
                LDMX4(af[mt][0], af[mt][1], af[mt][2], af[mt][3], addr);
            }
            uint32_t bf[4][2];
#pragma unroll
            for (int p = 0; p < 2; p++) {
                const uint32_t addr = sb + (uint32_t)((rB + p * 16) * 128)
                                    + (uint32_t)((((kc << 1) + hiB) ^ xB) << 4);
                LDMX4(bf[2*p][0], bf[2*p][1], bf[2*p+1][0], bf[2*p+1][1], addr);
            }
#pragma unroll
            for (int mt = 0; mt < 4; mt++)
#pragma unroll
                for (int nt = 0; nt < 4; nt++)
                    MMA_F16(acc[mt][nt], af[mt][0], af[mt][1], af[mt][2], af[mt][3],
                            bf[nt][0], bf[nt][1]);
        }
    }

    // ---- epilogue: bias (+gelu) (+q-scale for QKV), write fp32 or fp16
    const int rbase = row0 + warp_m * 64 + (lane >> 2);
    const int cb0   = col0 + warp_n * 32 + 2 * (lane & 3);
#pragma unroll
    for (int nt = 0; nt < 4; nt++) {
        const int cc = cb0 + nt * 8;
        const float bv0 = bias[cc], bv1 = bias[cc + 1];
        const float post = (GATHER && cc < 256) ? QSCALE : 1.f;
#pragma unroll
        for (int mt = 0; mt < 4; mt++) {
            const int r = rbase + mt * 16;
            float v[4];
#pragma unroll
            for (int e = 0; e < 4; e++) {
                float x = acc[mt][nt][e] + ((e & 1) ? bv1 : bv0);
                if (GELU) {
                    float x3 = x * x * x;
                    x = 0.5f * x * (1.f + tanh_fast(0.7978845608028654f * (x + 0.044715f * x3)));
                }
                v[e] = x * post;
            }
            if (HOUT) {
                __half* Ch = (__half*)Cv;
                *(__half2*)(Ch + (size_t)r * N + cc)       = __floats2half2_rn(v[0], v[1]);
                *(__half2*)(Ch + (size_t)(r + 8) * N + cc) = __floats2half2_rn(v[2], v[3]);
            } else {
                float* C = (float*)Cv;
                *(float2*)(C + (size_t)r * N + cc)       = make_float2(v[0], v[1]);
                *(float2*)(C + (size_t)(r + 8) * N + cc) = make_float2(v[2], v[3]);
            }
        }
    }
}

// ---------------- attention v6: fp16 mma, P kept in registers ------------------
#define AQ_STR 40
#define AV_STR 72

__global__ __launch_bounds__(128)
void attn_kernel(const __half* __restrict__ qkv, const float* __restrict__ bm,
                 __half* __restrict__ o)
{
    const int w = blockIdx.x, head = blockIdx.y;
    const int tid = threadIdx.x;
    const int lane = tid & 31;
    const int wid  = tid >> 5;

    __shared__ __align__(16) __half sQ[64 * AQ_STR];
    __shared__ __align__(16) __half sK[64 * AQ_STR];
    __shared__ __align__(16) __half sVt[32 * AV_STR];   // [d][s]

    // ---- load Q,K rows + V transpose (qkv already fp16; q pre-scaled in GEMM)
    {
        const int row  = tid >> 1;
        const int half16 = (tid & 1) * 16;
        const __half* base = qkv + (size_t)(w * 64 + row) * 768 + head * 32 + half16;
        uint4 qv0 = *(const uint4*)(base);
        uint4 qv1 = *(const uint4*)(base + 8);
        uint4 kv0 = *(const uint4*)(base + 256);
        uint4 kv1 = *(const uint4*)(base + 264);
        *(uint4*)(sQ + row * AQ_STR + half16)     = qv0;
        *(uint4*)(sQ + row * AQ_STR + half16 + 8) = qv1;
        *(uint4*)(sK + row * AQ_STR + half16)     = kv0;
        *(uint4*)(sK + row * AQ_STR + half16 + 8) = kv1;
        __half vv[16];
        *(uint4*)(vv)     = *(const uint4*)(base + 512);
        *(uint4*)(vv + 8) = *(const uint4*)(base + 520);
#pragma unroll
        for (int j = 0; j < 16; j++)
            sVt[(half16 + j) * AV_STR + row] = vv[j];
    }
    __syncthreads();

    const uint32_t sQb  = smem_u32(sQ);
    const uint32_t sKb  = smem_u32(sK);
    const uint32_t sVtb = smem_u32(sVt);

    const int rA  = (lane & 15);
    const int hiA = lane >> 4;
    const int rBl = ((lane >> 4) << 3) + (lane & 7);
    const int hiB = (lane >> 3) & 1;

    // ---- QK^T (k=32 -> 2 kc of k16)
    float acc[8][4];
#pragma unroll
    for (int nt = 0; nt < 8; nt++)
#pragma unroll
        for (int e = 0; e < 4; e++) acc[nt][e] = 0.f;

#pragma unroll
    for (int kc = 0; kc < 2; kc++) {
        uint32_t a0, a1, a2, a3;
        {
            const uint32_t addr = sQb + (uint32_t)(((wid * 16 + rA) * AQ_STR
                                   + kc * 16 + hiA * 8) * 2);
            LDMX4(a0, a1, a2, a3, addr);
        }
#pragma unroll
        for (int p = 0; p < 4; p++) {
            uint32_t b00, b01, b10, b11;
            const uint32_t addr = sKb + (uint32_t)(((p * 16 + rBl) * AQ_STR
                                   + kc * 16 + hiB * 8) * 2);
            LDMX4(b00, b01, b10, b11, addr);
            MMA_F16(acc[2*p],   a0, a1, a2, a3, b00, b01);
            MMA_F16(acc[2*p+1], a0, a1, a2, a3, b10, b11);
        }
    }

    // ---- bias+mask, softmax on fragments (fp32)
    const float* bmr = bm + (size_t)((w & 63) * 8 + head) * 4096;
    const int r0 = wid * 16 + (lane >> 2);
    const int cb = 2 * (lane & 3);
#pragma unroll
    for (int nt = 0; nt < 8; nt++) {
        const float2 blo = *(const float2*)(bmr + r0 * 64 + 8 * nt + cb);
        const float2 bhi = *(const float2*)(bmr + (r0 + 8) * 64 + 8 * nt + cb);
        acc[nt][0] += blo.x; acc[nt][1] += blo.y;
        acc[nt][2] += bhi.x; acc[nt][3] += bhi.y;
    }
    float m0 = -1e30f, m1 = -1e30f;
#pragma unroll
    for (int nt = 0; nt < 8; nt++) {
        m0 = fmaxf(m0, fmaxf(acc[nt][0], acc[nt][1]));
        m1 = fmaxf(m1, fmaxf(acc[nt][2], acc[nt][3]));
    }
    m0 = fmaxf(m0, __shfl_xor_sync(0xffffffffu, m0, 1));
    m0 = fmaxf(m0, __shfl_xor_sync(0xffffffffu, m0, 2));
    m1 = fmaxf(m1, __shfl_xor_sync(0xffffffffu, m1, 1));
    m1 = fmaxf(m1, __shfl_xor_sync(0xffffffffu, m1, 2));

    float s0 = 0.f, s1 = 0.f;
#pragma unroll
    for (int nt = 0; nt < 8; nt++) {
        acc[nt][0] = __expf(acc[nt][0] - m0); s0 += acc[nt][0];
        acc[nt][1] = __expf(acc[nt][1] - m0); s0 += acc[nt][1];
        acc[nt][2] = __expf(acc[nt][2] - m1); s1 += acc[nt][2];
        acc[nt][3] = __expf(acc[nt][3] - m1); s1 += acc[nt][3];
    }
    s0 += __shfl_xor_sync(0xffffffffu, s0, 1);
    s0 += __shfl_xor_sync(0xffffffffu, s0, 2);
    s1 += __shfl_xor_sync(0xffffffffu, s1, 1);
    s1 += __shfl_xor_sync(0xffffffffu, s1, 2);
    const float inv0 = 1.f / s0, inv1 = 1.f / s1;

    // ---- P @ V with P fragments built in registers:
    // A-frag for token chunk kc (s = 16kc..16kc+15):
    //   a0 = P[r][s0..+1]   = acc[2kc][0,1]*inv0
    //   a1 = P[r+8][s0..+1] = acc[2kc][2,3]*inv1
    //   a2 = P[r][s0+8..+9]   = acc[2kc+1][0,1]*inv0
    //   a3 = P[r+8][s0+8..+9] = acc[2kc+1][2,3]*inv1
    float oacc[4][4];
#pragma unroll
    for (int nt = 0; nt < 4; nt++)
#pragma unroll
        for (int e = 0; e < 4; e++) oacc[nt][e] = 0.f;

#pragma unroll
    for (int kc = 0; kc < 4; kc++) {
        const uint32_t a0 = h2pack(acc[2*kc][0]   * inv0, acc[2*kc][1]   * inv0);
        const uint32_t a1 = h2pack(acc[2*kc][2]   * inv1, acc[2*kc][3]   * inv1);
        const uint32_t a2 = h2pack(acc[2*kc+1][0] * inv0, acc[2*kc+1][1] * inv0);
        const uint32_t a3 = h2pack(acc[2*kc+1][2] * inv1, acc[2*kc+1][3] * inv1);
#pragma unroll
        for (int p = 0; p < 2; p++) {
            uint32_t b00, b01, b10, b11;
            const uint32_t addr = sVtb + (uint32_t)(((p * 16 + rBl) * AV_STR
                                   + kc * 16 + hiB * 8) * 2);
            LDMX4(b00, b01, b10, b11, addr);
            MMA_F16(oacc[2*p],   a0, a1, a2, a3, b00, b01);
            MMA_F16(oacc[2*p+1], a0, a1, a2, a3, b10, b11);
        }
    }

    // ---- write O fp16
    __half* obase = o + (size_t)(w * 64 + r0) * 256 + head * 32;
#pragma unroll
    for (int nt = 0; nt < 4; nt++) {
        *(__half2*)(obase + 8 * nt + cb) = __floats2half2_rn(oacc[nt][0], oacc[nt][1]);
        *(__half2*)(obase + 8 * 256 + 8 * nt + cb) = __floats2half2_rn(oacc[nt][2], oacc[nt][3]);
    }
}

// ---------------- LayerNorm: warp-per-row, fp16 inputs -------------------------
__global__ __launch_bounds__(256)
void ln1_kernel(const __half* __restrict__ X, const float* __restrict__ g,
                const float* __restrict__ b, const float* __restrict__ query,
                __half* __restrict__ out)
{
    const int row  = blockIdx.x * 8 + (threadIdx.x >> 5);
    const int lane = threadIdx.x & 31;
    const int c0   = lane * 8;

    __half x8[8];
    *(uint4*)(x8) = *(const uint4*)(X + (size_t)row * CH + c0);
    float v[8];
#pragma unroll
    for (int i = 0; i < 8; i++) v[i] = __half2float(x8[i]);

    float s = 0.f, s2 = 0.f;
#pragma unroll
    for (int i = 0; i < 8; i++) { s += v[i]; s2 += v[i] * v[i]; }
#pragma unroll
    for (int off = 16; off; off >>= 1) {
        s  += __shfl_xor_sync(0xffffffffu, s,  off);
        s2 += __shfl_xor_sync(0xffffffffu, s2, off);
    }
    const float mean = s * (1.f / 256.f);
    const float rstd = rsqrtf(s2 * (1.f / 256.f) - mean * mean + 1e-5f);

    float gv[8], bv[8], qv[8];
    *(float4*)(gv)     = *(const float4*)(g + c0);
    *(float4*)(gv + 4) = *(const float4*)(g + c0 + 4);
    *(float4*)(bv)     = *(const float4*)(b + c0);
    *(float4*)(bv + 4) = *(const float4*)(b + c0 + 4);
    const float* qr = query + (size_t)map_row(row) * CH + c0;
    *(float4*)(qv)     = *(const float4*)(qr);
    *(float4*)(qv + 4) = *(const float4*)(qr + 4);

    __half h8[8];
#pragma unroll
    for (int i = 0; i < 8; i++)
        h8[i] = __float2half((v[i] - mean) * rstd * gv[i] + bv[i] + qv[i]);
    *(uint4*)(out + (size_t)row * CH + c0) = *(uint4*)h8;
}

__global__ __launch_bounds__(256)
void ln2_kernel(const __half* __restrict__ X, const float* __restrict__ g,
                const float* __restrict__ b, const __half* __restrict__ x2,
                float* __restrict__ out)
{
    const int row  = blockIdx.x * 8 + (threadIdx.x >> 5);
    const int lane = threadIdx.x & 31;
    const int c0   = lane * 8;

    __half x8[8];
    *(uint4*)(x8) = *(const uint4*)(X + (size_t)row * CH + c0);
    float v[8];
#pragma unroll
    for (int i = 0; i < 8; i++) v[i] = __half2float(x8[i]);

    float s = 0.f, s2 = 0.f;
#pragma unroll
    for (int i = 0; i < 8; i++) { s += v[i]; s2 += v[i] * v[i]; }
#pragma unroll
    for (int off = 16; off; off >>= 1) {
        s  += __shfl_xor_sync(0xffffffffu, s,  off);
        s2 += __shfl_xor_sync(0xffffffffu, s2, off);
    }
    const float mean = s * (1.f / 256.f);
    const float rstd = rsqrtf(s2 * (1.f / 256.f) - mean * mean + 1e-5f);

    float gv[8], bv[8];
    *(float4*)(gv)     = *(const float4*)(g + c0);
    *(float4*)(gv + 4) = *(const float4*)(g + c0 + 4);
    *(float4*)(bv)     = *(const float4*)(b + c0);
    *(float4*)(bv + 4) = *(const float4*)(b + c0 + 4);
    __half r8[8];
    *(uint4*)(r8) = *(const uint4*)(x2 + (size_t)row * CH + c0);

    float o8[8];
#pragma unroll
    for (int i = 0; i < 8; i++)
        o8[i] = (v[i] - mean) * rstd * gv[i] + bv[i] + __half2float(r8[i]);
    float* op = out + (size_t)map_row(row) * CH + c0;
    *(float4*)(op)     = *(float4*)(o8);
    *(float4*)(op + 4) = *(float4*)(o8 + 4);
}

// ---------------- weight prep: transpose to [N,K] fp16 -------------------------
__global__ __launch_bounds__(256)
void prep_kernel(const float* __restrict__ wq, const float* __restrict__ wk,
                 const float* __restrict__ wv, const float* __restrict__ bq,
                 const float* __restrict__ bk, const float* __restrict__ bv,
                 const float* __restrict__ wo, const float* __restrict__ w1,
                 const float* __restrict__ w2,
                 __half* __restrict__ wqkvT, float* __restrict__ bqkv,
                 __half* __restrict__ woT, __half* __restrict__ w1T,
                 __half* __restrict__ w2T)
{
    int i = blockIdx.x * 256 + threadIdx.x;
    if (i < 196608) {
        int n = i >> 8, k = i & 255;
        float v = (n < 256) ? wq[k * 256 + n]
                : (n < 512) ? wk[k * 256 + (n - 256)]
                            : wv[k * 256 + (n - 512)];
        wqkvT[i] = __float2half(v);
    } else if (i < 262144) {
        int j = i - 196608; int n = j >> 8, k = j & 255;
        woT[j] = __float2half(wo[k * 256 + n]);
    } else if (i < 458752) {
        int j = i - 262144; int n = j >> 8, k = j & 255;
        w1T[j] = __float2half(w1[k * 768 + n]);
    } else if (i < 655360) {
        int j = i - 458752; int n = j / 768, k = j - n * 768;
        w2T[j] = __float2half(w2[k * 256 + n]);
    } else if (i < 656128) {
        int n = i - 655360;
        bqkv[n] = (n < 256) ? bq[n] : (n < 512) ? bk[n - 256] : bv[n - 512];
    }
}

// ---------------- query fp32 -> fp16 copy ---------------------------------------
__global__ __launch_bounds__(256)
void conv_query_kernel(const float* __restrict__ q, __half* __restrict__ qh)
{
    const int i = (blockIdx.x * 256 + threadIdx.x) * 4;
    float4 v = *(const float4*)(q + i);
    *(__half2*)(qh + i)     = __floats2half2_rn(v.x, v.y);
    *(__half2*)(qh + i + 2) = __floats2half2_rn(v.z, v.w);
}

// ---------------- bias+mask table ----------------------------------------------
__global__ __launch_bounds__(256)
void prep_bm_kernel(const float* __restrict__ rpe, const float* __restrict__ mask,
                    const int* __restrict__ rel, float* __restrict__ bm)
{
    int idx = blockIdx.x * 256 + threadIdx.x;
    int wi  = idx >> 15;
    int rem = idx & 32767;
    int h   = rem >> 12;
    int ts  = rem & 4095;
    bm[idx] = rpe[rel[ts] * NHEAD + h] + mask[wi * 4096 + ts];
}

// ---------------- launch --------------------------------------------------------
extern "C" void kernel_launch(void* const* d_in, const int* in_sizes, int n_in,
                              void* d_out, int out_size)
{
    const float* query = (const float*)d_in[0];
    const float* wq = (const float*)d_in[1];  const float* bq = (const float*)d_in[2];
    const float* wk = (const float*)d_in[3];  const float* bk = (const float*)d_in[4];
    const float* wv = (const float*)d_in[5];  const float* bv = (const float*)d_in[6];
    const float* wo = (const float*)d_in[7];  const float* bo = (const float*)d_in[8];
    const float* rpe = (const float*)d_in[9];
    const float* ln1g = (const float*)d_in[10]; const float* ln1b = (const float*)d_in[11];
    const float* ln2g = (const float*)d_in[12]; const float* ln2b = (const float*)d_in[13];
    const float* w1 = (const float*)d_in[14]; const float* b1 = (const float*)d_in[15];
    const float* w2 = (const float*)d_in[16]; const float* b2 = (const float*)d_in[17];
    const float* amask = (const float*)d_in[18];
    const int*   rel   = (const int*)d_in[19];
    float* out = (float*)d_out;

    float *qkvf, *hf, *bqkv, *bm;
    __half *qh, *oh, *x2h, *wqkvT, *woT, *w1T, *w2T;
    cudaGetSymbolAddress((void**)&qkvf,  g_qkv);
    cudaGetSymbolAddress((void**)&hf,    g_h);
    cudaGetSymbolAddress((void**)&qh,    g_qh);
    cudaGetSymbolAddress((void**)&oh,    g_oh);
    cudaGetSymbolAddress((void**)&x2h,   g_x2h);
    cudaGetSymbolAddress((void**)&wqkvT, g_wqkvT);
    cudaGetSymbolAddress((void**)&bqkv,  g_bqkv);
    cudaGetSymbolAddress((void**)&woT,   g_woT);
    cudaGetSymbolAddress((void**)&w1T,   g_w1T);
    cudaGetSymbolAddress((void**)&w2T,   g_w2T);
    cudaGetSymbolAddress((void**)&bm,    g_bm);
    __half* qkvh = (__half*)qkvf;   // fp16 qkv / mlp1 alias
    __half* hh   = (__half*)hf;     // fp16 proj-out alias

    cudaFuncSetAttribute(gemm_mma<true,  false, true>, cudaFuncAttributeMaxDynamicSharedMemorySize, GEMM_SMEM);
    cudaFuncSetAttribute(gemm_mma<false, false, true>, cudaFuncAttributeMaxDynamicSharedMemorySize, GEMM_SMEM);
    cudaFuncSetAttribute(gemm_mma<false, true,  true>, cudaFuncAttributeMaxDynamicSharedMemorySize, GEMM_SMEM);

    // prep: weights->fp16, bias/mask table, query->fp16
    prep_kernel<<<2563, 256>>>(wq, wk, wv, bq, bk, bv, wo, w1, w2,
                               wqkvT, bqkv, woT, w1T, w2T);
    prep_bm_kernel<<<8192, 256>>>(rpe, amask, rel, bm);
    conv_query_kernel<<<32768, 256>>>(query, qh);

    // fused QKV projection -> fp16 qkv (q pre-scaled by 1/sqrt(D) in epilogue)
    gemm_mma<true,  false, true><<<dim3(6, 1024), 256, GEMM_SMEM>>>(qh, wqkvT, bqkv, qkvh, 768, 256);

    // windowed attention (fp16 mma, P in registers) -> fp16 oh
    attn_kernel<<<dim3(TOTW, NHEAD), 128>>>(qkvh, bm, oh);

    // output projection -> fp16 hh
    gemm_mma<false, false, true><<<dim3(2, 1024), 256, GEMM_SMEM>>>(oh, woT, bo, hh, 256, 256);

    // LN1 + residual -> fp16 x2
    ln1_kernel<<<MROWS / 8, 256>>>(hh, ln1g, ln1b, query, x2h);

    // MLP: gelu(x2@w1+b1) -> fp16 (alias of qkv buf); @w2+b2 -> fp16 oh (dead after proj)
    gemm_mma<false, true,  true><<<dim3(6, 1024), 256, GEMM_SMEM>>>(x2h, w1T, b1, qkvh, 768, 256);
    gemm_mma<false, false, true><<<dim3(2, 1024), 256, GEMM_SMEM>>>(qkvh, w2T, b2, oh, 256, 768);

    // LN2 + residual, scatter to output
    ln2_kernel<<<MROWS / 8, 256>>>(oh, ln2g, ln2b, x2h, out);
}

// round 12
// speedup vs baseline: 6.8634x; 1.0091x over previous
#include <cuda_runtime.h>
#include <cuda_fp16.h>
#include <math.h>
#include <stdint.h>

#define BATCH 32
#define CH    256
#define EMB   256
#define NHEAD 8
#define SHFT  4
#define TT    64
#define TOTW  2048
#define MROWS 131072
#define HID   768

// ---------------- scratch ----------------
__device__ float  g_qkv[(size_t)MROWS * 768];   // fp16 alias: qkv out; later mlp1 out
__device__ float  g_h  [(size_t)MROWS * 256];   // fp16 alias: proj out
__device__ __half g_qh [(size_t)MROWS * 256];   // fp16 copy of query (pixel layout)
__device__ __half g_oh [(size_t)MROWS * 256];   // attn out; later mlp2 out (fp16)
__device__ __half g_x2h[(size_t)MROWS * 256];   // ln1 out / residual (fp16)
__device__ __half g_wqkvT[768 * 256];
__device__ float  g_bqkv [768];
__device__ __half g_woT  [256 * 256];
__device__ __half g_w1T  [768 * 256];
__device__ __half g_w2T  [256 * 768];
__device__ __half g_bm   [64 * 8 * 64 * 64];    // fp16 bias+mask [win][head][t][s]

// row (window*64+token) -> pixel index in original query (folds roll by -S)
__device__ __forceinline__ int map_row(int row) {
    int w  = row >> 6;
    int t  = row & 63;
    int b  = w >> 6;
    int wi = w & 63;
    int hb = wi >> 3, wb = wi & 7;
    int i  = ((hb << 3) + (t >> 3) + SHFT) & 63;
    int j  = ((wb << 3) + (t & 7) + SHFT) & 63;
    return (b << 12) + (i << 6) + j;
}

__device__ __forceinline__ uint32_t smem_u32(const void* p) {
    uint32_t a;
    asm("{ .reg .u64 t; cvta.to.shared.u64 t, %1; cvt.u32.u64 %0, t; }" : "=r"(a) : "l"(p));
    return a;
}

__device__ __forceinline__ float tanh_fast(float x) {
    float r;
    asm("tanh.approx.f32 %0, %1;" : "=f"(r) : "f"(x));
    return r;
}

__device__ __forceinline__ uint32_t h2pack(float lo, float hi) {
    __half2 h = __floats2half2_rn(lo, hi);
    return *(uint32_t*)&h;
}

#define LDMX4(r0, r1, r2, r3, addr) \
    asm volatile("ldmatrix.sync.aligned.m8n8.x4.shared.b16 {%0,%1,%2,%3}, [%4];" \
        : "=r"(r0), "=r"(r1), "=r"(r2), "=r"(r3) : "r"(addr))

#define MMA_F16(d, a0, a1, a2, a3, b0, b1) \
    asm volatile("mma.sync.aligned.m16n8k16.row.col.f32.f16.f16.f32 " \
        "{%0,%1,%2,%3}, {%4,%5,%6,%7}, {%8,%9}, {%0,%1,%2,%3};" \
        : "+f"((d)[0]), "+f"((d)[1]), "+f"((d)[2]), "+f"((d)[3]) \
        : "r"(a0), "r"(a1), "r"(a2), "r"(a3), "r"(b0), "r"(b1))

#define CP_ASYNC16(dst, src) \
    asm volatile("cp.async.cg.shared.global [%0], [%1], 16;" :: "r"(dst), "l"(src))
#define CP_COMMIT()  asm volatile("cp.async.commit_group;" ::: "memory")
#define CP_WAIT1()   asm volatile("cp.async.wait_group 1;" ::: "memory")

#define QSCALE 0.17677669529663687f

// ================================================================================
// A-resident N-looped GEMM (K = 256 fixed): C[M, NX*128] = A[M,256] @ Bt^T + bias
// CTA owns 128 rows; A (128x256 fp16 = 64KB) resident; B triple-buffered 16KB
// stages (proven 3-stage cp.async pattern). 8 warps (2m x 4n), warp tile 64x32.
// ================================================================================
#define NRES_SMEM (65536 + 3 * 16384)

template<bool GATHER, bool GELU, int NX>
__global__ __launch_bounds__(256, 2)
void gemm_nres(const __half* __restrict__ A, const __half* __restrict__ Bt,
               const float* __restrict__ bias, __half* __restrict__ C)
{
    constexpr int N = NX * 128;
    extern __shared__ float smem[];
    const uint32_t sbase = smem_u32(smem);
    const uint32_t sBb   = sbase + 65536;
    const int tid  = threadIdx.x;
    const int lane = tid & 31;
    const int wid  = tid >> 5;
    const int warp_m = wid >> 2;
    const int warp_n = wid & 3;
    const int row0 = blockIdx.x * 128;

    const int mrow = tid >> 3;            // 0..31
    const int c8   = tid & 7;
    const uint32_t swc = (uint32_t)((c8 ^ (mrow & 7)) << 4);

    const __half* bcol[4];
    uint32_t stO[4];
#pragma unroll
    for (int i = 0; i < 4; i++) {
        const int m = mrow + 32 * i;
        bcol[i] = Bt + (size_t)m * 256 + c8 * 8;
        stO[i] = (uint32_t)(m * 128) + swc;
    }

    // ---- prologue: group0 = A (4 slabs) + B stage0; group1 = B stage1
    {
        const __half* arow[4];
#pragma unroll
        for (int i = 0; i < 4; i++) {
            const int m = mrow + 32 * i;
            arow[i] = (GATHER ? (A + (size_t)map_row(row0 + m) * CH)
                              : (A + (size_t)(row0 + m) * 256)) + c8 * 8;
        }
#pragma unroll
        for (int t = 0; t < 4; t++)
#pragma unroll
            for (int i = 0; i < 4; i++)
                CP_ASYNC16(sbase + t * 16384 + stO[i], arow[i] + t * 64);
#pragma unroll
        for (int i = 0; i < 4; i++)
            CP_ASYNC16(sBb + stO[i], bcol[i]);               // stage 0 -> buf 0
        CP_COMMIT();
#pragma unroll
        for (int i = 0; i < 4; i++)
            CP_ASYNC16(sBb + 16384 + stO[i], bcol[i] + 64);  // stage 1 -> buf 1
        CP_COMMIT();
    }

    const int rA  = warp_m * 64 + (lane & 15);
    const int hiA = lane >> 4;
    const int xA  = lane & 7;
    const int rB  = warp_n * 32 + ((lane >> 4) << 3) + (lane & 7);
    const int hiB = (lane >> 3) & 1;
    const int xB  = lane & 7;

    float acc[4][4][4];
#pragma unroll
    for (int i = 0; i < 4; i++)
#pragma unroll
        for (int j = 0; j < 4; j++)
#pragma unroll
            for (int e = 0; e < 4; e++) acc[i][j][e] = 0.f;

    constexpr int S = NX * 4;
#pragma unroll 4
    for (int s = 0; s < S; ++s) {
        CP_WAIT1();            // stage s resident (<=1 pending: stage s+1)
        __syncthreads();       // all warps done with stage s-1 compute

        // prefetch stage s+2 into buf (s+2)%3 (consumer of that buf finished)
        const int sp = s + 2;
        if (sp < S) {
            const int nxp = sp >> 2, tp = sp & 3;
            const size_t off = (size_t)nxp * (128 * 256) + tp * 64;
            const uint32_t so = sBb + (uint32_t)(sp % 3) * 16384;
#pragma unroll
            for (int i = 0; i < 4; i++)
                CP_ASYNC16(so + stO[i], bcol[i] + off);
        }
        CP_COMMIT();

        // compute: A slab (s&3), B buffer (s%3)
        const uint32_t sa = sbase + (uint32_t)(s & 3) * 16384;
        const uint32_t sb = sBb   + (uint32_t)(s % 3) * 16384;
#pragma unroll
        for (int kc = 0; kc < 4; kc++) {
            uint32_t af[4][4];
#pragma unroll
            for (int mt = 0; mt < 4; mt++) {
                const uint32_t addr = sa + (uint32_t)((rA + mt * 16) * 128)
                                    + (uint32_t)((((kc << 1) + hiA) ^ xA) << 4);
                LDMX4(af[mt][0], af[mt][1], af[mt][2], af[mt][3], addr);
            }
            uint32_t bf[4][2];
#pragma unroll
            for (int p = 0; p < 2; p++) {
                const uint32_t addr = sb + (uint32_t)((rB + p * 16) * 128)
                                    + (uint32_t)((((kc << 1) + hiB) ^ xB) << 4);
                LDMX4(bf[2*p][0], bf[2*p][1], bf[2*p+1][0], bf[2*p+1][1], addr);
            }
#pragma unroll
            for (int mt = 0; mt < 4; mt++)
#pragma unroll
                for (int nt = 0; nt < 4; nt++)
                    MMA_F16(acc[mt][nt], af[mt][0], af[mt][1], af[mt][2], af[mt][3],
                            bf[nt][0], bf[nt][1]);
        }

        // epilogue at end of each n-tile
        if ((s & 3) == 3) {
            const int col0 = (s >> 2) * 128;
            const int rbase = row0 + warp_m * 64 + (lane >> 2);
            const int cb0   = col0 + warp_n * 32 + 2 * (lane & 3);
#pragma unroll
            for (int nt = 0; nt < 4; nt++) {
                const int cc = cb0 + nt * 8;
                const float bv0 = bias[cc], bv1 = bias[cc + 1];
                const float post = (GATHER && cc < 256) ? QSCALE : 1.f;
#pragma unroll
                for (int mt = 0; mt < 4; mt++) {
                    const int r = rbase + mt * 16;
                    float v[4];
#pragma unroll
                    for (int e = 0; e < 4; e++) {
                        float x = acc[mt][nt][e] + ((e & 1) ? bv1 : bv0);
                        if (GELU) {
                            float x3 = x * x * x;
                            x = 0.5f * x * (1.f + tanh_fast(0.7978845608028654f * (x + 0.044715f * x3)));
                        }
                        v[e] = x * post;
                        acc[mt][nt][e] = 0.f;
                    }
                    *(__half2*)(C + (size_t)r * N + cc)       = __floats2half2_rn(v[0], v[1]);
                    *(__half2*)(C + (size_t)(r + 8) * N + cc) = __floats2half2_rn(v[2], v[3]);
                }
            }
        }
    }
}

// ---------------- fp16 mma.sync GEMM (frozen R8/R9) — used for mlp2 (K=768) ----
#define STAGE_BYTES 32768
#define NSTAGE      3
#define GEMM_SMEM   (NSTAGE * STAGE_BYTES)

__global__ __launch_bounds__(256, 2)
void gemm_mma(const __half* __restrict__ A, const __half* __restrict__ Bt,
              const float* __restrict__ bias, __half* __restrict__ C,
              int N, int Kd)
{
    extern __shared__ float smem[];
    const uint32_t sbase = smem_u32(smem);
    const int tid  = threadIdx.x;
    const int lane = tid & 31;
    const int wid  = tid >> 5;
    const int warp_m = wid >> 2;
    const int warp_n = wid & 3;
    const int row0 = blockIdx.y * 128;
    const int col0 = blockIdx.x * 128;

    const int mrow = tid >> 3;
    const int c8   = tid & 7;
    const uint32_t swc = (uint32_t)((c8 ^ (mrow & 7)) << 4);

    const __half* arow[4];
    const __half* brow[4];
    uint32_t stA[4];
#pragma unroll
    for (int i = 0; i < 4; i++) {
        const int m = mrow + 32 * i;
        arow[i] = A + (size_t)(row0 + m) * Kd + c8 * 8;
        brow[i] = Bt + (size_t)(col0 + m) * Kd + c8 * 8;
        stA[i] = (uint32_t)(m * 128) + swc;
    }

    const int rA  = warp_m * 64 + (lane & 15);
    const int hiA = lane >> 4;
    const int xA  = lane & 7;
    const int rB  = warp_n * 32 + ((lane >> 4) << 3) + (lane & 7);
    const int hiB = (lane >> 3) & 1;
    const int xB  = lane & 7;

    float acc[4][4][4];
#pragma unroll
    for (int i = 0; i < 4; i++)
#pragma unroll
        for (int j = 0; j < 4; j++)
#pragma unroll
            for (int e = 0; e < 4; e++) acc[i][j][e] = 0.f;

    const int T = Kd >> 6;

#pragma unroll
    for (int s = 0; s < NSTAGE - 1; s++) {
        const int k0 = s * 64;
        const uint32_t so = sbase + s * STAGE_BYTES;
#pragma unroll
        for (int i = 0; i < 4; i++) {
            CP_ASYNC16(so + stA[i],         arow[i] + k0);
            CP_ASYNC16(so + stA[i] + 16384, brow[i] + k0);
        }
        CP_COMMIT();
    }

    for (int t = 0; t < T; ++t) {
        CP_WAIT1();
        __syncthreads();

        const int kt = t + NSTAGE - 1;
        if (kt < T) {
            const int k0 = kt * 64;
            const uint32_t so = sbase + (kt % NSTAGE) * STAGE_BYTES;
#pragma unroll
            for (int i = 0; i < 4; i++) {
                CP_ASYNC16(so + stA[i],         arow[i] + k0);
                CP_ASYNC16(so + stA[i] + 16384, brow[i] + k0);
            }
        }
        CP_COMMIT();

        const uint32_t sa = sbase + (t % NSTAGE) * STAGE_BYTES;
        const uint32_t sb = sa + 16384;
#pragma unroll
        for (int kc = 0; kc < 4; kc++) {
            uint32_t af[4][4];
#pragma unroll
            for (int mt = 0; mt < 4; mt++) {
                const uint32_t addr = sa + (uint32_t)((rA + mt * 16) * 128)
                                    + (uint32_t)((((kc << 1) + hiA) ^ xA) << 4);
                LDMX4(af[mt][0], af[mt][1], af[mt][2], af[mt][3], addr);
            }
            uint32_t bf[4][2];
#pragma unroll
            for (int p = 0; p < 2; p++) {
                const uint32_t addr = sb + (uint32_t)((rB + p * 16) * 128)
                                    + (uint32_t)((((kc << 1) + hiB) ^ xB) << 4);
                LDMX4(bf[2*p][0], bf[2*p][1], bf[2*p+1][0], bf[2*p+1][1], addr);
            }
#pragma unroll
            for (int mt = 0; mt < 4; mt++)
#pragma unroll
                for (int nt = 0; nt < 4; nt++)
                    MMA_F16(acc[mt][nt], af[mt][0], af[mt][1], af[mt][2], af[mt][3],
                            bf[nt][0], bf[nt][1]);
        }
    }

    const int rbase = row0 + warp_m * 64 + (lane >> 2);
    const int cb0   = col0 + warp_n * 32 + 2 * (lane & 3);
#pragma unroll
    for (int nt = 0; nt < 4; nt++) {
        const int cc = cb0 + nt * 8;
        const float bv0 = bias[cc], bv1 = bias[cc + 1];
#pragma unroll
        for (int mt = 0; mt < 4; mt++) {
            const int r = rbase + mt * 16;
            float v[4];
#pragma unroll
            for (int e = 0; e < 4; e++)
                v[e] = acc[mt][nt][e] + ((e & 1) ? bv1 : bv0);
            *(__half2*)(C + (size_t)r * N + cc)       = __floats2half2_rn(v[0], v[1]);
            *(__half2*)(C + (size_t)(r + 8) * N + cc) = __floats2half2_rn(v[2], v[3]);
        }
    }
}

// ---------------- attention (frozen R10, fp16 bm) ------------------------------
#define AQ_STR 40
#define AV_STR 72

__global__ __launch_bounds__(128)
void attn_kernel(const __half* __restrict__ qkv, const __half* __restrict__ bm,
                 __half* __restrict__ o)
{
    const int w = blockIdx.x, head = blockIdx.y;
    const int tid = threadIdx.x;
    const int lane = tid & 31;
    const int wid  = tid >> 5;

    __shared__ __align__(16) __half sQ[64 * AQ_STR];
    __shared__ __align__(16) __half sK[64 * AQ_STR];
    __shared__ __align__(16) __half sVt[32 * AV_STR];

    {
        const int row  = tid >> 1;
        const int half16 = (tid & 1) * 16;
        const __half* base = qkv + (size_t)(w * 64 + row) * 768 + head * 32 + half16;
        uint4 qv0 = *(const uint4*)(base);
        uint4 qv1 = *(const uint4*)(base + 8);
        uint4 kv0 = *(const uint4*)(base + 256);
        uint4 kv1 = *(const uint4*)(base + 264);
        *(uint4*)(sQ + row * AQ_STR + half16)     = qv0;
        *(uint4*)(sQ + row * AQ_STR + half16 + 8) = qv1;
        *(uint4*)(sK + row * AQ_STR + half16)     = kv0;
        *(uint4*)(sK + row * AQ_STR + half16 + 8) = kv1;
        __half vv[16];
        *(uint4*)(vv)     = *(const uint4*)(base + 512);
        *(uint4*)(vv + 8) = *(const uint4*)(base + 520);
#pragma unroll
        for (int j = 0; j < 16; j++)
            sVt[(half16 + j) * AV_STR + row] = vv[j];
    }
    __syncthreads();

    const uint32_t sQb  = smem_u32(sQ);
    const uint32_t sKb  = smem_u32(sK);
    const uint32_t sVtb = smem_u32(sVt);

    const int rA  = (lane & 15);
    const int hiA = lane >> 4;
    const int rBl = ((lane >> 4) << 3) + (lane & 7);
    const int hiB = (lane >> 3) & 1;

    float acc[8][4];
#pragma unroll
    for (int nt = 0; nt < 8; nt++)
#pragma unroll
        for (int e = 0; e < 4; e++) acc[nt][e] = 0.f;

#pragma unroll
    for (int kc = 0; kc < 2; kc++) {
        uint32_t a0, a1, a2, a3;
        {
            const uint32_t addr = sQb + (uint32_t)(((wid * 16 + rA) * AQ_STR
                                   + kc * 16 + hiA * 8) * 2);
            LDMX4(a0, a1, a2, a3, addr);
        }
#pragma unroll
        for (int p = 0; p < 4; p++) {
            uint32_t b00, b01, b10, b11;
            const uint32_t addr = sKb + (uint32_t)(((p * 16 + rBl) * AQ_STR
                                   + kc * 16 + hiB * 8) * 2);
            LDMX4(b00, b01, b10, b11, addr);
            MMA_F16(acc[2*p],   a0, a1, a2, a3, b00, b01);
            MMA_F16(acc[2*p+1], a0, a1, a2, a3, b10, b11);
        }
    }

    const __half* bmr = bm + (size_t)((w & 63) * 8 + head) * 4096;
    const int r0 = wid * 16 + (lane >> 2);
    const int cb = 2 * (lane & 3);
#pragma unroll
    for (int nt = 0; nt < 8; nt++) {
        const float2 blo = __half22float2(*(const __half2*)(bmr + r0 * 64 + 8 * nt + cb));
        const float2 bhi = __half22float2(*(const __half2*)(bmr + (r0 + 8) * 64 + 8 * nt + cb));
        acc[nt][0] += blo.x; acc[nt][1] += blo.y;
        acc[nt][2] += bhi.x; acc[nt][3] += bhi.y;
    }
    float m0 = -1e30f, m1 = -1e30f;
#pragma unroll
    for (int nt = 0; nt < 8; nt++) {
        m0 = fmaxf(m0, fmaxf(acc[nt][0], acc[nt][1]));
        m1 = fmaxf(m1, fmaxf(acc[nt][2], acc[nt][3]));
    }
    m0 = fmaxf(m0, __shfl_xor_sync(0xffffffffu, m0, 1));
    m0 = fmaxf(m0, __shfl_xor_sync(0xffffffffu, m0, 2));
    m1 = fmaxf(m1, __shfl_xor_sync(0xffffffffu, m1, 1));
    m1 = fmaxf(m1, __shfl_xor_sync(0xffffffffu, m1, 2));

    float s0 = 0.f, s1 = 0.f;
#pragma unroll
    for (int nt = 0; nt < 8; nt++) {
        acc[nt][0] = __expf(acc[nt][0] - m0); s0 += acc[nt][0];
        acc[nt][1] = __expf(acc[nt][1] - m0); s0 += acc[nt][1];
        acc[nt][2] = __expf(acc[nt][2] - m1); s1 += acc[nt][2];
        acc[nt][3] = __expf(acc[nt][3] - m1); s1 += acc[nt][3];
    }
    s0 += __shfl_xor_sync(0xffffffffu, s0, 1);
    s0 += __shfl_xor_sync(0xffffffffu, s0, 2);
    s1 += __shfl_xor_sync(0xffffffffu, s1, 1);
    s1 += __shfl_xor_sync(0xffffffffu, s1, 2);
    const float inv0 = 1.f / s0, inv1 = 1.f / s1;

    float oacc[4][4];
#pragma unroll
    for (int nt = 0; nt < 4; nt++)
#pragma unroll
        for (int e = 0; e < 4; e++) oacc[nt][e] = 0.f;

#pragma unroll
    for (int kc = 0; kc < 4; kc++) {
        const uint32_t a0 = h2pack(acc[2*kc][0]   * inv0, acc[2*kc][1]   * inv0);
        const uint32_t a1 = h2pack(acc[2*kc][2]   * inv1, acc[2*kc][3]   * inv1);
        const uint32_t a2 = h2pack(acc[2*kc+1][0] * inv0, acc[2*kc+1][1] * inv0);
        const uint32_t a3 = h2pack(acc[2*kc+1][2] * inv1, acc[2*kc+1][3] * inv1);
#pragma unroll
        for (int p = 0; p < 2; p++) {
            uint32_t b00, b01, b10, b11;
            const uint32_t addr = sVtb + (uint32_t)(((p * 16 + rBl) * AV_STR
                                   + kc * 16 + hiB * 8) * 2);
            LDMX4(b00, b01, b10, b11, addr);
            MMA_F16(oacc[2*p],   a0, a1, a2, a3, b00, b01);
            MMA_F16(oacc[2*p+1], a0, a1, a2, a3, b10, b11);
        }
    }

    __half* obase = o + (size_t)(w * 64 + r0) * 256 + head * 32;
#pragma unroll
    for (int nt = 0; nt < 4; nt++) {
        *(__half2*)(obase + 8 * nt + cb) = __floats2half2_rn(oacc[nt][0], oacc[nt][1]);
        *(__half2*)(obase + 8 * 256 + 8 * nt + cb) = __floats2half2_rn(oacc[nt][2], oacc[nt][3]);
    }
}

// ---------------- LayerNorm: warp-per-row, fp16 inputs (frozen R10) ------------
__global__ __launch_bounds__(256)
void ln1_kernel(const __half* __restrict__ X, const float* __restrict__ g,
                const float* __restrict__ b, const float* __restrict__ query,
                __half* __restrict__ out)
{
    const int row  = blockIdx.x * 8 + (threadIdx.x >> 5);
    const int lane = threadIdx.x & 31;
    const int c0   = lane * 8;

    __half x8[8];
    *(uint4*)(x8) = *(const uint4*)(X + (size_t)row * CH + c0);
    float v[8];
#pragma unroll
    for (int i = 0; i < 8; i++) v[i] = __half2float(x8[i]);

    float s = 0.f, s2 = 0.f;
#pragma unroll
    for (int i = 0; i < 8; i++) { s += v[i]; s2 += v[i] * v[i]; }
#pragma unroll
    for (int off = 16; off; off >>= 1) {
        s  += __shfl_xor_sync(0xffffffffu, s,  off);
        s2 += __shfl_xor_sync(0xffffffffu, s2, off);
    }
    const float mean = s * (1.f / 256.f);
    const float rstd = rsqrtf(s2 * (1.f / 256.f) - mean * mean + 1e-5f);

    float gv[8], bv[8], qv[8];
    *(float4*)(gv)     = *(const float4*)(g + c0);
    *(float4*)(gv + 4) = *(const float4*)(g + c0 + 4);
    *(float4*)(bv)     = *(const float4*)(b + c0);
    *(float4*)(bv + 4) = *(const float4*)(b + c0 + 4);
    const float* qr = query + (size_t)map_row(row) * CH + c0;
    *(float4*)(qv)     = *(const float4*)(qr);
    *(float4*)(qv + 4) = *(const float4*)(qr + 4);

    __half h8[8];
#pragma unroll
    for (int i = 0; i < 8; i++)
        h8[i] = __float2half((v[i] - mean) * rstd * gv[i] + bv[i] + qv[i]);
    *(uint4*)(out + (size_t)row * CH + c0) = *(uint4*)h8;
}

__global__ __launch_bounds__(256)
void ln2_kernel(const __half* __restrict__ X, const float* __restrict__ g,
                const float* __restrict__ b, const __half* __restrict__ x2,
                float* __restrict__ out)
{
    const int row  = blockIdx.x * 8 + (threadIdx.x >> 5);
    const int lane = threadIdx.x & 31;
    const int c0   = lane * 8;

    __half x8[8];
    *(uint4*)(x8) = *(const uint4*)(X + (size_t)row * CH + c0);
    float v[8];
#pragma unroll
    for (int i = 0; i < 8; i++) v[i] = __half2float(x8[i]);

    float s = 0.f, s2 = 0.f;
#pragma unroll
    for (int i = 0; i < 8; i++) { s += v[i]; s2 += v[i] * v[i]; }
#pragma unroll
    for (int off = 16; off; off >>= 1) {
        s  += __shfl_xor_sync(0xffffffffu, s,  off);
        s2 += __shfl_xor_sync(0xffffffffu, s2, off);
    }
    const float mean = s * (1.f / 256.f);
    const float rstd = rsqrtf(s2 * (1.f / 256.f) - mean * mean + 1e-5f);

    float gv[8], bv[8];
    *(float4*)(gv)     = *(const float4*)(g + c0);
    *(float4*)(gv + 4) = *(const float4*)(g + c0 + 4);
    *(float4*)(bv)     = *(const float4*)(b + c0);
    *(float4*)(bv + 4) = *(const float4*)(b + c0 + 4);
    __half r8[8];
    *(uint4*)(r8) = *(const uint4*)(x2 + (size_t)row * CH + c0);

    float o8[8];
#pragma unroll
    for (int i = 0; i < 8; i++)
        o8[i] = (v[i] - mean) * rstd * gv[i] + bv[i] + __half2float(r8[i]);
    float* op = out + (size_t)map_row(row) * CH + c0;
    *(float4*)(op)     = *(float4*)(o8);
    *(float4*)(op + 4) = *(float4*)(o8 + 4);
}

// ---------------- weight prep ----------------------------------------------------
__global__ __launch_bounds__(256)
void prep_kernel(const float* __restrict__ wq, const float* __restrict__ wk,
                 const float* __restrict__ wv, const float* __restrict__ bq,
                 const float* __restrict__ bk, const float* __restrict__ bv,
                 const float* __restrict__ wo, const float* __restrict__ w1,
                 const float* __restrict__ w2,
                 __half* __restrict__ wqkvT, float* __restrict__ bqkv,
                 __half* __restrict__ woT, __half* __restrict__ w1T,
                 __half* __restrict__ w2T)
{
    int i = blockIdx.x * 256 + threadIdx.x;
    if (i < 196608) {
        int n = i >> 8, k = i & 255;
        float v = (n < 256) ? wq[k * 256 + n]
                : (n < 512) ? wk[k * 256 + (n - 256)]
                            : wv[k * 256 + (n - 512)];
        wqkvT[i] = __float2half(v);
    } else if (i < 262144) {
        int j = i - 196608; int n = j >> 8, k = j & 255;
        woT[j] = __float2half(wo[k * 256 + n]);
    } else if (i < 458752) {
        int j = i - 262144; int n = j >> 8, k = j & 255;
        w1T[j] = __float2half(w1[k * 768 + n]);
    } else if (i < 655360) {
        int j = i - 458752; int n = j / 768, k = j - n * 768;
        w2T[j] = __float2half(w2[k * 256 + n]);
    } else if (i < 656128) {
        int n = i - 655360;
        bqkv[n] = (n < 256) ? bq[n] : (n < 512) ? bk[n - 256] : bv[n - 512];
    }
}

// ---------------- query fp32 -> fp16 copy ----------------------------------------
__global__ __launch_bounds__(256)
void conv_query_kernel(const float* __restrict__ q, __half* __restrict__ qh)
{
    const int i = (blockIdx.x * 256 + threadIdx.x) * 4;
    float4 v = *(const float4*)(q + i);
    *(__half2*)(qh + i)     = __floats2half2_rn(v.x, v.y);
    *(__half2*)(qh + i + 2) = __floats2half2_rn(v.z, v.w);
}

// ---------------- bias+mask table (fp16, mask clamped to -3e4) -------------------
__global__ __launch_bounds__(256)
void prep_bm_kernel(const float* __restrict__ rpe, const float* __restrict__ mask,
                    const int* __restrict__ rel, __half* __restrict__ bm)
{
    int idx = blockIdx.x * 256 + threadIdx.x;
    int wi  = idx >> 15;
    int rem = idx & 32767;
    int h   = rem >> 12;
    int ts  = rem & 4095;
    bm[idx] = __float2half(rpe[rel[ts] * NHEAD + h] + fmaxf(mask[wi * 4096 + ts], -30000.f));
}

// ---------------- launch ----------------------------------------------------------
extern "C" void kernel_launch(void* const* d_in, const int* in_sizes, int n_in,
                              void* d_out, int out_size)
{
    const float* query = (const float*)d_in[0];
    const float* wq = (const float*)d_in[1];  const float* bq = (const float*)d_in[2];
    const float* wk = (const float*)d_in[3];  const float* bk = (const float*)d_in[4];
    const float* wv = (const float*)d_in[5];  const float* bv = (const float*)d_in[6];
    const float* wo = (const float*)d_in[7];  const float* bo = (const float*)d_in[8];
    const float* rpe = (const float*)d_in[9];
    const float* ln1g = (const float*)d_in[10]; const float* ln1b = (const float*)d_in[11];
    const float* ln2g = (const float*)d_in[12]; const float* ln2b = (const float*)d_in[13];
    const float* w1 = (const float*)d_in[14]; const float* b1 = (const float*)d_in[15];
    const float* w2 = (const float*)d_in[16]; const float* b2 = (const float*)d_in[17];
    const float* amask = (const float*)d_in[18];
    const int*   rel   = (const int*)d_in[19];
    float* out = (float*)d_out;

    float *qkvf, *hf, *bqkv;
    __half *qh, *oh, *x2h, *wqkvT, *woT, *w1T, *w2T, *bm;
    cudaGetSymbolAddress((void**)&qkvf,  g_qkv);
    cudaGetSymbolAddress((void**)&hf,    g_h);
    cudaGetSymbolAddress((void**)&qh,    g_qh);
    cudaGetSymbolAddress((void**)&oh,    g_oh);
    cudaGetSymbolAddress((void**)&x2h,   g_x2h);
    cudaGetSymbolAddress((void**)&wqkvT, g_wqkvT);
    cudaGetSymbolAddress((void**)&bqkv,  g_bqkv);
    cudaGetSymbolAddress((void**)&woT,   g_woT);
    cudaGetSymbolAddress((void**)&w1T,   g_w1T);
    cudaGetSymbolAddress((void**)&w2T,   g_w2T);
    cudaGetSymbolAddress((void**)&bm,    g_bm);
    __half* qkvh = (__half*)qkvf;   // fp16 qkv / mlp1 alias
    __half* hh   = (__half*)hf;     // fp16 proj-out alias

    cudaFuncSetAttribute(gemm_nres<true,  false, 6>, cudaFuncAttributeMaxDynamicSharedMemorySize, NRES_SMEM);
    cudaFuncSetAttribute(gemm_nres<false, false, 2>, cudaFuncAttributeMaxDynamicSharedMemorySize, NRES_SMEM);
    cudaFuncSetAttribute(gemm_nres<false, true,  6>, cudaFuncAttributeMaxDynamicSharedMemorySize, NRES_SMEM);
    cudaFuncSetAttribute(gemm_mma, cudaFuncAttributeMaxDynamicSharedMemorySize, GEMM_SMEM);

    // prep: weights->fp16, bias/mask table (fp16), query->fp16
    prep_kernel<<<2563, 256>>>(wq, wk, wv, bq, bk, bv, wo, w1, w2,
                               wqkvT, bqkv, woT, w1T, w2T);
    prep_bm_kernel<<<8192, 256>>>(rpe, amask, rel, bm);
    conv_query_kernel<<<32768, 256>>>(query, qh);

    // fused QKV projection (A-resident, 6 n-tiles; q scaled in epilogue)
    gemm_nres<true,  false, 6><<<1024, 256, NRES_SMEM>>>(qh, wqkvT, bqkv, qkvh);

    // windowed attention -> fp16 oh
    attn_kernel<<<dim3(TOTW, NHEAD), 128>>>(qkvh, bm, oh);

    // output projection (A-resident, 2 n-tiles) -> fp16 hh
    gemm_nres<false, false, 2><<<1024, 256, NRES_SMEM>>>(oh, woT, bo, hh);

    // LN1 + residual -> fp16 x2
    ln1_kernel<<<MROWS / 8, 256>>>(hh, ln1g, ln1b, query, x2h);

    // MLP: gelu(x2@w1+b1) -> fp16 (A-resident, 6 n-tiles); @w2+b2 (K=768) -> fp16 oh
    gemm_nres<false, true,  6><<<1024, 256, NRES_SMEM>>>(x2h, w1T, b1, qkvh);
    gemm_mma<<<dim3(2, 1024), 256, GEMM_SMEM>>>(qkvh, w2T, b2, oh, 256, 768);

    // LN2 + residual, scatter to output
    ln2_kernel<<<MROWS / 8, 256>>>(oh, ln2g, ln2b, x2h, out);
}